// round 1
// baseline (speedup 1.0000x reference)
#include <cuda_runtime.h>
#include <math.h>
#include <stdint.h>

// Problem constants
#define BATCH 2
#define SEQ   2048
#define DMODEL 2048
#define NHEAD 16
#define HDIM  128
#define MTOT  (BATCH*SEQ)          // 4096

// ---------------- scratch (device globals; no allocations allowed) ----------
__device__ float g_q  [(size_t)BATCH*32*SEQ*HDIM];   // 32 query streams
__device__ float g_k  [(size_t)BATCH*16*SEQ*HDIM];
__device__ float g_v  [(size_t)BATCH*16*SEQ*HDIM];
__device__ float g_y  [(size_t)BATCH*32*SEQ*HDIM];   // attention outputs, 32 streams
__device__ float g_lam[(size_t)BATCH*16*SEQ];
__device__ float g_yc [(size_t)BATCH*SEQ*DMODEL];    // combined, pre output GEMM

// ============================== SGEMM =======================================
// C[M,N] = A[M,K] @ W[K,N], row-major inputs.
// MODE 0: plain row-major store.
// MODE 1: head-scatter store: out[((b*headsTotal + headOffset + n/128)*SEQ + t)*128 + n%128]
#define BM 128
#define BN 128
#define BK 16
#define SPITCH 132

template <int MODE>
__global__ void __launch_bounds__(256)
sgemm_kernel(const float* __restrict__ A, const float* __restrict__ W,
             float* __restrict__ C, int M, int N, int K,
             int headsTotal, int headOffset)
{
    __shared__ float As[2][BK][SPITCH];
    __shared__ float Bs[2][BK][SPITCH];

    const int bm = blockIdx.y, bn = blockIdx.x;
    const int tid = threadIdx.x;
    const int tm = tid >> 4;       // 0..15
    const int tn = tid & 15;       // 0..15

    const float* Ablk = A + (size_t)bm * BM * K;
    const float* Wblk = W + (size_t)bn * BN;

    // A loader: 512 float4 slots; slot = r*4 + c4
    const int arow = tid >> 2;         // 0..63 (and +64)
    const int ac4  = tid & 3;          // 0..3
    // B loader: slot = r*32 + c4
    const int brow = tid >> 5;         // 0..7 (and +8)
    const int bc4  = tid & 31;         // 0..31

    float acc[8][8];
#pragma unroll
    for (int i = 0; i < 8; i++)
#pragma unroll
        for (int j = 0; j < 8; j++) acc[i][j] = 0.f;

    float4 pA0, pA1, pB0, pB1;

    // prologue: load tile 0
    pA0 = *(const float4*)&Ablk[(size_t)arow        * K + ac4 * 4];
    pA1 = *(const float4*)&Ablk[(size_t)(arow + 64) * K + ac4 * 4];
    pB0 = *(const float4*)&Wblk[(size_t)brow        * N + bc4 * 4];
    pB1 = *(const float4*)&Wblk[(size_t)(brow + 8)  * N + bc4 * 4];

    As[0][ac4*4+0][arow]    = pA0.x; As[0][ac4*4+1][arow]    = pA0.y;
    As[0][ac4*4+2][arow]    = pA0.z; As[0][ac4*4+3][arow]    = pA0.w;
    As[0][ac4*4+0][arow+64] = pA1.x; As[0][ac4*4+1][arow+64] = pA1.y;
    As[0][ac4*4+2][arow+64] = pA1.z; As[0][ac4*4+3][arow+64] = pA1.w;
    *(float4*)&Bs[0][brow  ][bc4*4] = pB0;
    *(float4*)&Bs[0][brow+8][bc4*4] = pB1;
    __syncthreads();

    const int nkt = K / BK;
    int cur = 0;
    for (int kt = 0; kt < nkt; kt++) {
        if (kt + 1 < nkt) {
            const float* An = Ablk + (size_t)(kt + 1) * BK;
            const float* Wn = Wblk + (size_t)(kt + 1) * BK * N;
            pA0 = *(const float4*)&An[(size_t)arow        * K + ac4 * 4];
            pA1 = *(const float4*)&An[(size_t)(arow + 64) * K + ac4 * 4];
            pB0 = *(const float4*)&Wn[(size_t)brow        * N + bc4 * 4];
            pB1 = *(const float4*)&Wn[(size_t)(brow + 8)  * N + bc4 * 4];
        }
#pragma unroll
        for (int k = 0; k < BK; k++) {
            float4 a0 = *(float4*)&As[cur][k][tm * 8];
            float4 a1 = *(float4*)&As[cur][k][tm * 8 + 4];
            float4 b0 = *(float4*)&Bs[cur][k][tn * 8];
            float4 b1 = *(float4*)&Bs[cur][k][tn * 8 + 4];
            float av[8] = {a0.x,a0.y,a0.z,a0.w,a1.x,a1.y,a1.z,a1.w};
            float bv[8] = {b0.x,b0.y,b0.z,b0.w,b1.x,b1.y,b1.z,b1.w};
#pragma unroll
            for (int i = 0; i < 8; i++)
#pragma unroll
                for (int j = 0; j < 8; j++)
                    acc[i][j] = fmaf(av[i], bv[j], acc[i][j]);
        }
        if (kt + 1 < nkt) {
            int nb = cur ^ 1;
            As[nb][ac4*4+0][arow]    = pA0.x; As[nb][ac4*4+1][arow]    = pA0.y;
            As[nb][ac4*4+2][arow]    = pA0.z; As[nb][ac4*4+3][arow]    = pA0.w;
            As[nb][ac4*4+0][arow+64] = pA1.x; As[nb][ac4*4+1][arow+64] = pA1.y;
            As[nb][ac4*4+2][arow+64] = pA1.z; As[nb][ac4*4+3][arow+64] = pA1.w;
            *(float4*)&Bs[nb][brow  ][bc4*4] = pB0;
            *(float4*)&Bs[nb][brow+8][bc4*4] = pB1;
        }
        __syncthreads();
        cur ^= 1;
    }

    // epilogue
#pragma unroll
    for (int i = 0; i < 8; i++) {
        int gm = bm * BM + tm * 8 + i;
        float4 v0 = make_float4(acc[i][0], acc[i][1], acc[i][2], acc[i][3]);
        float4 v1 = make_float4(acc[i][4], acc[i][5], acc[i][6], acc[i][7]);
        if (MODE == 0) {
            float* dst = C + (size_t)gm * N + bn * BN + tn * 8;
            *(float4*)dst = v0;
            *(float4*)(dst + 4) = v1;
        } else {
            int b = gm >> 11;            // / SEQ
            int t = gm & (SEQ - 1);
            int h = headOffset + bn;     // BN == HDIM
            float* dst = C + (((size_t)(b * headsTotal + h)) * SEQ + t) * HDIM + tn * 8;
            *(float4*)dst = v0;
            *(float4*)(dst + 4) = v1;
        }
    }
}

// ============================ lambda gate ====================================
// lam[b,h,t] = sigmoid( x[b,t,:] . Wlam[:,h] ),  Wlam row-major [D,16]
__global__ void __launch_bounds__(128)
lam_kernel(const float* __restrict__ x, const float* __restrict__ Wl,
           float* __restrict__ lam)
{
    int btok = blockIdx.x;            // 0..4095
    int b = btok >> 11, t = btok & (SEQ - 1);
    const float* xr = x + (size_t)btok * DMODEL;

    float acc[16];
#pragma unroll
    for (int h = 0; h < 16; h++) acc[h] = 0.f;

    for (int k = threadIdx.x; k < DMODEL; k += 128) {
        float xv = xr[k];
        const float4* w = (const float4*)(Wl + (size_t)k * 16);
        float4 w0 = w[0], w1 = w[1], w2 = w[2], w3 = w[3];
        acc[0]  = fmaf(xv, w0.x, acc[0]);  acc[1]  = fmaf(xv, w0.y, acc[1]);
        acc[2]  = fmaf(xv, w0.z, acc[2]);  acc[3]  = fmaf(xv, w0.w, acc[3]);
        acc[4]  = fmaf(xv, w1.x, acc[4]);  acc[5]  = fmaf(xv, w1.y, acc[5]);
        acc[6]  = fmaf(xv, w1.z, acc[6]);  acc[7]  = fmaf(xv, w1.w, acc[7]);
        acc[8]  = fmaf(xv, w2.x, acc[8]);  acc[9]  = fmaf(xv, w2.y, acc[9]);
        acc[10] = fmaf(xv, w2.z, acc[10]); acc[11] = fmaf(xv, w2.w, acc[11]);
        acc[12] = fmaf(xv, w3.x, acc[12]); acc[13] = fmaf(xv, w3.y, acc[13]);
        acc[14] = fmaf(xv, w3.z, acc[14]); acc[15] = fmaf(xv, w3.w, acc[15]);
    }

    __shared__ float red[128][16];
#pragma unroll
    for (int h = 0; h < 16; h++) red[threadIdx.x][h] = acc[h];
    __syncthreads();
    for (int s = 64; s > 0; s >>= 1) {
        if (threadIdx.x < s)
#pragma unroll
            for (int h = 0; h < 16; h++)
                red[threadIdx.x][h] += red[threadIdx.x + s][h];
        __syncthreads();
    }
    if (threadIdx.x < 16) {
        float vv = red[0][threadIdx.x];
        lam[((size_t)b * 16 + threadIdx.x) * SEQ + t] = 1.f / (1.f + __expf(-vv));
    }
}

// ============================ flash attention ================================
// Q: [B,32,T,128]; K,V: [B,16,T,128]; Y: [B,32,T,128]; stream h uses kv head h/2.
#define AT_BM 64
#define AT_BN 64
#define QPITCH 68
#define VPITCH 132
// smem floats: Qt 128*68 + Kt 128*68 + Vs 64*132 + Pt 64*68 + 192 stats
#define ATT_SMEM_FLOATS (128*QPITCH + 128*QPITCH + 64*VPITCH + 64*QPITCH + 192)
#define ATT_SMEM_BYTES  (ATT_SMEM_FLOATS * 4)

__global__ void __launch_bounds__(256)
attn_kernel(const float* __restrict__ Q, const float* __restrict__ Kg,
            const float* __restrict__ Vg, float* __restrict__ Y)
{
    extern __shared__ float sm[];
    float* Qt   = sm;                       // [k][m] 128 x 68
    float* Kt   = Qt + 128 * QPITCH;        // [k][n] 128 x 68
    float* Vs   = Kt + 128 * QPITCH;        // [n][k] 64 x 132
    float* Pt   = Vs + 64 * VPITCH;         // [n][m] 64 x 68
    float* mrow = Pt + 64 * QPITCH;         // [64]
    float* lrow = mrow + 64;
    float* arow = lrow + 64;

    const int qb = blockIdx.x;              // 0..31
    const int hs = blockIdx.y;              // 0..31 (stream)
    const int b  = blockIdx.z;              // 0..1
    const int kvh = hs >> 1;

    const int tid = threadIdx.x;
    const int tm = tid >> 4;                // 0..15 -> rows tm*4..tm*4+3
    const int tn = tid & 15;                // 0..15

    const float* Qb = Q  + (((size_t)(b * 32 + hs))  * SEQ + qb * AT_BM) * HDIM;
    const float* Kb = Kg + ((size_t)(b * 16 + kvh)) * SEQ * HDIM;
    const float* Vb = Vg + ((size_t)(b * 16 + kvh)) * SEQ * HDIM;
    float* Yb = Y + (((size_t)(b * 32 + hs)) * SEQ + qb * AT_BM) * HDIM;

    // load Q (transposed)
    for (int e = tid; e < AT_BM * HDIM; e += 256) {
        int m = e >> 7, k = e & 127;
        Qt[k * QPITCH + m] = Qb[e];
    }
    if (tid < 64) { mrow[tid] = -INFINITY; lrow[tid] = 0.f; }

    float o[4][8];
#pragma unroll
    for (int i = 0; i < 4; i++)
#pragma unroll
        for (int j = 0; j < 8; j++) o[i][j] = 0.f;

    const float scale = 0.08838834764831845f;  // 1/sqrt(128)
    const int ntiles = qb + 1;

    for (int jt = 0; jt < ntiles; jt++) {
        __syncthreads();   // protect Kt/Vs/Pt from previous iteration; covers Q load on iter 0
        const float* Kgt = Kb + (size_t)jt * AT_BN * HDIM;
        const float* Vgt = Vb + (size_t)jt * AT_BN * HDIM;
        for (int e = tid; e < AT_BN * HDIM; e += 256) {
            int n = e >> 7, k = e & 127;
            Kt[k * QPITCH + n] = Kgt[e];
            Vs[n * VPITCH + k] = Vgt[e];
        }
        __syncthreads();

        // S = Q K^T (4x4 micro)
        float s[4][4];
#pragma unroll
        for (int i = 0; i < 4; i++)
#pragma unroll
            for (int j = 0; j < 4; j++) s[i][j] = 0.f;

        for (int k = 0; k < HDIM; k++) {
            float4 a4 = *(float4*)&Qt[k * QPITCH + tm * 4];
            float4 b4 = *(float4*)&Kt[k * QPITCH + tn * 4];
            float av[4] = {a4.x, a4.y, a4.z, a4.w};
            float bv[4] = {b4.x, b4.y, b4.z, b4.w};
#pragma unroll
            for (int i = 0; i < 4; i++)
#pragma unroll
                for (int j = 0; j < 4; j++)
                    s[i][j] = fmaf(av[i], bv[j], s[i][j]);
        }

        // scale + causal mask, store transposed P[n][m]
        const int qrow0 = qb * AT_BM + tm * 4;
        const int kcol0 = jt * AT_BN + tn * 4;
#pragma unroll
        for (int j = 0; j < 4; j++)
#pragma unroll
            for (int i = 0; i < 4; i++) {
                float vv = s[i][j] * scale;
                if (kcol0 + j > qrow0 + i) vv = -INFINITY;
                Pt[(tn * 4 + j) * QPITCH + tm * 4 + i] = vv;
            }
        __syncthreads();

        // online softmax stats (64 threads, one per row)
        if (tid < 64) {
            int r = tid;
            float mold = mrow[r];
            float mx = mold;
            for (int n = 0; n < AT_BN; n++)
                mx = fmaxf(mx, Pt[n * QPITCH + r]);
            float al = __expf(mold - mx);
            float sum = 0.f;
            for (int n = 0; n < AT_BN; n++) {
                float p = __expf(Pt[n * QPITCH + r] - mx);
                Pt[n * QPITCH + r] = p;
                sum += p;
            }
            lrow[r] = lrow[r] * al + sum;
            mrow[r] = mx;
            arow[r] = al;
        }
        __syncthreads();

        // rescale O and accumulate P @ V
        float al[4];
#pragma unroll
        for (int i = 0; i < 4; i++) al[i] = arow[tm * 4 + i];
#pragma unroll
        for (int i = 0; i < 4; i++)
#pragma unroll
            for (int j = 0; j < 8; j++) o[i][j] *= al[i];

        for (int k = 0; k < AT_BN; k++) {
            float4 a4 = *(float4*)&Pt[k * QPITCH + tm * 4];
            float4 b0 = *(float4*)&Vs[k * VPITCH + tn * 8];
            float4 b1 = *(float4*)&Vs[k * VPITCH + tn * 8 + 4];
            float av[4] = {a4.x, a4.y, a4.z, a4.w};
            float bv[8] = {b0.x,b0.y,b0.z,b0.w,b1.x,b1.y,b1.z,b1.w};
#pragma unroll
            for (int i = 0; i < 4; i++)
#pragma unroll
                for (int j = 0; j < 8; j++)
                    o[i][j] = fmaf(av[i], bv[j], o[i][j]);
        }
    }

    // epilogue
#pragma unroll
    for (int i = 0; i < 4; i++) {
        int row = tm * 4 + i;
        float li = 1.f / lrow[row];
        float4 v0 = make_float4(o[i][0]*li, o[i][1]*li, o[i][2]*li, o[i][3]*li);
        float4 v1 = make_float4(o[i][4]*li, o[i][5]*li, o[i][6]*li, o[i][7]*li);
        *(float4*)&Yb[(size_t)row * HDIM + tn * 8] = v0;
        *(float4*)&Yb[(size_t)row * HDIM + tn * 8 + 4] = v1;
    }
}

// ============================ combine y1 - lam*y2 ============================
__global__ void __launch_bounds__(256)
combine_kernel(const float* __restrict__ Yin, const float* __restrict__ lam,
               float* __restrict__ Yc)
{
    size_t slot = (size_t)blockIdx.x * blockDim.x + threadIdx.x;  // float4 slots
    size_t e = slot * 4;
    const size_t total = (size_t)BATCH * SEQ * DMODEL;
    if (e >= total) return;
    int dd = (int)(e & 127);
    int h  = (int)((e >> 7) & 15);
    int t  = (int)((e >> 11) & (SEQ - 1));
    int b  = (int)(e >> 22);

    float4 y1 = *(const float4*)&Yin[(((size_t)(b*32 + h))      * SEQ + t) * HDIM + dd];
    float4 y2 = *(const float4*)&Yin[(((size_t)(b*32 + 16 + h)) * SEQ + t) * HDIM + dd];
    float l = lam[((size_t)b * 16 + h) * SEQ + t];
    float4 r;
    r.x = y1.x - l * y2.x;  r.y = y1.y - l * y2.y;
    r.z = y1.z - l * y2.z;  r.w = y1.w - l * y2.w;
    *(float4*)&Yc[e] = r;
}

// ================================= launch ====================================
extern "C" void kernel_launch(void* const* d_in, const int* in_sizes, int n_in,
                              void* d_out, int out_size)
{
    const float* x    = (const float*)d_in[0];
    const float* Wq1  = (const float*)d_in[1];
    const float* Wq2  = (const float*)d_in[2];
    const float* Wk   = (const float*)d_in[3];
    const float* Wv   = (const float*)d_in[4];
    const float* Wlam = (const float*)d_in[5];
    const float* Wo   = (const float*)d_in[6];
    float* out = (float*)d_out;

    float *q, *k, *v, *y, *lam, *yc;
    cudaGetSymbolAddress((void**)&q,   g_q);
    cudaGetSymbolAddress((void**)&k,   g_k);
    cudaGetSymbolAddress((void**)&v,   g_v);
    cudaGetSymbolAddress((void**)&y,   g_y);
    cudaGetSymbolAddress((void**)&lam, g_lam);
    cudaGetSymbolAddress((void**)&yc,  g_yc);

    cudaFuncSetAttribute(attn_kernel,
                         cudaFuncAttributeMaxDynamicSharedMemorySize,
                         ATT_SMEM_BYTES);

    dim3 gg(DMODEL / BN, MTOT / BM);   // (16, 32)

    sgemm_kernel<1><<<gg, 256>>>(x, Wq1, q, MTOT, DMODEL, DMODEL, 32, 0);
    sgemm_kernel<1><<<gg, 256>>>(x, Wq2, q, MTOT, DMODEL, DMODEL, 32, 16);
    sgemm_kernel<1><<<gg, 256>>>(x, Wk,  k, MTOT, DMODEL, DMODEL, 16, 0);
    sgemm_kernel<1><<<gg, 256>>>(x, Wv,  v, MTOT, DMODEL, DMODEL, 16, 0);
    lam_kernel<<<MTOT, 128>>>(x, Wlam, lam);

    attn_kernel<<<dim3(SEQ / AT_BM, 32, BATCH), 256, ATT_SMEM_BYTES>>>(q, k, v, y);

    const size_t total = (size_t)BATCH * SEQ * DMODEL;
    combine_kernel<<<(unsigned)((total / 4 + 255) / 256), 256>>>(y, lam, yc);

    sgemm_kernel<0><<<gg, 256>>>(yc, Wo, out, MTOT, DMODEL, DMODEL, 0, 0);
}

// round 3
// speedup vs baseline: 1.4488x; 1.4488x over previous
#include <cuda_runtime.h>
#include <cuda_bf16.h>
#include <math.h>
#include <stdint.h>

// Problem constants
#define BATCH 2
#define SEQ   2048
#define DMODEL 2048
#define NHEAD 16
#define HDIM  128
#define MTOT  (BATCH*SEQ)          // 4096

// ======================= PTX helpers (portable, sm_80+) =====================
__device__ __forceinline__ uint32_t smem_to_u32(const void* p) {
    uint32_t addr;
    asm("{ .reg .u64 tmp; cvta.to.shared.u64 tmp, %1; cvt.u32.u64 %0, tmp; }"
        : "=r"(addr) : "l"(p));
    return addr;
}
__device__ __forceinline__ void cp_async16(uint32_t smem, const void* gmem) {
    asm volatile("cp.async.cg.shared.global [%0], [%1], 16;"
                 :: "r"(smem), "l"(gmem) : "memory");
}
#define CP_COMMIT() asm volatile("cp.async.commit_group;" ::: "memory")
#define CP_WAIT1()  asm volatile("cp.async.wait_group 1;" ::: "memory")
#define CP_WAIT0()  asm volatile("cp.async.wait_group 0;" ::: "memory")

__device__ __forceinline__ void ldsm_x4(uint32_t& r0, uint32_t& r1,
                                        uint32_t& r2, uint32_t& r3, uint32_t a) {
    asm volatile("ldmatrix.sync.aligned.m8n8.x4.shared.b16 {%0,%1,%2,%3}, [%4];"
                 : "=r"(r0), "=r"(r1), "=r"(r2), "=r"(r3) : "r"(a));
}
__device__ __forceinline__ void mma_bf16(float* c, const uint32_t* a,
                                         uint32_t b0, uint32_t b1) {
    asm volatile(
        "mma.sync.aligned.m16n8k16.row.col.f32.bf16.bf16.f32 "
        "{%0,%1,%2,%3}, {%4,%5,%6,%7}, {%8,%9}, {%0,%1,%2,%3};"
        : "+f"(c[0]), "+f"(c[1]), "+f"(c[2]), "+f"(c[3])
        : "r"(a[0]), "r"(a[1]), "r"(a[2]), "r"(a[3]), "r"(b0), "r"(b1));
}

// ---------------- scratch (device globals; no allocations allowed) ----------
__device__ float g_q  [(size_t)BATCH*32*SEQ*HDIM];
__device__ float g_k  [(size_t)BATCH*16*SEQ*HDIM];
__device__ float g_v  [(size_t)BATCH*16*SEQ*HDIM];
__device__ float g_y  [(size_t)BATCH*32*SEQ*HDIM];
__device__ float g_lam[(size_t)BATCH*16*SEQ];
__device__ float g_yc [(size_t)BATCH*SEQ*DMODEL];
// bf16 split buffers
__device__ __nv_bfloat16 g_xh[(size_t)MTOT*DMODEL];
__device__ __nv_bfloat16 g_xl[(size_t)MTOT*DMODEL];
__device__ __nv_bfloat16 g_wh[5][(size_t)DMODEL*DMODEL];   // W^T hi, [N][K]
__device__ __nv_bfloat16 g_wl[5][(size_t)DMODEL*DMODEL];   // W^T lo

// ============================ split kernels ==================================
__global__ void __launch_bounds__(256)
split_x_kernel(const float* __restrict__ X, __nv_bfloat16* __restrict__ H,
               __nv_bfloat16* __restrict__ L, int n4)
{
    int i = blockIdx.x * blockDim.x + threadIdx.x;
    if (i >= n4) return;
    float4 v = ((const float4*)X)[i];
    __nv_bfloat16 h0 = __float2bfloat16(v.x);
    __nv_bfloat16 h1 = __float2bfloat16(v.y);
    __nv_bfloat16 h2 = __float2bfloat16(v.z);
    __nv_bfloat16 h3 = __float2bfloat16(v.w);
    __nv_bfloat16 l0 = __float2bfloat16(v.x - __bfloat162float(h0));
    __nv_bfloat16 l1 = __float2bfloat16(v.y - __bfloat162float(h1));
    __nv_bfloat16 l2 = __float2bfloat16(v.z - __bfloat162float(h2));
    __nv_bfloat16 l3 = __float2bfloat16(v.w - __bfloat162float(h3));
    __nv_bfloat162* Hp = (__nv_bfloat162*)H;
    __nv_bfloat162* Lp = (__nv_bfloat162*)L;
    Hp[2*i]   = __nv_bfloat162(h0, h1);
    Hp[2*i+1] = __nv_bfloat162(h2, h3);
    Lp[2*i]   = __nv_bfloat162(l0, l1);
    Lp[2*i+1] = __nv_bfloat162(l2, l3);
}

// W [K][N] fp32 -> OH/OL [N][K] bf16  (transpose + split), K=N=2048
__global__ void __launch_bounds__(256)
splitT_kernel(const float* __restrict__ W, __nv_bfloat16* __restrict__ OH,
              __nv_bfloat16* __restrict__ OL)
{
    __shared__ float t[32][33];
    int nx = blockIdx.x * 32, ky = blockIdx.y * 32;
    int tx = threadIdx.x, ty = threadIdx.y;   // 32 x 8
#pragma unroll
    for (int i = 0; i < 4; i++)
        t[ty + 8*i][tx] = W[(size_t)(ky + ty + 8*i) * DMODEL + nx + tx];
    __syncthreads();
#pragma unroll
    for (int i = 0; i < 4; i++) {
        float v = t[tx][ty + 8*i];
        __nv_bfloat16 h = __float2bfloat16(v);
        __nv_bfloat16 l = __float2bfloat16(v - __bfloat162float(h));
        size_t o = (size_t)(nx + ty + 8*i) * DMODEL + ky + tx;
        OH[o] = h; OL[o] = l;
    }
}

// ===================== mma.sync split-bf16 GEMM ==============================
// C[4096,2048] = A[M,K] @ B^T, A as (Ah,Al) [M][K] bf16; B as (Bh,Bl) [N][K].
// MODE 0: row-major store. MODE 1: head-scatter (N tile == one head of 128).
#define GK     2048
#define NKCH   64            // K chunks of 32
#define PITCH  40            // bf16 elems per smem row (80B, conflict-free ldmatrix)
#define BUF_B  (128*PITCH*2) // 10240 bytes per operand buffer
#define STAGE_B (4*BUF_B)    // Ah, Al, Bh, Bl
#define GEMM_SMEM (2*STAGE_B)

template <int MODE>
__global__ void __launch_bounds__(256, 1)
tc_gemm(const __nv_bfloat16* __restrict__ Ah, const __nv_bfloat16* __restrict__ Al,
        const __nv_bfloat16* __restrict__ Bh, const __nv_bfloat16* __restrict__ Bl,
        float* __restrict__ C, int headsTotal, int headOffset)
{
    extern __shared__ char dsm[];
    const uint32_t smbase = smem_to_u32(dsm);

    const int tid = threadIdx.x;
    const int wid = tid >> 5;
    const int lid = tid & 31;
    const int wm = wid >> 2;        // 0..1 -> m offset wm*64
    const int wn = wid & 3;         // 0..3 -> n offset wn*32

    // ---- global bases
    const char* Asrc_h = (const char*)(Ah + (size_t)blockIdx.y * 128 * GK);
    const char* Asrc_l = (const char*)(Al + (size_t)blockIdx.y * 128 * GK);
    const char* Bsrc_h = (const char*)(Bh + (size_t)blockIdx.x * 128 * GK);
    const char* Bsrc_l = (const char*)(Bl + (size_t)blockIdx.x * 128 * GK);

    // loader geometry: 512 x 16B chunks per buffer; chunk = row*4 + c16
    const int lrow0 = tid >> 2;     // rows tid>>2 and +64
    const int lc16  = tid & 3;

    auto load_chunk = [&](int kt, int st) {
        uint32_t sb = smbase + st * STAGE_B;
        size_t go = (size_t)kt * 64 + lc16 * 16;   // byte offset within a K row
        const char* src[4] = { Asrc_h, Asrc_l, Bsrc_h, Bsrc_l };
#pragma unroll
        for (int bi = 0; bi < 4; bi++) {
            uint32_t bo = sb + bi * BUF_B;
#pragma unroll
            for (int i = 0; i < 2; i++) {
                int row = lrow0 + i * 64;
                cp_async16(bo + row * (PITCH*2) + lc16 * 16,
                           src[bi] + (size_t)row * (GK*2) + go);
            }
        }
    };

    float acc[4][4][4];
#pragma unroll
    for (int mi = 0; mi < 4; mi++)
#pragma unroll
        for (int nj = 0; nj < 4; nj++)
#pragma unroll
            for (int e = 0; e < 4; e++) acc[mi][nj][e] = 0.f;

    load_chunk(0, 0); CP_COMMIT();
    load_chunk(1, 1); CP_COMMIT();

    // ldmatrix lane addressing: row = lane%16, 16B-half = lane/16
    const int lrow = lid & 15;
    const int lhalf = (lid >> 4) * 16;   // byte offset

    for (int kt = 0; kt < NKCH; kt++) {
        if (kt + 1 < NKCH) { CP_WAIT1(); } else { CP_WAIT0(); }
        __syncthreads();

        uint32_t sb = smbase + (kt & 1) * STAGE_B;
        uint32_t a_h = sb;
        uint32_t a_l = sb + BUF_B;
        uint32_t b_h = sb + 2*BUF_B;
        uint32_t b_l = sb + 3*BUF_B;

#pragma unroll
        for (int k16 = 0; k16 < 2; k16++) {
            const int kb = k16 * 32 + lhalf;   // byte offset within row
            uint32_t ah[4][4], al[4][4], bh[2][4], bl[2][4];
#pragma unroll
            for (int mi = 0; mi < 4; mi++) {
                int r = wm * 64 + mi * 16 + lrow;
                ldsm_x4(ah[mi][0], ah[mi][1], ah[mi][2], ah[mi][3],
                        a_h + r * (PITCH*2) + kb);
                ldsm_x4(al[mi][0], al[mi][1], al[mi][2], al[mi][3],
                        a_l + r * (PITCH*2) + kb);
            }
#pragma unroll
            for (int ni = 0; ni < 2; ni++) {
                int r = wn * 32 + ni * 16 + lrow;
                ldsm_x4(bh[ni][0], bh[ni][1], bh[ni][2], bh[ni][3],
                        b_h + r * (PITCH*2) + kb);
                ldsm_x4(bl[ni][0], bl[ni][1], bl[ni][2], bl[ni][3],
                        b_l + r * (PITCH*2) + kb);
            }
#pragma unroll
            for (int mi = 0; mi < 4; mi++)
#pragma unroll
                for (int nj = 0; nj < 4; nj++) {
                    int ni = nj >> 1, sub = nj & 1;
                    uint32_t b0h = bh[ni][sub],     b1h = bh[ni][sub + 2];
                    uint32_t b0l = bl[ni][sub],     b1l = bl[ni][sub + 2];
                    mma_bf16(acc[mi][nj], ah[mi], b0h, b1h);
                    mma_bf16(acc[mi][nj], ah[mi], b0l, b1l);
                    mma_bf16(acc[mi][nj], al[mi], b0h, b1h);
                }
        }
        __syncthreads();
        if (kt + 2 < NKCH) { load_chunk(kt + 2, kt & 1); CP_COMMIT(); }
    }

    // ---- epilogue: each lane owns rows (g, g+8), cols 2*(l&3)+{0,1} per n8
    const int lg = lid >> 2;
    const int lc = (lid & 3) * 2;
#pragma unroll
    for (int mi = 0; mi < 4; mi++) {
        int row0 = blockIdx.y * 128 + wm * 64 + mi * 16 + lg;
#pragma unroll
        for (int half = 0; half < 2; half++) {
            int row = row0 + half * 8;
            float* dst;
            if (MODE == 0) {
                dst = C + (size_t)row * DMODEL + blockIdx.x * 128;
            } else {
                int b = row >> 11;
                int t = row & (SEQ - 1);
                int h = headOffset + blockIdx.x;
                dst = C + (((size_t)(b * headsTotal + h)) * SEQ + t) * HDIM;
            }
#pragma unroll
            for (int nj = 0; nj < 4; nj++) {
                int n = wn * 32 + nj * 8 + lc;
                float2 v;
                v.x = acc[mi][nj][half * 2 + 0];
                v.y = acc[mi][nj][half * 2 + 1];
                *(float2*)(dst + n) = v;
            }
        }
    }
}

// ============================ lambda gate ====================================
__global__ void __launch_bounds__(128)
lam_kernel(const float* __restrict__ x, const float* __restrict__ Wl,
           float* __restrict__ lam)
{
    int btok = blockIdx.x;
    int b = btok >> 11, t = btok & (SEQ - 1);
    const float* xr = x + (size_t)btok * DMODEL;

    float acc[16];
#pragma unroll
    for (int h = 0; h < 16; h++) acc[h] = 0.f;

    for (int k = threadIdx.x; k < DMODEL; k += 128) {
        float xv = xr[k];
        const float4* w = (const float4*)(Wl + (size_t)k * 16);
        float4 w0 = w[0], w1 = w[1], w2 = w[2], w3 = w[3];
        acc[0]  = fmaf(xv, w0.x, acc[0]);  acc[1]  = fmaf(xv, w0.y, acc[1]);
        acc[2]  = fmaf(xv, w0.z, acc[2]);  acc[3]  = fmaf(xv, w0.w, acc[3]);
        acc[4]  = fmaf(xv, w1.x, acc[4]);  acc[5]  = fmaf(xv, w1.y, acc[5]);
        acc[6]  = fmaf(xv, w1.z, acc[6]);  acc[7]  = fmaf(xv, w1.w, acc[7]);
        acc[8]  = fmaf(xv, w2.x, acc[8]);  acc[9]  = fmaf(xv, w2.y, acc[9]);
        acc[10] = fmaf(xv, w2.z, acc[10]); acc[11] = fmaf(xv, w2.w, acc[11]);
        acc[12] = fmaf(xv, w3.x, acc[12]); acc[13] = fmaf(xv, w3.y, acc[13]);
        acc[14] = fmaf(xv, w3.z, acc[14]); acc[15] = fmaf(xv, w3.w, acc[15]);
    }

    __shared__ float red[128][16];
#pragma unroll
    for (int h = 0; h < 16; h++) red[threadIdx.x][h] = acc[h];
    __syncthreads();
    for (int s = 64; s > 0; s >>= 1) {
        if (threadIdx.x < s)
#pragma unroll
            for (int h = 0; h < 16; h++)
                red[threadIdx.x][h] += red[threadIdx.x + s][h];
        __syncthreads();
    }
    if (threadIdx.x < 16) {
        float vv = red[0][threadIdx.x];
        lam[((size_t)b * 16 + threadIdx.x) * SEQ + t] = 1.f / (1.f + __expf(-vv));
    }
}

// ============================ flash attention ================================
#define AT_BM 64
#define AT_BN 64
#define QPITCH 68
#define VPITCH 132
#define ATT_SMEM_FLOATS (128*QPITCH + 128*QPITCH + 64*VPITCH + 64*QPITCH + 192)
#define ATT_SMEM_BYTES  (ATT_SMEM_FLOATS * 4)

__global__ void __launch_bounds__(256)
attn_kernel(const float* __restrict__ Q, const float* __restrict__ Kg,
            const float* __restrict__ Vg, float* __restrict__ Y)
{
    extern __shared__ float sm[];
    float* Qt   = sm;
    float* Kt   = Qt + 128 * QPITCH;
    float* Vs   = Kt + 128 * QPITCH;
    float* Pt   = Vs + 64 * VPITCH;
    float* mrow = Pt + 64 * QPITCH;
    float* lrow = mrow + 64;
    float* arow = lrow + 64;

    const int qb = blockIdx.x;
    const int hs = blockIdx.y;
    const int b  = blockIdx.z;
    const int kvh = hs >> 1;

    const int tid = threadIdx.x;
    const int tm = tid >> 4;
    const int tn = tid & 15;

    const float* Qb = Q  + (((size_t)(b * 32 + hs))  * SEQ + qb * AT_BM) * HDIM;
    const float* Kb = Kg + ((size_t)(b * 16 + kvh)) * SEQ * HDIM;
    const float* Vb = Vg + ((size_t)(b * 16 + kvh)) * SEQ * HDIM;
    float* Yb = Y + (((size_t)(b * 32 + hs)) * SEQ + qb * AT_BM) * HDIM;

    for (int e = tid; e < AT_BM * HDIM; e += 256) {
        int m = e >> 7, k = e & 127;
        Qt[k * QPITCH + m] = Qb[e];
    }
    if (tid < 64) { mrow[tid] = -INFINITY; lrow[tid] = 0.f; }

    float o[4][8];
#pragma unroll
    for (int i = 0; i < 4; i++)
#pragma unroll
        for (int j = 0; j < 8; j++) o[i][j] = 0.f;

    const float scale = 0.08838834764831845f;
    const int ntiles = qb + 1;

    for (int jt = 0; jt < ntiles; jt++) {
        __syncthreads();
        const float* Kgt = Kb + (size_t)jt * AT_BN * HDIM;
        const float* Vgt = Vb + (size_t)jt * AT_BN * HDIM;
        for (int e = tid; e < AT_BN * HDIM; e += 256) {
            int n = e >> 7, k = e & 127;
            Kt[k * QPITCH + n] = Kgt[e];
            Vs[n * VPITCH + k] = Vgt[e];
        }
        __syncthreads();

        float s[4][4];
#pragma unroll
        for (int i = 0; i < 4; i++)
#pragma unroll
            for (int j = 0; j < 4; j++) s[i][j] = 0.f;

        for (int k = 0; k < HDIM; k++) {
            float4 a4 = *(float4*)&Qt[k * QPITCH + tm * 4];
            float4 b4 = *(float4*)&Kt[k * QPITCH + tn * 4];
            float av[4] = {a4.x, a4.y, a4.z, a4.w};
            float bv[4] = {b4.x, b4.y, b4.z, b4.w};
#pragma unroll
            for (int i = 0; i < 4; i++)
#pragma unroll
                for (int j = 0; j < 4; j++)
                    s[i][j] = fmaf(av[i], bv[j], s[i][j]);
        }

        const int qrow0 = qb * AT_BM + tm * 4;
        const int kcol0 = jt * AT_BN + tn * 4;
#pragma unroll
        for (int j = 0; j < 4; j++)
#pragma unroll
            for (int i = 0; i < 4; i++) {
                float vv = s[i][j] * scale;
                if (kcol0 + j > qrow0 + i) vv = -INFINITY;
                Pt[(tn * 4 + j) * QPITCH + tm * 4 + i] = vv;
            }
        __syncthreads();

        if (tid < 64) {
            int r = tid;
            float mold = mrow[r];
            float mx = mold;
            for (int n = 0; n < AT_BN; n++)
                mx = fmaxf(mx, Pt[n * QPITCH + r]);
            float al = __expf(mold - mx);
            float sum = 0.f;
            for (int n = 0; n < AT_BN; n++) {
                float p = __expf(Pt[n * QPITCH + r] - mx);
                Pt[n * QPITCH + r] = p;
                sum += p;
            }
            lrow[r] = lrow[r] * al + sum;
            mrow[r] = mx;
            arow[r] = al;
        }
        __syncthreads();

        float al[4];
#pragma unroll
        for (int i = 0; i < 4; i++) al[i] = arow[tm * 4 + i];
#pragma unroll
        for (int i = 0; i < 4; i++)
#pragma unroll
            for (int j = 0; j < 8; j++) o[i][j] *= al[i];

        for (int k = 0; k < AT_BN; k++) {
            float4 a4 = *(float4*)&Pt[k * QPITCH + tm * 4];
            float4 b0 = *(float4*)&Vs[k * VPITCH + tn * 8];
            float4 b1 = *(float4*)&Vs[k * VPITCH + tn * 8 + 4];
            float av[4] = {a4.x, a4.y, a4.z, a4.w};
            float bv[8] = {b0.x,b0.y,b0.z,b0.w,b1.x,b1.y,b1.z,b1.w};
#pragma unroll
            for (int i = 0; i < 4; i++)
#pragma unroll
                for (int j = 0; j < 8; j++)
                    o[i][j] = fmaf(av[i], bv[j], o[i][j]);
        }
    }

#pragma unroll
    for (int i = 0; i < 4; i++) {
        int row = tm * 4 + i;
        float li = 1.f / lrow[row];
        float4 v0 = make_float4(o[i][0]*li, o[i][1]*li, o[i][2]*li, o[i][3]*li);
        float4 v1 = make_float4(o[i][4]*li, o[i][5]*li, o[i][6]*li, o[i][7]*li);
        *(float4*)&Yb[(size_t)row * HDIM + tn * 8] = v0;
        *(float4*)&Yb[(size_t)row * HDIM + tn * 8 + 4] = v1;
    }
}

// ============================ combine y1 - lam*y2 ============================
__global__ void __launch_bounds__(256)
combine_kernel(const float* __restrict__ Yin, const float* __restrict__ lam,
               float* __restrict__ Yc)
{
    size_t slot = (size_t)blockIdx.x * blockDim.x + threadIdx.x;
    size_t e = slot * 4;
    const size_t total = (size_t)BATCH * SEQ * DMODEL;
    if (e >= total) return;
    int dd = (int)(e & 127);
    int h  = (int)((e >> 7) & 15);
    int t  = (int)((e >> 11) & (SEQ - 1));
    int b  = (int)(e >> 22);

    float4 y1 = *(const float4*)&Yin[(((size_t)(b*32 + h))      * SEQ + t) * HDIM + dd];
    float4 y2 = *(const float4*)&Yin[(((size_t)(b*32 + 16 + h)) * SEQ + t) * HDIM + dd];
    float l = lam[((size_t)b * 16 + h) * SEQ + t];
    float4 r;
    r.x = y1.x - l * y2.x;  r.y = y1.y - l * y2.y;
    r.z = y1.z - l * y2.z;  r.w = y1.w - l * y2.w;
    *(float4*)&Yc[e] = r;
}

// ================================= launch ====================================
extern "C" void kernel_launch(void* const* d_in, const int* in_sizes, int n_in,
                              void* d_out, int out_size)
{
    const float* x    = (const float*)d_in[0];
    const float* Wq1  = (const float*)d_in[1];
    const float* Wq2  = (const float*)d_in[2];
    const float* Wk   = (const float*)d_in[3];
    const float* Wv   = (const float*)d_in[4];
    const float* Wlam = (const float*)d_in[5];
    const float* Wo   = (const float*)d_in[6];
    float* out = (float*)d_out;

    float *q, *k, *v, *y, *lam, *yc;
    __nv_bfloat16 *xh, *xl, *wh, *wl;
    cudaGetSymbolAddress((void**)&q,   g_q);
    cudaGetSymbolAddress((void**)&k,   g_k);
    cudaGetSymbolAddress((void**)&v,   g_v);
    cudaGetSymbolAddress((void**)&y,   g_y);
    cudaGetSymbolAddress((void**)&lam, g_lam);
    cudaGetSymbolAddress((void**)&yc,  g_yc);
    cudaGetSymbolAddress((void**)&xh,  g_xh);
    cudaGetSymbolAddress((void**)&xl,  g_xl);
    cudaGetSymbolAddress((void**)&wh,  g_wh);
    cudaGetSymbolAddress((void**)&wl,  g_wl);

    cudaFuncSetAttribute(attn_kernel,
                         cudaFuncAttributeMaxDynamicSharedMemorySize, ATT_SMEM_BYTES);
    cudaFuncSetAttribute(tc_gemm<0>,
                         cudaFuncAttributeMaxDynamicSharedMemorySize, GEMM_SMEM);
    cudaFuncSetAttribute(tc_gemm<1>,
                         cudaFuncAttributeMaxDynamicSharedMemorySize, GEMM_SMEM);

    const size_t WSZ = (size_t)DMODEL * DMODEL;
    const int n4x = MTOT * DMODEL / 4;
    dim3 tgrid(64, 64), tblk(32, 8);
    dim3 ggrid(DMODEL / 128, MTOT / 128);   // (16, 32)

    // splits
    split_x_kernel<<<(n4x + 255) / 256, 256>>>(x, xh, xl, n4x);
    splitT_kernel<<<tgrid, tblk>>>(Wq1, wh + 0*WSZ, wl + 0*WSZ);
    splitT_kernel<<<tgrid, tblk>>>(Wq2, wh + 1*WSZ, wl + 1*WSZ);
    splitT_kernel<<<tgrid, tblk>>>(Wk,  wh + 2*WSZ, wl + 2*WSZ);
    splitT_kernel<<<tgrid, tblk>>>(Wv,  wh + 3*WSZ, wl + 3*WSZ);
    splitT_kernel<<<tgrid, tblk>>>(Wo,  wh + 4*WSZ, wl + 4*WSZ);

    // projections (head-scatter epilogue)
    tc_gemm<1><<<ggrid, 256, GEMM_SMEM>>>(xh, xl, wh + 0*WSZ, wl + 0*WSZ, q, 32, 0);
    tc_gemm<1><<<ggrid, 256, GEMM_SMEM>>>(xh, xl, wh + 1*WSZ, wl + 1*WSZ, q, 32, 16);
    tc_gemm<1><<<ggrid, 256, GEMM_SMEM>>>(xh, xl, wh + 2*WSZ, wl + 2*WSZ, k, 16, 0);
    tc_gemm<1><<<ggrid, 256, GEMM_SMEM>>>(xh, xl, wh + 3*WSZ, wl + 3*WSZ, v, 16, 0);

    lam_kernel<<<MTOT, 128>>>(x, Wlam, lam);

    attn_kernel<<<dim3(SEQ / AT_BM, 32, BATCH), 256, ATT_SMEM_BYTES>>>(q, k, v, y);

    const size_t total = (size_t)BATCH * SEQ * DMODEL;
    combine_kernel<<<(unsigned)((total / 4 + 255) / 256), 256>>>(y, lam, yc);

    // output GEMM: split yc (reuse xh/xl), then row-major store to out
    split_x_kernel<<<(n4x + 255) / 256, 256>>>(yc, xh, xl, n4x);
    tc_gemm<0><<<ggrid, 256, GEMM_SMEM>>>(xh, xl, wh + 4*WSZ, wl + 4*WSZ, out, 0, 0);
}

// round 4
// speedup vs baseline: 2.1706x; 1.4982x over previous
#include <cuda_runtime.h>
#include <cuda_bf16.h>
#include <cuda_fp16.h>
#include <math.h>
#include <stdint.h>

// Problem constants
#define BATCH 2
#define SEQ   2048
#define DMODEL 2048
#define NHEAD 16
#define HDIM  128
#define MTOT  (BATCH*SEQ)          // 4096

// ======================= PTX helpers (portable, sm_80+) =====================
__device__ __forceinline__ uint32_t smem_to_u32(const void* p) {
    uint32_t addr;
    asm("{ .reg .u64 tmp; cvta.to.shared.u64 tmp, %1; cvt.u32.u64 %0, tmp; }"
        : "=r"(addr) : "l"(p));
    return addr;
}
__device__ __forceinline__ void cp_async16(uint32_t smem, const void* gmem) {
    asm volatile("cp.async.cg.shared.global [%0], [%1], 16;"
                 :: "r"(smem), "l"(gmem) : "memory");
}
#define CP_COMMIT() asm volatile("cp.async.commit_group;" ::: "memory")
#define CP_WAIT1()  asm volatile("cp.async.wait_group 1;" ::: "memory")
#define CP_WAIT0()  asm volatile("cp.async.wait_group 0;" ::: "memory")

__device__ __forceinline__ void ldsm_x4(uint32_t& r0, uint32_t& r1,
                                        uint32_t& r2, uint32_t& r3, uint32_t a) {
    asm volatile("ldmatrix.sync.aligned.m8n8.x4.shared.b16 {%0,%1,%2,%3}, [%4];"
                 : "=r"(r0), "=r"(r1), "=r"(r2), "=r"(r3) : "r"(a));
}
__device__ __forceinline__ void ldsm_x4t(uint32_t& r0, uint32_t& r1,
                                         uint32_t& r2, uint32_t& r3, uint32_t a) {
    asm volatile("ldmatrix.sync.aligned.m8n8.x4.trans.shared.b16 {%0,%1,%2,%3}, [%4];"
                 : "=r"(r0), "=r"(r1), "=r"(r2), "=r"(r3) : "r"(a));
}
__device__ __forceinline__ void mma_bf16(float* c, const uint32_t* a,
                                         uint32_t b0, uint32_t b1) {
    asm volatile(
        "mma.sync.aligned.m16n8k16.row.col.f32.bf16.bf16.f32 "
        "{%0,%1,%2,%3}, {%4,%5,%6,%7}, {%8,%9}, {%0,%1,%2,%3};"
        : "+f"(c[0]), "+f"(c[1]), "+f"(c[2]), "+f"(c[3])
        : "r"(a[0]), "r"(a[1]), "r"(a[2]), "r"(a[3]), "r"(b0), "r"(b1));
}
__device__ __forceinline__ void mma_f16(float* c, const uint32_t* a,
                                        uint32_t b0, uint32_t b1) {
    asm volatile(
        "mma.sync.aligned.m16n8k16.row.col.f32.f16.f16.f32 "
        "{%0,%1,%2,%3}, {%4,%5,%6,%7}, {%8,%9}, {%0,%1,%2,%3};"
        : "+f"(c[0]), "+f"(c[1]), "+f"(c[2]), "+f"(c[3])
        : "r"(a[0]), "r"(a[1]), "r"(a[2]), "r"(a[3]), "r"(b0), "r"(b1));
}
__device__ __forceinline__ float ex2f(float x) {
    float r;
    asm("ex2.approx.f32 %0, %1;" : "=f"(r) : "f"(x));
    return r;
}
__device__ __forceinline__ uint32_t packh2(float lo, float hi) {
    uint32_t d;
    asm("cvt.rn.f16x2.f32 %0, %1, %2;" : "=r"(d) : "f"(hi), "f"(lo));
    return d;
}

// ---------------- scratch (device globals; no allocations allowed) ----------
__device__ __half g_q [(size_t)BATCH*32*SEQ*HDIM];
__device__ __half g_k [(size_t)BATCH*16*SEQ*HDIM];
__device__ __half g_v [(size_t)BATCH*16*SEQ*HDIM];
__device__ float g_y  [(size_t)BATCH*32*SEQ*HDIM];
__device__ float g_lam[(size_t)BATCH*16*SEQ];
__device__ float g_yc [(size_t)BATCH*SEQ*DMODEL];
// bf16 split buffers
__device__ __nv_bfloat16 g_xh[(size_t)MTOT*DMODEL];
__device__ __nv_bfloat16 g_xl[(size_t)MTOT*DMODEL];
__device__ __nv_bfloat16 g_wh[5][(size_t)DMODEL*DMODEL];   // W^T hi, [N][K]
__device__ __nv_bfloat16 g_wl[5][(size_t)DMODEL*DMODEL];   // W^T lo

// ============================ split kernels ==================================
__global__ void __launch_bounds__(256)
split_x_kernel(const float* __restrict__ X, __nv_bfloat16* __restrict__ H,
               __nv_bfloat16* __restrict__ L, int n4)
{
    int i = blockIdx.x * blockDim.x + threadIdx.x;
    if (i >= n4) return;
    float4 v = ((const float4*)X)[i];
    __nv_bfloat16 h0 = __float2bfloat16(v.x);
    __nv_bfloat16 h1 = __float2bfloat16(v.y);
    __nv_bfloat16 h2 = __float2bfloat16(v.z);
    __nv_bfloat16 h3 = __float2bfloat16(v.w);
    __nv_bfloat16 l0 = __float2bfloat16(v.x - __bfloat162float(h0));
    __nv_bfloat16 l1 = __float2bfloat16(v.y - __bfloat162float(h1));
    __nv_bfloat16 l2 = __float2bfloat16(v.z - __bfloat162float(h2));
    __nv_bfloat16 l3 = __float2bfloat16(v.w - __bfloat162float(h3));
    __nv_bfloat162* Hp = (__nv_bfloat162*)H;
    __nv_bfloat162* Lp = (__nv_bfloat162*)L;
    Hp[2*i]   = __nv_bfloat162(h0, h1);
    Hp[2*i+1] = __nv_bfloat162(h2, h3);
    Lp[2*i]   = __nv_bfloat162(l0, l1);
    Lp[2*i+1] = __nv_bfloat162(l2, l3);
}

// W [K][N] fp32 -> OH/OL [N][K] bf16  (transpose + split), K=N=2048
__global__ void __launch_bounds__(256)
splitT_kernel(const float* __restrict__ W, __nv_bfloat16* __restrict__ OH,
              __nv_bfloat16* __restrict__ OL)
{
    __shared__ float t[32][33];
    int nx = blockIdx.x * 32, ky = blockIdx.y * 32;
    int tx = threadIdx.x, ty = threadIdx.y;   // 32 x 8
#pragma unroll
    for (int i = 0; i < 4; i++)
        t[ty + 8*i][tx] = W[(size_t)(ky + ty + 8*i) * DMODEL + nx + tx];
    __syncthreads();
#pragma unroll
    for (int i = 0; i < 4; i++) {
        float v = t[tx][ty + 8*i];
        __nv_bfloat16 h = __float2bfloat16(v);
        __nv_bfloat16 l = __float2bfloat16(v - __bfloat162float(h));
        size_t o = (size_t)(nx + ty + 8*i) * DMODEL + ky + tx;
        OH[o] = h; OL[o] = l;
    }
}

// ===================== mma.sync split-bf16 GEMM ==============================
// C[4096,2048] = A[M,K] @ B^T, A as (Ah,Al) [M][K] bf16; B as (Bh,Bl) [N][K].
// MODE 0: row-major fp32 store. MODE 1: head-scatter fp16 store.
#define GK     2048
#define NKCH   64            // K chunks of 32
#define PITCH  40            // bf16 elems per smem row (80B)
#define BUF_B  (128*PITCH*2)
#define STAGE_B (4*BUF_B)
#define GEMM_SMEM (2*STAGE_B)

template <int MODE>
__global__ void __launch_bounds__(256, 1)
tc_gemm(const __nv_bfloat16* __restrict__ Ah, const __nv_bfloat16* __restrict__ Al,
        const __nv_bfloat16* __restrict__ Bh, const __nv_bfloat16* __restrict__ Bl,
        void* __restrict__ Cout, int headsTotal, int headOffset)
{
    extern __shared__ char dsm[];
    const uint32_t smbase = smem_to_u32(dsm);

    const int tid = threadIdx.x;
    const int wid = tid >> 5;
    const int lid = tid & 31;
    const int wm = wid >> 2;
    const int wn = wid & 3;

    const char* Asrc_h = (const char*)(Ah + (size_t)blockIdx.y * 128 * GK);
    const char* Asrc_l = (const char*)(Al + (size_t)blockIdx.y * 128 * GK);
    const char* Bsrc_h = (const char*)(Bh + (size_t)blockIdx.x * 128 * GK);
    const char* Bsrc_l = (const char*)(Bl + (size_t)blockIdx.x * 128 * GK);

    const int lrow0 = tid >> 2;
    const int lc16  = tid & 3;

    auto load_chunk = [&](int kt, int st) {
        uint32_t sb = smbase + st * STAGE_B;
        size_t go = (size_t)kt * 64 + lc16 * 16;
        const char* src[4] = { Asrc_h, Asrc_l, Bsrc_h, Bsrc_l };
#pragma unroll
        for (int bi = 0; bi < 4; bi++) {
            uint32_t bo = sb + bi * BUF_B;
#pragma unroll
            for (int i = 0; i < 2; i++) {
                int row = lrow0 + i * 64;
                cp_async16(bo + row * (PITCH*2) + lc16 * 16,
                           src[bi] + (size_t)row * (GK*2) + go);
            }
        }
    };

    float acc[4][4][4];
#pragma unroll
    for (int mi = 0; mi < 4; mi++)
#pragma unroll
        for (int nj = 0; nj < 4; nj++)
#pragma unroll
            for (int e = 0; e < 4; e++) acc[mi][nj][e] = 0.f;

    load_chunk(0, 0); CP_COMMIT();
    load_chunk(1, 1); CP_COMMIT();

    const int lrow = lid & 15;
    const int lhalf = (lid >> 4) * 16;

    for (int kt = 0; kt < NKCH; kt++) {
        if (kt + 1 < NKCH) { CP_WAIT1(); } else { CP_WAIT0(); }
        __syncthreads();

        uint32_t sb = smbase + (kt & 1) * STAGE_B;
        uint32_t a_h = sb;
        uint32_t a_l = sb + BUF_B;
        uint32_t b_h = sb + 2*BUF_B;
        uint32_t b_l = sb + 3*BUF_B;

#pragma unroll
        for (int k16 = 0; k16 < 2; k16++) {
            const int kb = k16 * 32 + lhalf;
            uint32_t ah[4][4], al[4][4], bh[2][4], bl[2][4];
#pragma unroll
            for (int mi = 0; mi < 4; mi++) {
                int r = wm * 64 + mi * 16 + lrow;
                ldsm_x4(ah[mi][0], ah[mi][1], ah[mi][2], ah[mi][3],
                        a_h + r * (PITCH*2) + kb);
                ldsm_x4(al[mi][0], al[mi][1], al[mi][2], al[mi][3],
                        a_l + r * (PITCH*2) + kb);
            }
#pragma unroll
            for (int ni = 0; ni < 2; ni++) {
                int r = wn * 32 + ni * 16 + lrow;
                ldsm_x4(bh[ni][0], bh[ni][1], bh[ni][2], bh[ni][3],
                        b_h + r * (PITCH*2) + kb);
                ldsm_x4(bl[ni][0], bl[ni][1], bl[ni][2], bl[ni][3],
                        b_l + r * (PITCH*2) + kb);
            }
#pragma unroll
            for (int mi = 0; mi < 4; mi++)
#pragma unroll
                for (int nj = 0; nj < 4; nj++) {
                    int ni = nj >> 1, sub = nj & 1;
                    uint32_t b0h = bh[ni][sub],     b1h = bh[ni][sub + 2];
                    uint32_t b0l = bl[ni][sub],     b1l = bl[ni][sub + 2];
                    mma_bf16(acc[mi][nj], ah[mi], b0h, b1h);
                    mma_bf16(acc[mi][nj], ah[mi], b0l, b1l);
                    mma_bf16(acc[mi][nj], al[mi], b0h, b1h);
                }
        }
        __syncthreads();
        if (kt + 2 < NKCH) { load_chunk(kt + 2, kt & 1); CP_COMMIT(); }
    }

    const int lg = lid >> 2;
    const int lc = (lid & 3) * 2;
#pragma unroll
    for (int mi = 0; mi < 4; mi++) {
        int row0 = blockIdx.y * 128 + wm * 64 + mi * 16 + lg;
#pragma unroll
        for (int half = 0; half < 2; half++) {
            int row = row0 + half * 8;
            if (MODE == 0) {
                float* dst = (float*)Cout + (size_t)row * DMODEL + blockIdx.x * 128;
#pragma unroll
                for (int nj = 0; nj < 4; nj++) {
                    int n = wn * 32 + nj * 8 + lc;
                    float2 v;
                    v.x = acc[mi][nj][half * 2 + 0];
                    v.y = acc[mi][nj][half * 2 + 1];
                    *(float2*)(dst + n) = v;
                }
            } else {
                int b = row >> 11;
                int t = row & (SEQ - 1);
                int h = headOffset + blockIdx.x;
                __half* dst = (__half*)Cout +
                    (((size_t)(b * headsTotal + h)) * SEQ + t) * HDIM;
#pragma unroll
                for (int nj = 0; nj < 4; nj++) {
                    int n = wn * 32 + nj * 8 + lc;
                    __half2 v = __floats2half2_rn(acc[mi][nj][half*2],
                                                  acc[mi][nj][half*2+1]);
                    *(__half2*)(dst + n) = v;
                }
            }
        }
    }
}

// ============================ lambda gate ====================================
__global__ void __launch_bounds__(128)
lam_kernel(const float* __restrict__ x, const float* __restrict__ Wl,
           float* __restrict__ lam)
{
    int btok = blockIdx.x;
    int b = btok >> 11, t = btok & (SEQ - 1);
    const float* xr = x + (size_t)btok * DMODEL;

    float acc[16];
#pragma unroll
    for (int h = 0; h < 16; h++) acc[h] = 0.f;

    for (int k = threadIdx.x; k < DMODEL; k += 128) {
        float xv = xr[k];
        const float4* w = (const float4*)(Wl + (size_t)k * 16);
        float4 w0 = w[0], w1 = w[1], w2 = w[2], w3 = w[3];
        acc[0]  = fmaf(xv, w0.x, acc[0]);  acc[1]  = fmaf(xv, w0.y, acc[1]);
        acc[2]  = fmaf(xv, w0.z, acc[2]);  acc[3]  = fmaf(xv, w0.w, acc[3]);
        acc[4]  = fmaf(xv, w1.x, acc[4]);  acc[5]  = fmaf(xv, w1.y, acc[5]);
        acc[6]  = fmaf(xv, w1.z, acc[6]);  acc[7]  = fmaf(xv, w1.w, acc[7]);
        acc[8]  = fmaf(xv, w2.x, acc[8]);  acc[9]  = fmaf(xv, w2.y, acc[9]);
        acc[10] = fmaf(xv, w2.z, acc[10]); acc[11] = fmaf(xv, w2.w, acc[11]);
        acc[12] = fmaf(xv, w3.x, acc[12]); acc[13] = fmaf(xv, w3.y, acc[13]);
        acc[14] = fmaf(xv, w3.z, acc[14]); acc[15] = fmaf(xv, w3.w, acc[15]);
    }

    __shared__ float red[128][16];
#pragma unroll
    for (int h = 0; h < 16; h++) red[threadIdx.x][h] = acc[h];
    __syncthreads();
    for (int s = 64; s > 0; s >>= 1) {
        if (threadIdx.x < s)
#pragma unroll
            for (int h = 0; h < 16; h++)
                red[threadIdx.x][h] += red[threadIdx.x + s][h];
        __syncthreads();
    }
    if (threadIdx.x < 16) {
        float vv = red[0][threadIdx.x];
        lam[((size_t)b * 16 + threadIdx.x) * SEQ + t] = 1.f / (1.f + __expf(-vv));
    }
}

// ================= flash attention (mma.sync fp16) ===========================
// Q: [B,32,T,128] fp16; K,V: [B,16,T,128] fp16; Y: [B,32,T,128] fp32.
// 4 warps/CTA, 64 q-rows per CTA, 64-key tiles, ones-column row-sum trick.
#define APITCH 272            // bytes per smem row (136 halves)
#define KSTAGE 17408          // 64*272
#define VSTAGE 17680          // 65*272 (pad row for trans ldsm overread)
#define ATT_SMEM (17408 + 2*KSTAGE + 2*VSTAGE)   // Q + K*2 + V*2 = 87584
#define ACL 0.12751744f       // (1/sqrt(128)) * log2(e)

__global__ void __launch_bounds__(128)
attn_kernel(const __half* __restrict__ Q, const __half* __restrict__ Kg,
            const __half* __restrict__ Vg, float* __restrict__ Y)
{
    extern __shared__ char asmem[];
    const uint32_t sb  = smem_to_u32(asmem);
    const uint32_t Qs  = sb;
    const uint32_t Ks0 = sb + 17408;
    const uint32_t Vs0 = Ks0 + 2*KSTAGE;

    const int qb = blockIdx.x, hs = blockIdx.y, b = blockIdx.z;
    const int kvh = hs >> 1;
    const int tid = threadIdx.x;
    const int wid = tid >> 5, lid = tid & 31;
    const int wq = wid * 16;
    const int g = lid >> 2, qd = lid & 3;

    const __half* Qb = Q  + (((size_t)(b*32 + hs))  * SEQ + qb * 64) * HDIM;
    const __half* Kb = Kg + ((size_t)(b*16 + kvh)) * SEQ * HDIM;
    const __half* Vb = Vg + ((size_t)(b*16 + kvh)) * SEQ * HDIM;

    // ones/zeros columns 128..135 of V smem (both stages, incl pad row)
    for (int idx = tid; idx < 130; idx += 128) {
        int st = idx / 65, r = idx % 65;
        *(uint4*)(asmem + (Vs0 - sb) + st*VSTAGE + r*APITCH + 256) =
            make_uint4(0x00003C00u, 0u, 0u, 0u);
    }

    auto load_q = [&]() {
#pragma unroll
        for (int i = 0; i < 8; i++) {
            int id = i*128 + tid, r = id >> 4, c = id & 15;
            cp_async16(Qs + r*APITCH + c*16, (const char*)Qb + r*256 + c*16);
        }
    };
    auto load_kv = [&](int jt, int st) {
        const char* kp = (const char*)(Kb + (size_t)jt * 64 * HDIM);
        const char* vp = (const char*)(Vb + (size_t)jt * 64 * HDIM);
#pragma unroll
        for (int i = 0; i < 8; i++) {
            int id = i*128 + tid, r = id >> 4, c = id & 15;
            cp_async16(Ks0 + st*KSTAGE + r*APITCH + c*16, kp + r*256 + c*16);
            cp_async16(Vs0 + st*VSTAGE + r*APITCH + c*16, vp + r*256 + c*16);
        }
    };

    const int ntiles = qb + 1;
    load_q(); load_kv(0, 0); CP_COMMIT();
    if (ntiles > 1) load_kv(1, 1);
    CP_COMMIT();

    float o[17][4];
#pragma unroll
    for (int d = 0; d < 17; d++)
#pragma unroll
        for (int e = 0; e < 4; e++) o[d][e] = 0.f;
    float M_lo = -INFINITY, M_hi = -INFINITY;
    uint32_t qf[8][4];

    const int lr16 = lid & 15;
    const int lh16 = (lid >> 4) * 16;

    for (int jt = 0; jt < ntiles; jt++) {
        CP_WAIT1();
        __syncthreads();
        if (jt == 0) {
#pragma unroll
            for (int k16 = 0; k16 < 8; k16++)
                ldsm_x4(qf[k16][0], qf[k16][1], qf[k16][2], qf[k16][3],
                        Qs + (wq + lr16)*APITCH + k16*32 + lh16);
        }
        const uint32_t Ks = Ks0 + (jt & 1) * KSTAGE;
        const uint32_t Vs = Vs0 + (jt & 1) * VSTAGE;

        // ---- S = Q K^T
        float sa[8][4];
#pragma unroll
        for (int j = 0; j < 8; j++)
#pragma unroll
            for (int e = 0; e < 4; e++) sa[j][e] = 0.f;

#pragma unroll
        for (int k16 = 0; k16 < 8; k16++) {
            uint32_t kb[4][4];
#pragma unroll
            for (int nb = 0; nb < 4; nb++)
                ldsm_x4(kb[nb][0], kb[nb][1], kb[nb][2], kb[nb][3],
                        Ks + (nb*16 + lr16)*APITCH + k16*32 + lh16);
#pragma unroll
            for (int j = 0; j < 8; j++) {
                int nb = j >> 1, sub = j & 1;
                mma_f16(sa[j], qf[k16], kb[nb][sub], kb[nb][sub + 2]);
            }
        }

        // ---- causal mask on diagonal tile
        if (jt == qb) {
#pragma unroll
            for (int j = 0; j < 8; j++) {
                int colb = j*8 + qd*2;
#pragma unroll
                for (int e = 0; e < 4; e++) {
                    int colg = colb + (e & 1);
                    int rowg = wq + g + (e >> 1) * 8;
                    if (colg > rowg) sa[j][e] = -INFINITY;
                }
            }
        }

        // ---- online softmax (registers + quad shuffles)
        float mx_lo = -INFINITY, mx_hi = -INFINITY;
#pragma unroll
        for (int j = 0; j < 8; j++) {
            mx_lo = fmaxf(mx_lo, fmaxf(sa[j][0], sa[j][1]));
            mx_hi = fmaxf(mx_hi, fmaxf(sa[j][2], sa[j][3]));
        }
        mx_lo = fmaxf(mx_lo, __shfl_xor_sync(0xffffffffu, mx_lo, 1));
        mx_lo = fmaxf(mx_lo, __shfl_xor_sync(0xffffffffu, mx_lo, 2));
        mx_hi = fmaxf(mx_hi, __shfl_xor_sync(0xffffffffu, mx_hi, 1));
        mx_hi = fmaxf(mx_hi, __shfl_xor_sync(0xffffffffu, mx_hi, 2));
        float Mn_lo = fmaxf(M_lo, mx_lo * ACL);
        float Mn_hi = fmaxf(M_hi, mx_hi * ACL);
        float al_lo = ex2f(M_lo - Mn_lo);
        float al_hi = ex2f(M_hi - Mn_hi);
        M_lo = Mn_lo; M_hi = Mn_hi;

        uint32_t p16[8][2];
#pragma unroll
        for (int j = 0; j < 8; j++) {
            float p0 = ex2f(fmaf(sa[j][0], ACL, -Mn_lo));
            float p1 = ex2f(fmaf(sa[j][1], ACL, -Mn_lo));
            float p2 = ex2f(fmaf(sa[j][2], ACL, -Mn_hi));
            float p3 = ex2f(fmaf(sa[j][3], ACL, -Mn_hi));
            p16[j][0] = packh2(p0, p1);
            p16[j][1] = packh2(p2, p3);
        }

#pragma unroll
        for (int d = 0; d < 17; d++) {
            o[d][0] *= al_lo; o[d][1] *= al_lo;
            o[d][2] *= al_hi; o[d][3] *= al_hi;
        }

        // ---- O += P V  (ones column at d-tile 16 accumulates l)
#pragma unroll
        for (int kk = 0; kk < 4; kk++) {
            uint32_t pa[4] = { p16[2*kk][0], p16[2*kk][1],
                               p16[2*kk+1][0], p16[2*kk+1][1] };
#pragma unroll
            for (int dp = 0; dp < 9; dp++) {
                uint32_t vb0, vb1, vb2, vb3;
                ldsm_x4t(vb0, vb1, vb2, vb3,
                         Vs + (kk*16 + lr16)*APITCH + dp*32 + lh16);
                mma_f16(o[2*dp], pa, vb0, vb1);
                if (dp < 8) mma_f16(o[2*dp + 1], pa, vb2, vb3);
            }
        }

        __syncthreads();
        if (jt + 2 < ntiles) load_kv(jt + 2, jt & 1);
        CP_COMMIT();
    }

    // ---- epilogue
    float l_lo = __shfl_sync(0xffffffffu, o[16][0], lid & ~3);
    float l_hi = __shfl_sync(0xffffffffu, o[16][2], lid & ~3);
    float r_lo = 1.f / l_lo;
    float r_hi = 1.f / l_hi;
    float* Y0 = Y + (((size_t)(b*32 + hs)) * SEQ + qb*64 + wq + g) * HDIM;
    float* Y1 = Y0 + 8 * HDIM;
#pragma unroll
    for (int dj = 0; dj < 16; dj++) {
        float2 v0 = make_float2(o[dj][0] * r_lo, o[dj][1] * r_lo);
        float2 v1 = make_float2(o[dj][2] * r_hi, o[dj][3] * r_hi);
        *(float2*)(Y0 + dj*8 + qd*2) = v0;
        *(float2*)(Y1 + dj*8 + qd*2) = v1;
    }
}

// ============================ combine y1 - lam*y2 ============================
__global__ void __launch_bounds__(256)
combine_kernel(const float* __restrict__ Yin, const float* __restrict__ lam,
               float* __restrict__ Yc)
{
    size_t slot = (size_t)blockIdx.x * blockDim.x + threadIdx.x;
    size_t e = slot * 4;
    const size_t total = (size_t)BATCH * SEQ * DMODEL;
    if (e >= total) return;
    int dd = (int)(e & 127);
    int h  = (int)((e >> 7) & 15);
    int t  = (int)((e >> 11) & (SEQ - 1));
    int b  = (int)(e >> 22);

    float4 y1 = *(const float4*)&Yin[(((size_t)(b*32 + h))      * SEQ + t) * HDIM + dd];
    float4 y2 = *(const float4*)&Yin[(((size_t)(b*32 + 16 + h)) * SEQ + t) * HDIM + dd];
    float l = lam[((size_t)b * 16 + h) * SEQ + t];
    float4 r;
    r.x = y1.x - l * y2.x;  r.y = y1.y - l * y2.y;
    r.z = y1.z - l * y2.z;  r.w = y1.w - l * y2.w;
    *(float4*)&Yc[e] = r;
}

// ================================= launch ====================================
extern "C" void kernel_launch(void* const* d_in, const int* in_sizes, int n_in,
                              void* d_out, int out_size)
{
    const float* x    = (const float*)d_in[0];
    const float* Wq1  = (const float*)d_in[1];
    const float* Wq2  = (const float*)d_in[2];
    const float* Wk   = (const float*)d_in[3];
    const float* Wv   = (const float*)d_in[4];
    const float* Wlam = (const float*)d_in[5];
    const float* Wo   = (const float*)d_in[6];
    float* out = (float*)d_out;

    __half *q, *k, *v;
    float *y, *lam, *yc;
    __nv_bfloat16 *xh, *xl, *wh, *wl;
    cudaGetSymbolAddress((void**)&q,   g_q);
    cudaGetSymbolAddress((void**)&k,   g_k);
    cudaGetSymbolAddress((void**)&v,   g_v);
    cudaGetSymbolAddress((void**)&y,   g_y);
    cudaGetSymbolAddress((void**)&lam, g_lam);
    cudaGetSymbolAddress((void**)&yc,  g_yc);
    cudaGetSymbolAddress((void**)&xh,  g_xh);
    cudaGetSymbolAddress((void**)&xl,  g_xl);
    cudaGetSymbolAddress((void**)&wh,  g_wh);
    cudaGetSymbolAddress((void**)&wl,  g_wl);

    cudaFuncSetAttribute(attn_kernel,
                         cudaFuncAttributeMaxDynamicSharedMemorySize, ATT_SMEM);
    cudaFuncSetAttribute(tc_gemm<0>,
                         cudaFuncAttributeMaxDynamicSharedMemorySize, GEMM_SMEM);
    cudaFuncSetAttribute(tc_gemm<1>,
                         cudaFuncAttributeMaxDynamicSharedMemorySize, GEMM_SMEM);

    const size_t WSZ = (size_t)DMODEL * DMODEL;
    const int n4x = MTOT * DMODEL / 4;
    dim3 tgrid(64, 64), tblk(32, 8);
    dim3 ggrid(DMODEL / 128, MTOT / 128);   // (16, 32)

    // splits
    split_x_kernel<<<(n4x + 255) / 256, 256>>>(x, xh, xl, n4x);
    splitT_kernel<<<tgrid, tblk>>>(Wq1, wh + 0*WSZ, wl + 0*WSZ);
    splitT_kernel<<<tgrid, tblk>>>(Wq2, wh + 1*WSZ, wl + 1*WSZ);
    splitT_kernel<<<tgrid, tblk>>>(Wk,  wh + 2*WSZ, wl + 2*WSZ);
    splitT_kernel<<<tgrid, tblk>>>(Wv,  wh + 3*WSZ, wl + 3*WSZ);
    splitT_kernel<<<tgrid, tblk>>>(Wo,  wh + 4*WSZ, wl + 4*WSZ);

    // projections -> fp16 head-scattered q/k/v
    tc_gemm<1><<<ggrid, 256, GEMM_SMEM>>>(xh, xl, wh + 0*WSZ, wl + 0*WSZ, q, 32, 0);
    tc_gemm<1><<<ggrid, 256, GEMM_SMEM>>>(xh, xl, wh + 1*WSZ, wl + 1*WSZ, q, 32, 16);
    tc_gemm<1><<<ggrid, 256, GEMM_SMEM>>>(xh, xl, wh + 2*WSZ, wl + 2*WSZ, k, 16, 0);
    tc_gemm<1><<<ggrid, 256, GEMM_SMEM>>>(xh, xl, wh + 3*WSZ, wl + 3*WSZ, v, 16, 0);

    lam_kernel<<<MTOT, 128>>>(x, Wlam, lam);

    attn_kernel<<<dim3(SEQ / 64, 32, BATCH), 128, ATT_SMEM>>>(q, k, v, y);

    const size_t total = (size_t)BATCH * SEQ * DMODEL;
    combine_kernel<<<(unsigned)((total / 4 + 255) / 256), 256>>>(y, lam, yc);

    // output GEMM
    split_x_kernel<<<(n4x + 255) / 256, 256>>>(yc, xh, xl, n4x);
    tc_gemm<0><<<ggrid, 256, GEMM_SMEM>>>(xh, xl, wh + 4*WSZ, wl + 4*WSZ, out, 0, 0);
}

// round 5
// speedup vs baseline: 3.3873x; 1.5605x over previous
#include <cuda_runtime.h>
#include <cuda_bf16.h>
#include <cuda_fp16.h>
#include <math.h>
#include <stdint.h>

// Problem constants
#define BATCH 2
#define SEQ   2048
#define DMODEL 2048
#define NHEAD 16
#define HDIM  128
#define MTOT  (BATCH*SEQ)          // 4096

// ======================= PTX helpers (portable, sm_80+) =====================
__device__ __forceinline__ uint32_t smem_to_u32(const void* p) {
    uint32_t addr;
    asm("{ .reg .u64 tmp; cvta.to.shared.u64 tmp, %1; cvt.u32.u64 %0, tmp; }"
        : "=r"(addr) : "l"(p));
    return addr;
}
__device__ __forceinline__ void cp_async16(uint32_t smem, const void* gmem) {
    asm volatile("cp.async.cg.shared.global [%0], [%1], 16;"
                 :: "r"(smem), "l"(gmem) : "memory");
}
#define CP_COMMIT() asm volatile("cp.async.commit_group;" ::: "memory")
#define CP_WAIT1()  asm volatile("cp.async.wait_group 1;" ::: "memory")
#define CP_WAIT0()  asm volatile("cp.async.wait_group 0;" ::: "memory")

__device__ __forceinline__ void ldsm_x4(uint32_t& r0, uint32_t& r1,
                                        uint32_t& r2, uint32_t& r3, uint32_t a) {
    asm volatile("ldmatrix.sync.aligned.m8n8.x4.shared.b16 {%0,%1,%2,%3}, [%4];"
                 : "=r"(r0), "=r"(r1), "=r"(r2), "=r"(r3) : "r"(a));
}
__device__ __forceinline__ void ldsm_x4t(uint32_t& r0, uint32_t& r1,
                                         uint32_t& r2, uint32_t& r3, uint32_t a) {
    asm volatile("ldmatrix.sync.aligned.m8n8.x4.trans.shared.b16 {%0,%1,%2,%3}, [%4];"
                 : "=r"(r0), "=r"(r1), "=r"(r2), "=r"(r3) : "r"(a));
}
__device__ __forceinline__ void mma_bf16(float* c, const uint32_t* a,
                                         uint32_t b0, uint32_t b1) {
    asm volatile(
        "mma.sync.aligned.m16n8k16.row.col.f32.bf16.bf16.f32 "
        "{%0,%1,%2,%3}, {%4,%5,%6,%7}, {%8,%9}, {%0,%1,%2,%3};"
        : "+f"(c[0]), "+f"(c[1]), "+f"(c[2]), "+f"(c[3])
        : "r"(a[0]), "r"(a[1]), "r"(a[2]), "r"(a[3]), "r"(b0), "r"(b1));
}
__device__ __forceinline__ void mma_f16(float* c, const uint32_t* a,
                                        uint32_t b0, uint32_t b1) {
    asm volatile(
        "mma.sync.aligned.m16n8k16.row.col.f32.f16.f16.f32 "
        "{%0,%1,%2,%3}, {%4,%5,%6,%7}, {%8,%9}, {%0,%1,%2,%3};"
        : "+f"(c[0]), "+f"(c[1]), "+f"(c[2]), "+f"(c[3])
        : "r"(a[0]), "r"(a[1]), "r"(a[2]), "r"(a[3]), "r"(b0), "r"(b1));
}
__device__ __forceinline__ float ex2f(float x) {
    float r;
    asm("ex2.approx.f32 %0, %1;" : "=f"(r) : "f"(x));
    return r;
}
__device__ __forceinline__ uint32_t ex2_h2(float lo, float hi) {
    uint32_t packed, res;
    asm("cvt.rn.f16x2.f32 %0, %1, %2;" : "=r"(packed) : "f"(hi), "f"(lo));
    asm("ex2.approx.f16x2 %0, %1;" : "=r"(res) : "r"(packed));
    return res;
}

// ---------------- scratch (device globals; no allocations allowed) ----------
__device__ __half g_q [(size_t)BATCH*32*SEQ*HDIM];
__device__ __half g_k [(size_t)BATCH*16*SEQ*HDIM];
__device__ __half g_v [(size_t)BATCH*16*SEQ*HDIM];
__device__ float g_y  [(size_t)BATCH*32*SEQ*HDIM];
__device__ float g_lam[(size_t)BATCH*16*SEQ];
// bf16 split buffers
__device__ __nv_bfloat16 g_xh[(size_t)MTOT*DMODEL];
__device__ __nv_bfloat16 g_xl[(size_t)MTOT*DMODEL];
__device__ __nv_bfloat16 g_wh[5][(size_t)DMODEL*DMODEL];   // W^T hi, [N][K]
__device__ __nv_bfloat16 g_wl[5][(size_t)DMODEL*DMODEL];   // W^T lo

// ============================ split kernels ==================================
__global__ void __launch_bounds__(256)
split_x_kernel(const float* __restrict__ X, __nv_bfloat16* __restrict__ H,
               __nv_bfloat16* __restrict__ L, int n4)
{
    int i = blockIdx.x * blockDim.x + threadIdx.x;
    if (i >= n4) return;
    float4 v = ((const float4*)X)[i];
    __nv_bfloat16 h0 = __float2bfloat16(v.x);
    __nv_bfloat16 h1 = __float2bfloat16(v.y);
    __nv_bfloat16 h2 = __float2bfloat16(v.z);
    __nv_bfloat16 h3 = __float2bfloat16(v.w);
    __nv_bfloat16 l0 = __float2bfloat16(v.x - __bfloat162float(h0));
    __nv_bfloat16 l1 = __float2bfloat16(v.y - __bfloat162float(h1));
    __nv_bfloat16 l2 = __float2bfloat16(v.z - __bfloat162float(h2));
    __nv_bfloat16 l3 = __float2bfloat16(v.w - __bfloat162float(h3));
    __nv_bfloat162* Hp = (__nv_bfloat162*)H;
    __nv_bfloat162* Lp = (__nv_bfloat162*)L;
    Hp[2*i]   = __nv_bfloat162(h0, h1);
    Hp[2*i+1] = __nv_bfloat162(h2, h3);
    Lp[2*i]   = __nv_bfloat162(l0, l1);
    Lp[2*i+1] = __nv_bfloat162(l2, l3);
}

// W [K][N] fp32 -> OH/OL [N][K] bf16  (transpose + split), K=N=2048
__global__ void __launch_bounds__(256)
splitT_kernel(const float* __restrict__ W, __nv_bfloat16* __restrict__ OH,
              __nv_bfloat16* __restrict__ OL)
{
    __shared__ float t[32][33];
    int nx = blockIdx.x * 32, ky = blockIdx.y * 32;
    int tx = threadIdx.x, ty = threadIdx.y;   // 32 x 8
#pragma unroll
    for (int i = 0; i < 4; i++)
        t[ty + 8*i][tx] = W[(size_t)(ky + ty + 8*i) * DMODEL + nx + tx];
    __syncthreads();
#pragma unroll
    for (int i = 0; i < 4; i++) {
        float v = t[tx][ty + 8*i];
        __nv_bfloat16 h = __float2bfloat16(v);
        __nv_bfloat16 l = __float2bfloat16(v - __bfloat162float(h));
        size_t o = (size_t)(nx + ty + 8*i) * DMODEL + ky + tx;
        OH[o] = h; OL[o] = l;
    }
}

// ===================== mma.sync split-bf16 GEMM ==============================
// C[4096,2048] = A[M,K] @ B^T, A as (Ah,Al) [M][K] bf16; B as (Bh,Bl) [N][K].
// MODE 0: row-major fp32 store. MODE 1: head-scatter fp16 store.
#define GK     2048
#define NKCH   64            // K chunks of 32
#define PITCH  40            // bf16 elems per smem row (80B)
#define BUF_B  (128*PITCH*2)
#define STAGE_B (4*BUF_B)
#define GEMM_SMEM (2*STAGE_B)

template <int MODE>
__global__ void __launch_bounds__(256, 1)
tc_gemm(const __nv_bfloat16* __restrict__ Ah, const __nv_bfloat16* __restrict__ Al,
        const __nv_bfloat16* __restrict__ Bh, const __nv_bfloat16* __restrict__ Bl,
        void* __restrict__ Cout, int headsTotal, int headOffset)
{
    extern __shared__ char dsm[];
    const uint32_t smbase = smem_to_u32(dsm);

    const int tid = threadIdx.x;
    const int wid = tid >> 5;
    const int lid = tid & 31;
    const int wm = wid >> 2;
    const int wn = wid & 3;

    const char* Asrc_h = (const char*)(Ah + (size_t)blockIdx.y * 128 * GK);
    const char* Asrc_l = (const char*)(Al + (size_t)blockIdx.y * 128 * GK);
    const char* Bsrc_h = (const char*)(Bh + (size_t)blockIdx.x * 128 * GK);
    const char* Bsrc_l = (const char*)(Bl + (size_t)blockIdx.x * 128 * GK);

    const int lrow0 = tid >> 2;
    const int lc16  = tid & 3;

    auto load_chunk = [&](int kt, int st) {
        uint32_t sb = smbase + st * STAGE_B;
        size_t go = (size_t)kt * 64 + lc16 * 16;
        const char* src[4] = { Asrc_h, Asrc_l, Bsrc_h, Bsrc_l };
#pragma unroll
        for (int bi = 0; bi < 4; bi++) {
            uint32_t bo = sb + bi * BUF_B;
#pragma unroll
            for (int i = 0; i < 2; i++) {
                int row = lrow0 + i * 64;
                cp_async16(bo + row * (PITCH*2) + lc16 * 16,
                           src[bi] + (size_t)row * (GK*2) + go);
            }
        }
    };

    float acc[4][4][4];
#pragma unroll
    for (int mi = 0; mi < 4; mi++)
#pragma unroll
        for (int nj = 0; nj < 4; nj++)
#pragma unroll
            for (int e = 0; e < 4; e++) acc[mi][nj][e] = 0.f;

    load_chunk(0, 0); CP_COMMIT();
    load_chunk(1, 1); CP_COMMIT();

    const int lrow = lid & 15;
    const int lhalf = (lid >> 4) * 16;

    for (int kt = 0; kt < NKCH; kt++) {
        if (kt + 1 < NKCH) { CP_WAIT1(); } else { CP_WAIT0(); }
        __syncthreads();

        uint32_t sb = smbase + (kt & 1) * STAGE_B;
        uint32_t a_h = sb;
        uint32_t a_l = sb + BUF_B;
        uint32_t b_h = sb + 2*BUF_B;
        uint32_t b_l = sb + 3*BUF_B;

#pragma unroll
        for (int k16 = 0; k16 < 2; k16++) {
            const int kb = k16 * 32 + lhalf;
            uint32_t ah[4][4], al[4][4], bh[2][4], bl[2][4];
#pragma unroll
            for (int mi = 0; mi < 4; mi++) {
                int r = wm * 64 + mi * 16 + lrow;
                ldsm_x4(ah[mi][0], ah[mi][1], ah[mi][2], ah[mi][3],
                        a_h + r * (PITCH*2) + kb);
                ldsm_x4(al[mi][0], al[mi][1], al[mi][2], al[mi][3],
                        a_l + r * (PITCH*2) + kb);
            }
#pragma unroll
            for (int ni = 0; ni < 2; ni++) {
                int r = wn * 32 + ni * 16 + lrow;
                ldsm_x4(bh[ni][0], bh[ni][1], bh[ni][2], bh[ni][3],
                        b_h + r * (PITCH*2) + kb);
                ldsm_x4(bl[ni][0], bl[ni][1], bl[ni][2], bl[ni][3],
                        b_l + r * (PITCH*2) + kb);
            }
#pragma unroll
            for (int mi = 0; mi < 4; mi++)
#pragma unroll
                for (int nj = 0; nj < 4; nj++) {
                    int ni = nj >> 1, sub = nj & 1;
                    uint32_t b0h = bh[ni][sub],     b1h = bh[ni][sub + 2];
                    uint32_t b0l = bl[ni][sub],     b1l = bl[ni][sub + 2];
                    mma_bf16(acc[mi][nj], ah[mi], b0h, b1h);
                    mma_bf16(acc[mi][nj], ah[mi], b0l, b1l);
                    mma_bf16(acc[mi][nj], al[mi], b0h, b1h);
                }
        }
        __syncthreads();
        if (kt + 2 < NKCH) { load_chunk(kt + 2, kt & 1); CP_COMMIT(); }
    }

    const int lg = lid >> 2;
    const int lc = (lid & 3) * 2;
#pragma unroll
    for (int mi = 0; mi < 4; mi++) {
        int row0 = blockIdx.y * 128 + wm * 64 + mi * 16 + lg;
#pragma unroll
        for (int half = 0; half < 2; half++) {
            int row = row0 + half * 8;
            if (MODE == 0) {
                float* dst = (float*)Cout + (size_t)row * DMODEL + blockIdx.x * 128;
#pragma unroll
                for (int nj = 0; nj < 4; nj++) {
                    int n = wn * 32 + nj * 8 + lc;
                    float2 v;
                    v.x = acc[mi][nj][half * 2 + 0];
                    v.y = acc[mi][nj][half * 2 + 1];
                    *(float2*)(dst + n) = v;
                }
            } else {
                int b = row >> 11;
                int t = row & (SEQ - 1);
                int h = headOffset + blockIdx.x;
                __half* dst = (__half*)Cout +
                    (((size_t)(b * headsTotal + h)) * SEQ + t) * HDIM;
#pragma unroll
                for (int nj = 0; nj < 4; nj++) {
                    int n = wn * 32 + nj * 8 + lc;
                    __half2 v = __floats2half2_rn(acc[mi][nj][half*2],
                                                  acc[mi][nj][half*2+1]);
                    *(__half2*)(dst + n) = v;
                }
            }
        }
    }
}

// ============================ lambda gate ====================================
__global__ void __launch_bounds__(128)
lam_kernel(const float* __restrict__ x, const float* __restrict__ Wl,
           float* __restrict__ lam)
{
    int btok = blockIdx.x;
    int b = btok >> 11, t = btok & (SEQ - 1);
    const float* xr = x + (size_t)btok * DMODEL;

    float acc[16];
#pragma unroll
    for (int h = 0; h < 16; h++) acc[h] = 0.f;

    for (int k = threadIdx.x; k < DMODEL; k += 128) {
        float xv = xr[k];
        const float4* w = (const float4*)(Wl + (size_t)k * 16);
        float4 w0 = w[0], w1 = w[1], w2 = w[2], w3 = w[3];
        acc[0]  = fmaf(xv, w0.x, acc[0]);  acc[1]  = fmaf(xv, w0.y, acc[1]);
        acc[2]  = fmaf(xv, w0.z, acc[2]);  acc[3]  = fmaf(xv, w0.w, acc[3]);
        acc[4]  = fmaf(xv, w1.x, acc[4]);  acc[5]  = fmaf(xv, w1.y, acc[5]);
        acc[6]  = fmaf(xv, w1.z, acc[6]);  acc[7]  = fmaf(xv, w1.w, acc[7]);
        acc[8]  = fmaf(xv, w2.x, acc[8]);  acc[9]  = fmaf(xv, w2.y, acc[9]);
        acc[10] = fmaf(xv, w2.z, acc[10]); acc[11] = fmaf(xv, w2.w, acc[11]);
        acc[12] = fmaf(xv, w3.x, acc[12]); acc[13] = fmaf(xv, w3.y, acc[13]);
        acc[14] = fmaf(xv, w3.z, acc[14]); acc[15] = fmaf(xv, w3.w, acc[15]);
    }

    __shared__ float red[128][16];
#pragma unroll
    for (int h = 0; h < 16; h++) red[threadIdx.x][h] = acc[h];
    __syncthreads();
    for (int s = 64; s > 0; s >>= 1) {
        if (threadIdx.x < s)
#pragma unroll
            for (int h = 0; h < 16; h++)
                red[threadIdx.x][h] += red[threadIdx.x + s][h];
        __syncthreads();
    }
    if (threadIdx.x < 16) {
        float vv = red[0][threadIdx.x];
        lam[((size_t)b * 16 + threadIdx.x) * SEQ + t] = 1.f / (1.f + __expf(-vv));
    }
}

// ================= flash attention (mma.sync fp16) ===========================
// Q: [B,32,T,128] fp16; K,V: [B,16,T,128] fp16; Y: [B,32,T,128] fp32.
// 4 warps/CTA, 64 q-rows per CTA, 64-key tiles, ones-column row-sum trick.
#define APITCH 272            // bytes per smem row (136 halves)
#define KSTAGE 17408          // 64*272
#define VSTAGE 17680          // 65*272 (pad row for trans ldsm overread)
#define ATT_SMEM (17408 + 2*KSTAGE + 2*VSTAGE)   // Q + K*2 + V*2 = 87584
#define ACL 0.12751744f       // (1/sqrt(128)) * log2(e)

__global__ void __launch_bounds__(128)
attn_kernel(const __half* __restrict__ Q, const __half* __restrict__ Kg,
            const __half* __restrict__ Vg, float* __restrict__ Y)
{
    extern __shared__ char asmem[];
    const uint32_t sb  = smem_to_u32(asmem);
    const uint32_t Qs  = sb;
    const uint32_t Ks0 = sb + 17408;
    const uint32_t Vs0 = Ks0 + 2*KSTAGE;

    // heavy (large qb) CTAs first in launch order
    const int qb = gridDim.x - 1 - blockIdx.x;
    const int hs = blockIdx.y, b = blockIdx.z;
    const int kvh = hs >> 1;
    const int tid = threadIdx.x;
    const int wid = tid >> 5, lid = tid & 31;
    const int wq = wid * 16;
    const int g = lid >> 2, qd = lid & 3;

    const __half* Qb = Q  + (((size_t)(b*32 + hs))  * SEQ + qb * 64) * HDIM;
    const __half* Kb = Kg + ((size_t)(b*16 + kvh)) * SEQ * HDIM;
    const __half* Vb = Vg + ((size_t)(b*16 + kvh)) * SEQ * HDIM;

    // ones/zeros columns 128..135 of V smem (both stages, incl pad row)
    for (int idx = tid; idx < 130; idx += 128) {
        int st = idx / 65, r = idx % 65;
        *(uint4*)(asmem + (Vs0 - sb) + st*VSTAGE + r*APITCH + 256) =
            make_uint4(0x00003C00u, 0u, 0u, 0u);
    }

    auto load_q = [&]() {
#pragma unroll
        for (int i = 0; i < 8; i++) {
            int id = i*128 + tid, r = id >> 4, c = id & 15;
            cp_async16(Qs + r*APITCH + c*16, (const char*)Qb + r*256 + c*16);
        }
    };
    auto load_kv = [&](int jt, int st) {
        const char* kp = (const char*)(Kb + (size_t)jt * 64 * HDIM);
        const char* vp = (const char*)(Vb + (size_t)jt * 64 * HDIM);
#pragma unroll
        for (int i = 0; i < 8; i++) {
            int id = i*128 + tid, r = id >> 4, c = id & 15;
            cp_async16(Ks0 + st*KSTAGE + r*APITCH + c*16, kp + r*256 + c*16);
            cp_async16(Vs0 + st*VSTAGE + r*APITCH + c*16, vp + r*256 + c*16);
        }
    };

    const int ntiles = qb + 1;
    load_q(); load_kv(0, 0); CP_COMMIT();
    if (ntiles > 1) load_kv(1, 1);
    CP_COMMIT();

    float o[17][4];
#pragma unroll
    for (int d = 0; d < 17; d++)
#pragma unroll
        for (int e = 0; e < 4; e++) o[d][e] = 0.f;
    float M_lo = -INFINITY, M_hi = -INFINITY;
    uint32_t qf[8][4];

    const int lr16 = lid & 15;
    const int lh16 = (lid >> 4) * 16;

    for (int jt = 0; jt < ntiles; jt++) {
        CP_WAIT1();
        __syncthreads();
        if (jt == 0) {
#pragma unroll
            for (int k16 = 0; k16 < 8; k16++)
                ldsm_x4(qf[k16][0], qf[k16][1], qf[k16][2], qf[k16][3],
                        Qs + (wq + lr16)*APITCH + k16*32 + lh16);
        }
        const uint32_t Ks = Ks0 + (jt & 1) * KSTAGE;
        const uint32_t Vs = Vs0 + (jt & 1) * VSTAGE;

        // ---- S = Q K^T
        float sa[8][4];
#pragma unroll
        for (int j = 0; j < 8; j++)
#pragma unroll
            for (int e = 0; e < 4; e++) sa[j][e] = 0.f;

#pragma unroll
        for (int k16 = 0; k16 < 8; k16++) {
            uint32_t kb[4][4];
#pragma unroll
            for (int nb = 0; nb < 4; nb++)
                ldsm_x4(kb[nb][0], kb[nb][1], kb[nb][2], kb[nb][3],
                        Ks + (nb*16 + lr16)*APITCH + k16*32 + lh16);
#pragma unroll
            for (int j = 0; j < 8; j++) {
                int nb = j >> 1, sub = j & 1;
                mma_f16(sa[j], qf[k16], kb[nb][sub], kb[nb][sub + 2]);
            }
        }

        // ---- causal mask on diagonal tile
        if (jt == qb) {
#pragma unroll
            for (int j = 0; j < 8; j++) {
                int colb = j*8 + qd*2;
#pragma unroll
                for (int e = 0; e < 4; e++) {
                    int colg = colb + (e & 1);
                    int rowg = wq + g + (e >> 1) * 8;
                    if (colg > rowg) sa[j][e] = -INFINITY;
                }
            }
        }

        // ---- online softmax (registers + quad shuffles)
        float mx_lo = -INFINITY, mx_hi = -INFINITY;
#pragma unroll
        for (int j = 0; j < 8; j++) {
            mx_lo = fmaxf(mx_lo, fmaxf(sa[j][0], sa[j][1]));
            mx_hi = fmaxf(mx_hi, fmaxf(sa[j][2], sa[j][3]));
        }
        mx_lo = fmaxf(mx_lo, __shfl_xor_sync(0xffffffffu, mx_lo, 1));
        mx_lo = fmaxf(mx_lo, __shfl_xor_sync(0xffffffffu, mx_lo, 2));
        mx_hi = fmaxf(mx_hi, __shfl_xor_sync(0xffffffffu, mx_hi, 1));
        mx_hi = fmaxf(mx_hi, __shfl_xor_sync(0xffffffffu, mx_hi, 2));
        float Mn_lo = fmaxf(M_lo, mx_lo * ACL);
        float Mn_hi = fmaxf(M_hi, mx_hi * ACL);
        float al_lo = ex2f(M_lo - Mn_lo);
        float al_hi = ex2f(M_hi - Mn_hi);
        M_lo = Mn_lo; M_hi = Mn_hi;

        // exp in f16x2 (halves MUFU ops vs f32)
        uint32_t p16[8][2];
#pragma unroll
        for (int j = 0; j < 8; j++) {
            p16[j][0] = ex2_h2(fmaf(sa[j][0], ACL, -Mn_lo),
                               fmaf(sa[j][1], ACL, -Mn_lo));
            p16[j][1] = ex2_h2(fmaf(sa[j][2], ACL, -Mn_hi),
                               fmaf(sa[j][3], ACL, -Mn_hi));
        }

#pragma unroll
        for (int d = 0; d < 17; d++) {
            o[d][0] *= al_lo; o[d][1] *= al_lo;
            o[d][2] *= al_hi; o[d][3] *= al_hi;
        }

        // ---- O += P V  (ones column at d-tile 16 accumulates l)
#pragma unroll
        for (int kk = 0; kk < 4; kk++) {
            uint32_t pa[4] = { p16[2*kk][0], p16[2*kk][1],
                               p16[2*kk+1][0], p16[2*kk+1][1] };
#pragma unroll
            for (int dp = 0; dp < 9; dp++) {
                uint32_t vb0, vb1, vb2, vb3;
                ldsm_x4t(vb0, vb1, vb2, vb3,
                         Vs + (kk*16 + lr16)*APITCH + dp*32 + lh16);
                mma_f16(o[2*dp], pa, vb0, vb1);
                if (dp < 8) mma_f16(o[2*dp + 1], pa, vb2, vb3);
            }
        }

        __syncthreads();
        if (jt + 2 < ntiles) load_kv(jt + 2, jt & 1);
        CP_COMMIT();
    }

    // ---- epilogue
    float l_lo = __shfl_sync(0xffffffffu, o[16][0], lid & ~3);
    float l_hi = __shfl_sync(0xffffffffu, o[16][2], lid & ~3);
    float r_lo = 1.f / l_lo;
    float r_hi = 1.f / l_hi;
    float* Y0 = Y + (((size_t)(b*32 + hs)) * SEQ + qb*64 + wq + g) * HDIM;
    float* Y1 = Y0 + 8 * HDIM;
#pragma unroll
    for (int dj = 0; dj < 16; dj++) {
        float2 v0 = make_float2(o[dj][0] * r_lo, o[dj][1] * r_lo);
        float2 v1 = make_float2(o[dj][2] * r_hi, o[dj][3] * r_hi);
        *(float2*)(Y0 + dj*8 + qd*2) = v0;
        *(float2*)(Y1 + dj*8 + qd*2) = v1;
    }
}

// ================ combine y1 - lam*y2, fused bf16 split ======================
__global__ void __launch_bounds__(256)
combine_split_kernel(const float* __restrict__ Yin, const float* __restrict__ lam,
                     __nv_bfloat16* __restrict__ H, __nv_bfloat16* __restrict__ L)
{
    size_t slot = (size_t)blockIdx.x * blockDim.x + threadIdx.x;
    size_t e = slot * 4;
    const size_t total = (size_t)BATCH * SEQ * DMODEL;
    if (e >= total) return;
    int dd = (int)(e & 127);
    int h  = (int)((e >> 7) & 15);
    int t  = (int)((e >> 11) & (SEQ - 1));
    int b  = (int)(e >> 22);

    float4 y1 = *(const float4*)&Yin[(((size_t)(b*32 + h))      * SEQ + t) * HDIM + dd];
    float4 y2 = *(const float4*)&Yin[(((size_t)(b*32 + 16 + h)) * SEQ + t) * HDIM + dd];
    float l = lam[((size_t)b * 16 + h) * SEQ + t];
    float r0 = y1.x - l * y2.x, r1 = y1.y - l * y2.y;
    float r2 = y1.z - l * y2.z, r3 = y1.w - l * y2.w;

    __nv_bfloat16 h0 = __float2bfloat16(r0);
    __nv_bfloat16 h1 = __float2bfloat16(r1);
    __nv_bfloat16 h2 = __float2bfloat16(r2);
    __nv_bfloat16 h3 = __float2bfloat16(r3);
    __nv_bfloat16 l0 = __float2bfloat16(r0 - __bfloat162float(h0));
    __nv_bfloat16 l1 = __float2bfloat16(r1 - __bfloat162float(h1));
    __nv_bfloat16 l2 = __float2bfloat16(r2 - __bfloat162float(h2));
    __nv_bfloat16 l3 = __float2bfloat16(r3 - __bfloat162float(h3));
    __nv_bfloat162* Hp = (__nv_bfloat162*)(H + e);
    __nv_bfloat162* Lp = (__nv_bfloat162*)(L + e);
    Hp[0] = __nv_bfloat162(h0, h1);
    Hp[1] = __nv_bfloat162(h2, h3);
    Lp[0] = __nv_bfloat162(l0, l1);
    Lp[1] = __nv_bfloat162(l2, l3);
}

// ================================= launch ====================================
extern "C" void kernel_launch(void* const* d_in, const int* in_sizes, int n_in,
                              void* d_out, int out_size)
{
    const float* x    = (const float*)d_in[0];
    const float* Wq1  = (const float*)d_in[1];
    const float* Wq2  = (const float*)d_in[2];
    const float* Wk   = (const float*)d_in[3];
    const float* Wv   = (const float*)d_in[4];
    const float* Wlam = (const float*)d_in[5];
    const float* Wo   = (const float*)d_in[6];
    float* out = (float*)d_out;

    __half *q, *k, *v;
    float *y, *lam;
    __nv_bfloat16 *xh, *xl, *wh, *wl;
    cudaGetSymbolAddress((void**)&q,   g_q);
    cudaGetSymbolAddress((void**)&k,   g_k);
    cudaGetSymbolAddress((void**)&v,   g_v);
    cudaGetSymbolAddress((void**)&y,   g_y);
    cudaGetSymbolAddress((void**)&lam, g_lam);
    cudaGetSymbolAddress((void**)&xh,  g_xh);
    cudaGetSymbolAddress((void**)&xl,  g_xl);
    cudaGetSymbolAddress((void**)&wh,  g_wh);
    cudaGetSymbolAddress((void**)&wl,  g_wl);

    cudaFuncSetAttribute(attn_kernel,
                         cudaFuncAttributeMaxDynamicSharedMemorySize, ATT_SMEM);
    cudaFuncSetAttribute(tc_gemm<0>,
                         cudaFuncAttributeMaxDynamicSharedMemorySize, GEMM_SMEM);
    cudaFuncSetAttribute(tc_gemm<1>,
                         cudaFuncAttributeMaxDynamicSharedMemorySize, GEMM_SMEM);

    const size_t WSZ = (size_t)DMODEL * DMODEL;
    const int n4x = MTOT * DMODEL / 4;
    dim3 tgrid(64, 64), tblk(32, 8);
    dim3 ggrid(DMODEL / 128, MTOT / 128);   // (16, 32)

    // splits
    split_x_kernel<<<(n4x + 255) / 256, 256>>>(x, xh, xl, n4x);
    splitT_kernel<<<tgrid, tblk>>>(Wq1, wh + 0*WSZ, wl + 0*WSZ);
    splitT_kernel<<<tgrid, tblk>>>(Wq2, wh + 1*WSZ, wl + 1*WSZ);
    splitT_kernel<<<tgrid, tblk>>>(Wk,  wh + 2*WSZ, wl + 2*WSZ);
    splitT_kernel<<<tgrid, tblk>>>(Wv,  wh + 3*WSZ, wl + 3*WSZ);
    splitT_kernel<<<tgrid, tblk>>>(Wo,  wh + 4*WSZ, wl + 4*WSZ);

    // projections -> fp16 head-scattered q/k/v
    tc_gemm<1><<<ggrid, 256, GEMM_SMEM>>>(xh, xl, wh + 0*WSZ, wl + 0*WSZ, q, 32, 0);
    tc_gemm<1><<<ggrid, 256, GEMM_SMEM>>>(xh, xl, wh + 1*WSZ, wl + 1*WSZ, q, 32, 16);
    tc_gemm<1><<<ggrid, 256, GEMM_SMEM>>>(xh, xl, wh + 2*WSZ, wl + 2*WSZ, k, 16, 0);
    tc_gemm<1><<<ggrid, 256, GEMM_SMEM>>>(xh, xl, wh + 3*WSZ, wl + 3*WSZ, v, 16, 0);

    lam_kernel<<<MTOT, 128>>>(x, Wlam, lam);

    attn_kernel<<<dim3(SEQ / 64, 32, BATCH), 128, ATT_SMEM>>>(q, k, v, y);

    // combine + split fused (writes bf16 hi/lo directly)
    const size_t total = (size_t)BATCH * SEQ * DMODEL;
    combine_split_kernel<<<(unsigned)((total / 4 + 255) / 256), 256>>>(y, lam, xh, xl);

    // output GEMM
    tc_gemm<0><<<ggrid, 256, GEMM_SMEM>>>(xh, xl, wh + 4*WSZ, wl + 4*WSZ, out, 0, 0);
}

// round 6
// speedup vs baseline: 4.6062x; 1.3598x over previous
#include <cuda_runtime.h>
#include <cuda_bf16.h>
#include <cuda_fp16.h>
#include <math.h>
#include <stdint.h>

// Problem constants
#define BATCH 2
#define SEQ   2048
#define DMODEL 2048
#define NHEAD 16
#define HDIM  128
#define MTOT  (BATCH*SEQ)          // 4096

// ======================= PTX helpers (portable, sm_80+) =====================
__device__ __forceinline__ uint32_t smem_to_u32(const void* p) {
    uint32_t addr;
    asm("{ .reg .u64 tmp; cvta.to.shared.u64 tmp, %1; cvt.u32.u64 %0, tmp; }"
        : "=r"(addr) : "l"(p));
    return addr;
}
__device__ __forceinline__ void cp_async16(uint32_t smem, const void* gmem) {
    asm volatile("cp.async.cg.shared.global [%0], [%1], 16;"
                 :: "r"(smem), "l"(gmem) : "memory");
}
#define CP_COMMIT() asm volatile("cp.async.commit_group;" ::: "memory")
#define CP_WAIT1()  asm volatile("cp.async.wait_group 1;" ::: "memory")
#define CP_WAIT0()  asm volatile("cp.async.wait_group 0;" ::: "memory")

__device__ __forceinline__ void ldsm_x4(uint32_t& r0, uint32_t& r1,
                                        uint32_t& r2, uint32_t& r3, uint32_t a) {
    asm volatile("ldmatrix.sync.aligned.m8n8.x4.shared.b16 {%0,%1,%2,%3}, [%4];"
                 : "=r"(r0), "=r"(r1), "=r"(r2), "=r"(r3) : "r"(a));
}
__device__ __forceinline__ void ldsm_x4t(uint32_t& r0, uint32_t& r1,
                                         uint32_t& r2, uint32_t& r3, uint32_t a) {
    asm volatile("ldmatrix.sync.aligned.m8n8.x4.trans.shared.b16 {%0,%1,%2,%3}, [%4];"
                 : "=r"(r0), "=r"(r1), "=r"(r2), "=r"(r3) : "r"(a));
}
__device__ __forceinline__ void mma_f16(float* c, const uint32_t* a,
                                        uint32_t b0, uint32_t b1) {
    asm volatile(
        "mma.sync.aligned.m16n8k16.row.col.f32.f16.f16.f32 "
        "{%0,%1,%2,%3}, {%4,%5,%6,%7}, {%8,%9}, {%0,%1,%2,%3};"
        : "+f"(c[0]), "+f"(c[1]), "+f"(c[2]), "+f"(c[3])
        : "r"(a[0]), "r"(a[1]), "r"(a[2]), "r"(a[3]), "r"(b0), "r"(b1));
}
__device__ __forceinline__ float ex2f(float x) {
    float r;
    asm("ex2.approx.f32 %0, %1;" : "=f"(r) : "f"(x));
    return r;
}
__device__ __forceinline__ uint32_t ex2_h2(float lo, float hi) {
    uint32_t packed, res;
    asm("cvt.rn.f16x2.f32 %0, %1, %2;" : "=r"(packed) : "f"(hi), "f"(lo));
    asm("ex2.approx.f16x2 %0, %1;" : "=r"(res) : "r"(packed));
    return res;
}

// ---------------- scratch (device globals; no allocations allowed) ----------
__device__ __half g_q [(size_t)BATCH*32*SEQ*HDIM];
__device__ __half g_k [(size_t)BATCH*16*SEQ*HDIM];
__device__ __half g_v [(size_t)BATCH*16*SEQ*HDIM];
__device__ float g_y  [(size_t)BATCH*32*SEQ*HDIM];
__device__ float g_lam[(size_t)BATCH*16*SEQ];
// fp16 GEMM operands
__device__ __half g_xf[(size_t)MTOT*DMODEL];               // activations fp16
__device__ __half g_wh[5][(size_t)DMODEL*DMODEL];          // W^T hi, [N][K]
__device__ __half g_wl[5][(size_t)DMODEL*DMODEL];          // W^T lo

// ============================ conversion kernels =============================
__global__ void __launch_bounds__(256)
convert_x_kernel(const float* __restrict__ X, __half* __restrict__ F, int n4)
{
    int i = blockIdx.x * blockDim.x + threadIdx.x;
    if (i >= n4) return;
    float4 v = ((const float4*)X)[i];
    __half2* Fp = (__half2*)F;
    Fp[2*i]   = __floats2half2_rn(v.x, v.y);
    Fp[2*i+1] = __floats2half2_rn(v.z, v.w);
}

// W [K][N] fp32 -> OH/OL [N][K] fp16 (transpose + hi/lo split), K=N=2048
__global__ void __launch_bounds__(256)
splitT_kernel(const float* __restrict__ W, __half* __restrict__ OH,
              __half* __restrict__ OL)
{
    __shared__ float t[32][33];
    int nx = blockIdx.x * 32, ky = blockIdx.y * 32;
    int tx = threadIdx.x, ty = threadIdx.y;   // 32 x 8
#pragma unroll
    for (int i = 0; i < 4; i++)
        t[ty + 8*i][tx] = W[(size_t)(ky + ty + 8*i) * DMODEL + nx + tx];
    __syncthreads();
#pragma unroll
    for (int i = 0; i < 4; i++) {
        float v = t[tx][ty + 8*i];
        __half h = __float2half_rn(v);
        __half l = __float2half_rn(v - __half2float(h));
        size_t o = (size_t)(nx + ty + 8*i) * DMODEL + ky + tx;
        OH[o] = h; OL[o] = l;
    }
}

// ===================== mma.sync 2-product fp16 GEMM ==========================
// C[4096,2048] = A[M,K] @ B^T.  A fp16 [M][K]; B as (Bh,Bl) fp16 [N][K].
// D = A*Bh + A*Bl  (B split exact to 2^-22; only A-rounding error remains).
// MODE 0: row-major fp32 store. MODE 1: head-scatter fp16 store.
#define GK     2048
#define NKCH   64            // K chunks of 32
#define PITCH  40            // fp16 elems per smem row (80B)
#define BUF_B  (128*PITCH*2)
#define STAGE_B (3*BUF_B)    // A, Bh, Bl
#define GEMM_SMEM (2*STAGE_B)

template <int MODE>
__global__ void __launch_bounds__(256, 1)
tc_gemm(const __half* __restrict__ Af,
        const __half* __restrict__ Bh, const __half* __restrict__ Bl,
        void* __restrict__ Cout, int headsTotal, int headOffset)
{
    extern __shared__ char dsm[];
    const uint32_t smbase = smem_to_u32(dsm);

    const int tid = threadIdx.x;
    const int wid = tid >> 5;
    const int lid = tid & 31;
    const int wm = wid >> 2;
    const int wn = wid & 3;

    const char* Asrc   = (const char*)(Af + (size_t)blockIdx.y * 128 * GK);
    const char* Bsrc_h = (const char*)(Bh + (size_t)blockIdx.x * 128 * GK);
    const char* Bsrc_l = (const char*)(Bl + (size_t)blockIdx.x * 128 * GK);

    const int lrow0 = tid >> 2;
    const int lc16  = tid & 3;

    auto load_chunk = [&](int kt, int st) {
        uint32_t sb = smbase + st * STAGE_B;
        size_t go = (size_t)kt * 64 + lc16 * 16;
        const char* src[3] = { Asrc, Bsrc_h, Bsrc_l };
#pragma unroll
        for (int bi = 0; bi < 3; bi++) {
            uint32_t bo = sb + bi * BUF_B;
#pragma unroll
            for (int i = 0; i < 2; i++) {
                int row = lrow0 + i * 64;
                cp_async16(bo + row * (PITCH*2) + lc16 * 16,
                           src[bi] + (size_t)row * (GK*2) + go);
            }
        }
    };

    float acc[4][4][4];
#pragma unroll
    for (int mi = 0; mi < 4; mi++)
#pragma unroll
        for (int nj = 0; nj < 4; nj++)
#pragma unroll
            for (int e = 0; e < 4; e++) acc[mi][nj][e] = 0.f;

    load_chunk(0, 0); CP_COMMIT();
    load_chunk(1, 1); CP_COMMIT();

    const int lrow = lid & 15;
    const int lhalf = (lid >> 4) * 16;

    for (int kt = 0; kt < NKCH; kt++) {
        if (kt + 1 < NKCH) { CP_WAIT1(); } else { CP_WAIT0(); }
        __syncthreads();

        uint32_t sb = smbase + (kt & 1) * STAGE_B;
        uint32_t a_f = sb;
        uint32_t b_h = sb + BUF_B;
        uint32_t b_l = sb + 2*BUF_B;

#pragma unroll
        for (int k16 = 0; k16 < 2; k16++) {
            const int kb = k16 * 32 + lhalf;
            uint32_t af[4][4], bh[2][4], bl[2][4];
#pragma unroll
            for (int mi = 0; mi < 4; mi++) {
                int r = wm * 64 + mi * 16 + lrow;
                ldsm_x4(af[mi][0], af[mi][1], af[mi][2], af[mi][3],
                        a_f + r * (PITCH*2) + kb);
            }
#pragma unroll
            for (int ni = 0; ni < 2; ni++) {
                int r = wn * 32 + ni * 16 + lrow;
                ldsm_x4(bh[ni][0], bh[ni][1], bh[ni][2], bh[ni][3],
                        b_h + r * (PITCH*2) + kb);
                ldsm_x4(bl[ni][0], bl[ni][1], bl[ni][2], bl[ni][3],
                        b_l + r * (PITCH*2) + kb);
            }
#pragma unroll
            for (int mi = 0; mi < 4; mi++)
#pragma unroll
                for (int nj = 0; nj < 4; nj++) {
                    int ni = nj >> 1, sub = nj & 1;
                    mma_f16(acc[mi][nj], af[mi], bh[ni][sub], bh[ni][sub + 2]);
                    mma_f16(acc[mi][nj], af[mi], bl[ni][sub], bl[ni][sub + 2]);
                }
        }
        __syncthreads();
        if (kt + 2 < NKCH) { load_chunk(kt + 2, kt & 1); CP_COMMIT(); }
    }

    const int lg = lid >> 2;
    const int lc = (lid & 3) * 2;
#pragma unroll
    for (int mi = 0; mi < 4; mi++) {
        int row0 = blockIdx.y * 128 + wm * 64 + mi * 16 + lg;
#pragma unroll
        for (int half = 0; half < 2; half++) {
            int row = row0 + half * 8;
            if (MODE == 0) {
                float* dst = (float*)Cout + (size_t)row * DMODEL + blockIdx.x * 128;
#pragma unroll
                for (int nj = 0; nj < 4; nj++) {
                    int n = wn * 32 + nj * 8 + lc;
                    float2 v;
                    v.x = acc[mi][nj][half * 2 + 0];
                    v.y = acc[mi][nj][half * 2 + 1];
                    *(float2*)(dst + n) = v;
                }
            } else {
                int b = row >> 11;
                int t = row & (SEQ - 1);
                int h = headOffset + blockIdx.x;
                __half* dst = (__half*)Cout +
                    (((size_t)(b * headsTotal + h)) * SEQ + t) * HDIM;
#pragma unroll
                for (int nj = 0; nj < 4; nj++) {
                    int n = wn * 32 + nj * 8 + lc;
                    __half2 v = __floats2half2_rn(acc[mi][nj][half*2],
                                                  acc[mi][nj][half*2+1]);
                    *(__half2*)(dst + n) = v;
                }
            }
        }
    }
}

// ============================ lambda gate ====================================
__global__ void __launch_bounds__(128)
lam_kernel(const float* __restrict__ x, const float* __restrict__ Wl,
           float* __restrict__ lam)
{
    int btok = blockIdx.x;
    int b = btok >> 11, t = btok & (SEQ - 1);
    const float* xr = x + (size_t)btok * DMODEL;

    float acc[16];
#pragma unroll
    for (int h = 0; h < 16; h++) acc[h] = 0.f;

    for (int k = threadIdx.x; k < DMODEL; k += 128) {
        float xv = xr[k];
        const float4* w = (const float4*)(Wl + (size_t)k * 16);
        float4 w0 = w[0], w1 = w[1], w2 = w[2], w3 = w[3];
        acc[0]  = fmaf(xv, w0.x, acc[0]);  acc[1]  = fmaf(xv, w0.y, acc[1]);
        acc[2]  = fmaf(xv, w0.z, acc[2]);  acc[3]  = fmaf(xv, w0.w, acc[3]);
        acc[4]  = fmaf(xv, w1.x, acc[4]);  acc[5]  = fmaf(xv, w1.y, acc[5]);
        acc[6]  = fmaf(xv, w1.z, acc[6]);  acc[7]  = fmaf(xv, w1.w, acc[7]);
        acc[8]  = fmaf(xv, w2.x, acc[8]);  acc[9]  = fmaf(xv, w2.y, acc[9]);
        acc[10] = fmaf(xv, w2.z, acc[10]); acc[11] = fmaf(xv, w2.w, acc[11]);
        acc[12] = fmaf(xv, w3.x, acc[12]); acc[13] = fmaf(xv, w3.y, acc[13]);
        acc[14] = fmaf(xv, w3.z, acc[14]); acc[15] = fmaf(xv, w3.w, acc[15]);
    }

    __shared__ float red[128][16];
#pragma unroll
    for (int h = 0; h < 16; h++) red[threadIdx.x][h] = acc[h];
    __syncthreads();
    for (int s = 64; s > 0; s >>= 1) {
        if (threadIdx.x < s)
#pragma unroll
            for (int h = 0; h < 16; h++)
                red[threadIdx.x][h] += red[threadIdx.x + s][h];
        __syncthreads();
    }
    if (threadIdx.x < 16) {
        float vv = red[0][threadIdx.x];
        lam[((size_t)b * 16 + threadIdx.x) * SEQ + t] = 1.f / (1.f + __expf(-vv));
    }
}

// ================= flash attention (mma.sync fp16) ===========================
// Q: [B,32,T,128] fp16; K,V: [B,16,T,128] fp16; Y: [B,32,T,128] fp32.
#define APITCH 272            // bytes per smem row (136 halves)
#define KSTAGE 17408          // 64*272
#define VSTAGE 17680          // 65*272 (pad row for trans ldsm overread)
#define ATT_SMEM (17408 + 2*KSTAGE + 2*VSTAGE)   // 87584
#define ACL 0.12751744f       // (1/sqrt(128)) * log2(e)

__global__ void __launch_bounds__(128)
attn_kernel(const __half* __restrict__ Q, const __half* __restrict__ Kg,
            const __half* __restrict__ Vg, float* __restrict__ Y)
{
    extern __shared__ char asmem[];
    const uint32_t sb  = smem_to_u32(asmem);
    const uint32_t Qs  = sb;
    const uint32_t Ks0 = sb + 17408;
    const uint32_t Vs0 = Ks0 + 2*KSTAGE;

    const int qb = gridDim.x - 1 - blockIdx.x;   // heavy CTAs first
    const int hs = blockIdx.y, b = blockIdx.z;
    const int kvh = hs >> 1;
    const int tid = threadIdx.x;
    const int wid = tid >> 5, lid = tid & 31;
    const int wq = wid * 16;
    const int g = lid >> 2, qd = lid & 3;

    const __half* Qb = Q  + (((size_t)(b*32 + hs))  * SEQ + qb * 64) * HDIM;
    const __half* Kb = Kg + ((size_t)(b*16 + kvh)) * SEQ * HDIM;
    const __half* Vb = Vg + ((size_t)(b*16 + kvh)) * SEQ * HDIM;

    for (int idx = tid; idx < 130; idx += 128) {
        int st = idx / 65, r = idx % 65;
        *(uint4*)(asmem + (Vs0 - sb) + st*VSTAGE + r*APITCH + 256) =
            make_uint4(0x00003C00u, 0u, 0u, 0u);
    }

    auto load_q = [&]() {
#pragma unroll
        for (int i = 0; i < 8; i++) {
            int id = i*128 + tid, r = id >> 4, c = id & 15;
            cp_async16(Qs + r*APITCH + c*16, (const char*)Qb + r*256 + c*16);
        }
    };
    auto load_kv = [&](int jt, int st) {
        const char* kp = (const char*)(Kb + (size_t)jt * 64 * HDIM);
        const char* vp = (const char*)(Vb + (size_t)jt * 64 * HDIM);
#pragma unroll
        for (int i = 0; i < 8; i++) {
            int id = i*128 + tid, r = id >> 4, c = id & 15;
            cp_async16(Ks0 + st*KSTAGE + r*APITCH + c*16, kp + r*256 + c*16);
            cp_async16(Vs0 + st*VSTAGE + r*APITCH + c*16, vp + r*256 + c*16);
        }
    };

    const int ntiles = qb + 1;
    load_q(); load_kv(0, 0); CP_COMMIT();
    if (ntiles > 1) load_kv(1, 1);
    CP_COMMIT();

    float o[17][4];
#pragma unroll
    for (int d = 0; d < 17; d++)
#pragma unroll
        for (int e = 0; e < 4; e++) o[d][e] = 0.f;
    float M_lo = -INFINITY, M_hi = -INFINITY;
    uint32_t qf[8][4];

    const int lr16 = lid & 15;
    const int lh16 = (lid >> 4) * 16;

    for (int jt = 0; jt < ntiles; jt++) {
        CP_WAIT1();
        __syncthreads();
        if (jt == 0) {
#pragma unroll
            for (int k16 = 0; k16 < 8; k16++)
                ldsm_x4(qf[k16][0], qf[k16][1], qf[k16][2], qf[k16][3],
                        Qs + (wq + lr16)*APITCH + k16*32 + lh16);
        }
        const uint32_t Ks = Ks0 + (jt & 1) * KSTAGE;
        const uint32_t Vs = Vs0 + (jt & 1) * VSTAGE;

        float sa[8][4];
#pragma unroll
        for (int j = 0; j < 8; j++)
#pragma unroll
            for (int e = 0; e < 4; e++) sa[j][e] = 0.f;

#pragma unroll
        for (int k16 = 0; k16 < 8; k16++) {
            uint32_t kb[4][4];
#pragma unroll
            for (int nb = 0; nb < 4; nb++)
                ldsm_x4(kb[nb][0], kb[nb][1], kb[nb][2], kb[nb][3],
                        Ks + (nb*16 + lr16)*APITCH + k16*32 + lh16);
#pragma unroll
            for (int j = 0; j < 8; j++) {
                int nb = j >> 1, sub = j & 1;
                mma_f16(sa[j], qf[k16], kb[nb][sub], kb[nb][sub + 2]);
            }
        }

        if (jt == qb) {
#pragma unroll
            for (int j = 0; j < 8; j++) {
                int colb = j*8 + qd*2;
#pragma unroll
                for (int e = 0; e < 4; e++) {
                    int colg = colb + (e & 1);
                    int rowg = wq + g + (e >> 1) * 8;
                    if (colg > rowg) sa[j][e] = -INFINITY;
                }
            }
        }

        float mx_lo = -INFINITY, mx_hi = -INFINITY;
#pragma unroll
        for (int j = 0; j < 8; j++) {
            mx_lo = fmaxf(mx_lo, fmaxf(sa[j][0], sa[j][1]));
            mx_hi = fmaxf(mx_hi, fmaxf(sa[j][2], sa[j][3]));
        }
        mx_lo = fmaxf(mx_lo, __shfl_xor_sync(0xffffffffu, mx_lo, 1));
        mx_lo = fmaxf(mx_lo, __shfl_xor_sync(0xffffffffu, mx_lo, 2));
        mx_hi = fmaxf(mx_hi, __shfl_xor_sync(0xffffffffu, mx_hi, 1));
        mx_hi = fmaxf(mx_hi, __shfl_xor_sync(0xffffffffu, mx_hi, 2));
        float Mn_lo = fmaxf(M_lo, mx_lo * ACL);
        float Mn_hi = fmaxf(M_hi, mx_hi * ACL);
        float al_lo = ex2f(M_lo - Mn_lo);
        float al_hi = ex2f(M_hi - Mn_hi);
        M_lo = Mn_lo; M_hi = Mn_hi;

        uint32_t p16[8][2];
#pragma unroll
        for (int j = 0; j < 8; j++) {
            p16[j][0] = ex2_h2(fmaf(sa[j][0], ACL, -Mn_lo),
                               fmaf(sa[j][1], ACL, -Mn_lo));
            p16[j][1] = ex2_h2(fmaf(sa[j][2], ACL, -Mn_hi),
                               fmaf(sa[j][3], ACL, -Mn_hi));
        }

#pragma unroll
        for (int d = 0; d < 17; d++) {
            o[d][0] *= al_lo; o[d][1] *= al_lo;
            o[d][2] *= al_hi; o[d][3] *= al_hi;
        }

#pragma unroll
        for (int kk = 0; kk < 4; kk++) {
            uint32_t pa[4] = { p16[2*kk][0], p16[2*kk][1],
                               p16[2*kk+1][0], p16[2*kk+1][1] };
#pragma unroll
            for (int dp = 0; dp < 9; dp++) {
                uint32_t vb0, vb1, vb2, vb3;
                ldsm_x4t(vb0, vb1, vb2, vb3,
                         Vs + (kk*16 + lr16)*APITCH + dp*32 + lh16);
                mma_f16(o[2*dp], pa, vb0, vb1);
                if (dp < 8) mma_f16(o[2*dp + 1], pa, vb2, vb3);
            }
        }

        __syncthreads();
        if (jt + 2 < ntiles) load_kv(jt + 2, jt & 1);
        CP_COMMIT();
    }

    float l_lo = __shfl_sync(0xffffffffu, o[16][0], lid & ~3);
    float l_hi = __shfl_sync(0xffffffffu, o[16][2], lid & ~3);
    float r_lo = 1.f / l_lo;
    float r_hi = 1.f / l_hi;
    float* Y0 = Y + (((size_t)(b*32 + hs)) * SEQ + qb*64 + wq + g) * HDIM;
    float* Y1 = Y0 + 8 * HDIM;
#pragma unroll
    for (int dj = 0; dj < 16; dj++) {
        float2 v0 = make_float2(o[dj][0] * r_lo, o[dj][1] * r_lo);
        float2 v1 = make_float2(o[dj][2] * r_hi, o[dj][3] * r_hi);
        *(float2*)(Y0 + dj*8 + qd*2) = v0;
        *(float2*)(Y1 + dj*8 + qd*2) = v1;
    }
}

// ================ combine y1 - lam*y2, emits fp16 ============================
__global__ void __launch_bounds__(256)
combine_kernel(const float* __restrict__ Yin, const float* __restrict__ lam,
               __half* __restrict__ F)
{
    size_t slot = (size_t)blockIdx.x * blockDim.x + threadIdx.x;
    size_t e = slot * 4;
    const size_t total = (size_t)BATCH * SEQ * DMODEL;
    if (e >= total) return;
    int dd = (int)(e & 127);
    int h  = (int)((e >> 7) & 15);
    int t  = (int)((e >> 11) & (SEQ - 1));
    int b  = (int)(e >> 22);

    float4 y1 = *(const float4*)&Yin[(((size_t)(b*32 + h))      * SEQ + t) * HDIM + dd];
    float4 y2 = *(const float4*)&Yin[(((size_t)(b*32 + 16 + h)) * SEQ + t) * HDIM + dd];
    float l = lam[((size_t)b * 16 + h) * SEQ + t];
    __half2* Fp = (__half2*)(F + e);
    Fp[0] = __floats2half2_rn(y1.x - l * y2.x, y1.y - l * y2.y);
    Fp[1] = __floats2half2_rn(y1.z - l * y2.z, y1.w - l * y2.w);
}

// ================================= launch ====================================
extern "C" void kernel_launch(void* const* d_in, const int* in_sizes, int n_in,
                              void* d_out, int out_size)
{
    const float* x    = (const float*)d_in[0];
    const float* Wq1  = (const float*)d_in[1];
    const float* Wq2  = (const float*)d_in[2];
    const float* Wk   = (const float*)d_in[3];
    const float* Wv   = (const float*)d_in[4];
    const float* Wlam = (const float*)d_in[5];
    const float* Wo   = (const float*)d_in[6];
    float* out = (float*)d_out;

    __half *q, *k, *v, *xf, *wh, *wl;
    float *y, *lam;
    cudaGetSymbolAddress((void**)&q,   g_q);
    cudaGetSymbolAddress((void**)&k,   g_k);
    cudaGetSymbolAddress((void**)&v,   g_v);
    cudaGetSymbolAddress((void**)&y,   g_y);
    cudaGetSymbolAddress((void**)&lam, g_lam);
    cudaGetSymbolAddress((void**)&xf,  g_xf);
    cudaGetSymbolAddress((void**)&wh,  g_wh);
    cudaGetSymbolAddress((void**)&wl,  g_wl);

    cudaFuncSetAttribute(attn_kernel,
                         cudaFuncAttributeMaxDynamicSharedMemorySize, ATT_SMEM);
    cudaFuncSetAttribute(tc_gemm<0>,
                         cudaFuncAttributeMaxDynamicSharedMemorySize, GEMM_SMEM);
    cudaFuncSetAttribute(tc_gemm<1>,
                         cudaFuncAttributeMaxDynamicSharedMemorySize, GEMM_SMEM);

    const size_t WSZ = (size_t)DMODEL * DMODEL;
    const int n4x = MTOT * DMODEL / 4;
    dim3 tgrid(64, 64), tblk(32, 8);
    dim3 ggrid(DMODEL / 128, MTOT / 128);   // (16, 32)

    // conversions / splits
    convert_x_kernel<<<(n4x + 255) / 256, 256>>>(x, xf, n4x);
    splitT_kernel<<<tgrid, tblk>>>(Wq1, wh + 0*WSZ, wl + 0*WSZ);
    splitT_kernel<<<tgrid, tblk>>>(Wq2, wh + 1*WSZ, wl + 1*WSZ);
    splitT_kernel<<<tgrid, tblk>>>(Wk,  wh + 2*WSZ, wl + 2*WSZ);
    splitT_kernel<<<tgrid, tblk>>>(Wv,  wh + 3*WSZ, wl + 3*WSZ);
    splitT_kernel<<<tgrid, tblk>>>(Wo,  wh + 4*WSZ, wl + 4*WSZ);

    // projections -> fp16 head-scattered q/k/v
    tc_gemm<1><<<ggrid, 256, GEMM_SMEM>>>(xf, wh + 0*WSZ, wl + 0*WSZ, q, 32, 0);
    tc_gemm<1><<<ggrid, 256, GEMM_SMEM>>>(xf, wh + 1*WSZ, wl + 1*WSZ, q, 32, 16);
    tc_gemm<1><<<ggrid, 256, GEMM_SMEM>>>(xf, wh + 2*WSZ, wl + 2*WSZ, k, 16, 0);
    tc_gemm<1><<<ggrid, 256, GEMM_SMEM>>>(xf, wh + 3*WSZ, wl + 3*WSZ, v, 16, 0);

    lam_kernel<<<MTOT, 128>>>(x, Wlam, lam);

    attn_kernel<<<dim3(SEQ / 64, 32, BATCH), 128, ATT_SMEM>>>(q, k, v, y);

    // combine -> fp16 activations for the output GEMM
    const size_t total = (size_t)BATCH * SEQ * DMODEL;
    combine_kernel<<<(unsigned)((total / 4 + 255) / 256), 256>>>(y, lam, xf);

    // output GEMM
    tc_gemm<0><<<ggrid, 256, GEMM_SMEM>>>(xf, wh + 4*WSZ, wl + 4*WSZ, out, 0, 0);
}

// round 7
// speedup vs baseline: 6.1401x; 1.3330x over previous
#include <cuda_runtime.h>
#include <cuda_bf16.h>
#include <cuda_fp16.h>
#include <math.h>
#include <stdint.h>

// Problem constants
#define BATCH 2
#define SEQ   2048
#define DMODEL 2048
#define NHEAD 16
#define HDIM  128
#define MTOT  (BATCH*SEQ)          // 4096

// ======================= PTX helpers (portable, sm_80+) =====================
__device__ __forceinline__ uint32_t smem_to_u32(const void* p) {
    uint32_t addr;
    asm("{ .reg .u64 tmp; cvta.to.shared.u64 tmp, %1; cvt.u32.u64 %0, tmp; }"
        : "=r"(addr) : "l"(p));
    return addr;
}
__device__ __forceinline__ void cp_async16(uint32_t smem, const void* gmem) {
    asm volatile("cp.async.cg.shared.global [%0], [%1], 16;"
                 :: "r"(smem), "l"(gmem) : "memory");
}
#define CP_COMMIT() asm volatile("cp.async.commit_group;" ::: "memory")
#define CP_WAIT1()  asm volatile("cp.async.wait_group 1;" ::: "memory")
#define CP_WAIT0()  asm volatile("cp.async.wait_group 0;" ::: "memory")

__device__ __forceinline__ void ldsm_x4(uint32_t& r0, uint32_t& r1,
                                        uint32_t& r2, uint32_t& r3, uint32_t a) {
    asm volatile("ldmatrix.sync.aligned.m8n8.x4.shared.b16 {%0,%1,%2,%3}, [%4];"
                 : "=r"(r0), "=r"(r1), "=r"(r2), "=r"(r3) : "r"(a));
}
__device__ __forceinline__ void ldsm_x4t(uint32_t& r0, uint32_t& r1,
                                         uint32_t& r2, uint32_t& r3, uint32_t a) {
    asm volatile("ldmatrix.sync.aligned.m8n8.x4.trans.shared.b16 {%0,%1,%2,%3}, [%4];"
                 : "=r"(r0), "=r"(r1), "=r"(r2), "=r"(r3) : "r"(a));
}
__device__ __forceinline__ void mma_f16(float* c, const uint32_t* a,
                                        uint32_t b0, uint32_t b1) {
    asm volatile(
        "mma.sync.aligned.m16n8k16.row.col.f32.f16.f16.f32 "
        "{%0,%1,%2,%3}, {%4,%5,%6,%7}, {%8,%9}, {%0,%1,%2,%3};"
        : "+f"(c[0]), "+f"(c[1]), "+f"(c[2]), "+f"(c[3])
        : "r"(a[0]), "r"(a[1]), "r"(a[2]), "r"(a[3]), "r"(b0), "r"(b1));
}
__device__ __forceinline__ float ex2f(float x) {
    float r;
    asm("ex2.approx.f32 %0, %1;" : "=f"(r) : "f"(x));
    return r;
}
__device__ __forceinline__ uint32_t ex2_h2(float lo, float hi) {
    uint32_t packed, res;
    asm("cvt.rn.f16x2.f32 %0, %1, %2;" : "=r"(packed) : "f"(hi), "f"(lo));
    asm("ex2.approx.f16x2 %0, %1;" : "=r"(res) : "r"(packed));
    return res;
}

// ---------------- scratch (device globals; no allocations allowed) ----------
__device__ __half g_q [(size_t)BATCH*32*SEQ*HDIM];
__device__ __half g_k [(size_t)BATCH*16*SEQ*HDIM];
__device__ __half g_v [(size_t)BATCH*16*SEQ*HDIM];
__device__ float g_y  [(size_t)BATCH*32*SEQ*HDIM];
__device__ float g_lam[(size_t)BATCH*16*SEQ];
// fp16 GEMM operands
__device__ __half g_xf[(size_t)MTOT*DMODEL];               // activations fp16
__device__ __half g_wh[5][(size_t)DMODEL*DMODEL];          // W^T hi, [N][K]
__device__ __half g_wl[(size_t)DMODEL*DMODEL];             // W^T lo (Wo only)

// ============================ conversion kernels =============================
__global__ void __launch_bounds__(256)
convert_x_kernel(const float* __restrict__ X, __half* __restrict__ F, int n4)
{
    int i = blockIdx.x * blockDim.x + threadIdx.x;
    if (i >= n4) return;
    float4 v = ((const float4*)X)[i];
    __half2* Fp = (__half2*)F;
    Fp[2*i]   = __floats2half2_rn(v.x, v.y);
    Fp[2*i+1] = __floats2half2_rn(v.z, v.w);
}

// W [K][N] fp32 -> OH (+ optional OL) [N][K] fp16 (transpose + split)
__global__ void __launch_bounds__(256)
splitT_kernel(const float* __restrict__ W, __half* __restrict__ OH,
              __half* __restrict__ OL)
{
    __shared__ float t[32][33];
    int nx = blockIdx.x * 32, ky = blockIdx.y * 32;
    int tx = threadIdx.x, ty = threadIdx.y;   // 32 x 8
#pragma unroll
    for (int i = 0; i < 4; i++)
        t[ty + 8*i][tx] = W[(size_t)(ky + ty + 8*i) * DMODEL + nx + tx];
    __syncthreads();
#pragma unroll
    for (int i = 0; i < 4; i++) {
        float v = t[tx][ty + 8*i];
        __half h = __float2half_rn(v);
        size_t o = (size_t)(nx + ty + 8*i) * DMODEL + ky + tx;
        OH[o] = h;
        if (OL) OL[o] = __float2half_rn(v - __half2float(h));
    }
}

// ===================== mma.sync fp16 GEMM (1 or 2 products) ==================
// C[4096,2048] = A[M,K] @ B^T.  A fp16 [M][K]; B as Bh (+Bl) fp16 [N][K].
// MODE 0: row-major fp32 store. MODE 1: head-scatter fp16 store.
#define GK     2048
#define NKCH   64            // K chunks of 32
#define PITCH  40            // fp16 elems per smem row (80B)
#define BUF_B  (128*PITCH*2)
#define GEMM_SMEM_MAX (2*3*BUF_B)

template <int MODE, int NPROD>
__global__ void __launch_bounds__(256, 1)
tc_gemm(const __half* __restrict__ Af,
        const __half* __restrict__ Bh, const __half* __restrict__ Bl,
        void* __restrict__ Cout, int headsTotal, int headOffset)
{
    constexpr int NBUF = 1 + NPROD;            // A, Bh[, Bl]
    constexpr int STAGE = NBUF * BUF_B;
    extern __shared__ char dsm[];
    const uint32_t smbase = smem_to_u32(dsm);

    const int tid = threadIdx.x;
    const int wid = tid >> 5;
    const int lid = tid & 31;
    const int wm = wid >> 2;
    const int wn = wid & 3;

    const char* Asrc   = (const char*)(Af + (size_t)blockIdx.y * 128 * GK);
    const char* Bsrc_h = (const char*)(Bh + (size_t)blockIdx.x * 128 * GK);
    const char* Bsrc_l = (const char*)(Bl + (size_t)blockIdx.x * 128 * GK);

    const int lrow0 = tid >> 2;
    const int lc16  = tid & 3;

    auto load_chunk = [&](int kt, int st) {
        uint32_t sb = smbase + st * STAGE;
        size_t go = (size_t)kt * 64 + lc16 * 16;
        const char* src[3] = { Asrc, Bsrc_h, Bsrc_l };
#pragma unroll
        for (int bi = 0; bi < NBUF; bi++) {
            uint32_t bo = sb + bi * BUF_B;
#pragma unroll
            for (int i = 0; i < 2; i++) {
                int row = lrow0 + i * 64;
                cp_async16(bo + row * (PITCH*2) + lc16 * 16,
                           src[bi] + (size_t)row * (GK*2) + go);
            }
        }
    };

    float acc[4][4][4];
#pragma unroll
    for (int mi = 0; mi < 4; mi++)
#pragma unroll
        for (int nj = 0; nj < 4; nj++)
#pragma unroll
            for (int e = 0; e < 4; e++) acc[mi][nj][e] = 0.f;

    load_chunk(0, 0); CP_COMMIT();
    load_chunk(1, 1); CP_COMMIT();

    const int lrow = lid & 15;
    const int lhalf = (lid >> 4) * 16;

    for (int kt = 0; kt < NKCH; kt++) {
        if (kt + 1 < NKCH) { CP_WAIT1(); } else { CP_WAIT0(); }
        __syncthreads();

        uint32_t sb = smbase + (kt & 1) * STAGE;
        uint32_t a_f = sb;
        uint32_t b_h = sb + BUF_B;
        uint32_t b_l = sb + 2*BUF_B;

#pragma unroll
        for (int k16 = 0; k16 < 2; k16++) {
            const int kb = k16 * 32 + lhalf;
            uint32_t af[4][4], bh[2][4], bl[2][4];
#pragma unroll
            for (int mi = 0; mi < 4; mi++) {
                int r = wm * 64 + mi * 16 + lrow;
                ldsm_x4(af[mi][0], af[mi][1], af[mi][2], af[mi][3],
                        a_f + r * (PITCH*2) + kb);
            }
#pragma unroll
            for (int ni = 0; ni < 2; ni++) {
                int r = wn * 32 + ni * 16 + lrow;
                ldsm_x4(bh[ni][0], bh[ni][1], bh[ni][2], bh[ni][3],
                        b_h + r * (PITCH*2) + kb);
                if (NPROD == 2)
                    ldsm_x4(bl[ni][0], bl[ni][1], bl[ni][2], bl[ni][3],
                            b_l + r * (PITCH*2) + kb);
            }
#pragma unroll
            for (int mi = 0; mi < 4; mi++)
#pragma unroll
                for (int nj = 0; nj < 4; nj++) {
                    int ni = nj >> 1, sub = nj & 1;
                    mma_f16(acc[mi][nj], af[mi], bh[ni][sub], bh[ni][sub + 2]);
                    if (NPROD == 2)
                        mma_f16(acc[mi][nj], af[mi], bl[ni][sub], bl[ni][sub + 2]);
                }
        }
        __syncthreads();
        if (kt + 2 < NKCH) { load_chunk(kt + 2, kt & 1); CP_COMMIT(); }
    }

    const int lg = lid >> 2;
    const int lc = (lid & 3) * 2;
#pragma unroll
    for (int mi = 0; mi < 4; mi++) {
        int row0 = blockIdx.y * 128 + wm * 64 + mi * 16 + lg;
#pragma unroll
        for (int half = 0; half < 2; half++) {
            int row = row0 + half * 8;
            if (MODE == 0) {
                float* dst = (float*)Cout + (size_t)row * DMODEL + blockIdx.x * 128;
#pragma unroll
                for (int nj = 0; nj < 4; nj++) {
                    int n = wn * 32 + nj * 8 + lc;
                    float2 v;
                    v.x = acc[mi][nj][half * 2 + 0];
                    v.y = acc[mi][nj][half * 2 + 1];
                    *(float2*)(dst + n) = v;
                }
            } else {
                int b = row >> 11;
                int t = row & (SEQ - 1);
                int h = headOffset + blockIdx.x;
                __half* dst = (__half*)Cout +
                    (((size_t)(b * headsTotal + h)) * SEQ + t) * HDIM;
#pragma unroll
                for (int nj = 0; nj < 4; nj++) {
                    int n = wn * 32 + nj * 8 + lc;
                    __half2 v = __floats2half2_rn(acc[mi][nj][half*2],
                                                  acc[mi][nj][half*2+1]);
                    *(__half2*)(dst + n) = v;
                }
            }
        }
    }
}

// ============================ lambda gate ====================================
__global__ void __launch_bounds__(128)
lam_kernel(const float* __restrict__ x, const float* __restrict__ Wl,
           float* __restrict__ lam)
{
    int btok = blockIdx.x;
    int b = btok >> 11, t = btok & (SEQ - 1);
    const float* xr = x + (size_t)btok * DMODEL;

    float acc[16];
#pragma unroll
    for (int h = 0; h < 16; h++) acc[h] = 0.f;

    for (int k = threadIdx.x; k < DMODEL; k += 128) {
        float xv = xr[k];
        const float4* w = (const float4*)(Wl + (size_t)k * 16);
        float4 w0 = w[0], w1 = w[1], w2 = w[2], w3 = w[3];
        acc[0]  = fmaf(xv, w0.x, acc[0]);  acc[1]  = fmaf(xv, w0.y, acc[1]);
        acc[2]  = fmaf(xv, w0.z, acc[2]);  acc[3]  = fmaf(xv, w0.w, acc[3]);
        acc[4]  = fmaf(xv, w1.x, acc[4]);  acc[5]  = fmaf(xv, w1.y, acc[5]);
        acc[6]  = fmaf(xv, w1.z, acc[6]);  acc[7]  = fmaf(xv, w1.w, acc[7]);
        acc[8]  = fmaf(xv, w2.x, acc[8]);  acc[9]  = fmaf(xv, w2.y, acc[9]);
        acc[10] = fmaf(xv, w2.z, acc[10]); acc[11] = fmaf(xv, w2.w, acc[11]);
        acc[12] = fmaf(xv, w3.x, acc[12]); acc[13] = fmaf(xv, w3.y, acc[13]);
        acc[14] = fmaf(xv, w3.z, acc[14]); acc[15] = fmaf(xv, w3.w, acc[15]);
    }

    __shared__ float red[128][16];
#pragma unroll
    for (int h = 0; h < 16; h++) red[threadIdx.x][h] = acc[h];
    __syncthreads();
    for (int s = 64; s > 0; s >>= 1) {
        if (threadIdx.x < s)
#pragma unroll
            for (int h = 0; h < 16; h++)
                red[threadIdx.x][h] += red[threadIdx.x + s][h];
        __syncthreads();
    }
    if (threadIdx.x < 16) {
        float vv = red[0][threadIdx.x];
        lam[((size_t)b * 16 + threadIdx.x) * SEQ + t] = 1.f / (1.f + __expf(-vv));
    }
}

// ================= flash attention (mma.sync fp16) ===========================
#define APITCH 272            // bytes per smem row (136 halves)
#define KSTAGE 17408          // 64*272
#define VSTAGE 17680          // 65*272 (pad row for trans ldsm overread)
#define ATT_SMEM (17408 + 2*KSTAGE + 2*VSTAGE)   // 87584
#define ACL 0.12751744f       // (1/sqrt(128)) * log2(e)

__global__ void __launch_bounds__(128)
attn_kernel(const __half* __restrict__ Q, const __half* __restrict__ Kg,
            const __half* __restrict__ Vg, float* __restrict__ Y)
{
    extern __shared__ char asmem[];
    const uint32_t sb  = smem_to_u32(asmem);
    const uint32_t Qs  = sb;
    const uint32_t Ks0 = sb + 17408;
    const uint32_t Vs0 = Ks0 + 2*KSTAGE;

    const int qb = gridDim.x - 1 - blockIdx.x;   // heavy CTAs first
    const int hs = blockIdx.y, b = blockIdx.z;
    const int kvh = hs >> 1;
    const int tid = threadIdx.x;
    const int wid = tid >> 5, lid = tid & 31;
    const int wq = wid * 16;
    const int g = lid >> 2, qd = lid & 3;

    const __half* Qb = Q  + (((size_t)(b*32 + hs))  * SEQ + qb * 64) * HDIM;
    const __half* Kb = Kg + ((size_t)(b*16 + kvh)) * SEQ * HDIM;
    const __half* Vb = Vg + ((size_t)(b*16 + kvh)) * SEQ * HDIM;

    for (int idx = tid; idx < 130; idx += 128) {
        int st = idx / 65, r = idx % 65;
        *(uint4*)(asmem + (Vs0 - sb) + st*VSTAGE + r*APITCH + 256) =
            make_uint4(0x00003C00u, 0u, 0u, 0u);
    }

    auto load_q = [&]() {
#pragma unroll
        for (int i = 0; i < 8; i++) {
            int id = i*128 + tid, r = id >> 4, c = id & 15;
            cp_async16(Qs + r*APITCH + c*16, (const char*)Qb + r*256 + c*16);
        }
    };
    auto load_kv = [&](int jt, int st) {
        const char* kp = (const char*)(Kb + (size_t)jt * 64 * HDIM);
        const char* vp = (const char*)(Vb + (size_t)jt * 64 * HDIM);
#pragma unroll
        for (int i = 0; i < 8; i++) {
            int id = i*128 + tid, r = id >> 4, c = id & 15;
            cp_async16(Ks0 + st*KSTAGE + r*APITCH + c*16, kp + r*256 + c*16);
            cp_async16(Vs0 + st*VSTAGE + r*APITCH + c*16, vp + r*256 + c*16);
        }
    };

    const int ntiles = qb + 1;
    load_q(); load_kv(0, 0); CP_COMMIT();
    if (ntiles > 1) load_kv(1, 1);
    CP_COMMIT();

    float o[17][4];
#pragma unroll
    for (int d = 0; d < 17; d++)
#pragma unroll
        for (int e = 0; e < 4; e++) o[d][e] = 0.f;
    float M_lo = -INFINITY, M_hi = -INFINITY;
    uint32_t qf[8][4];

    const int lr16 = lid & 15;
    const int lh16 = (lid >> 4) * 16;

    for (int jt = 0; jt < ntiles; jt++) {
        CP_WAIT1();
        __syncthreads();
        if (jt == 0) {
#pragma unroll
            for (int k16 = 0; k16 < 8; k16++)
                ldsm_x4(qf[k16][0], qf[k16][1], qf[k16][2], qf[k16][3],
                        Qs + (wq + lr16)*APITCH + k16*32 + lh16);
        }
        const uint32_t Ks = Ks0 + (jt & 1) * KSTAGE;
        const uint32_t Vs = Vs0 + (jt & 1) * VSTAGE;

        float sa[8][4];
#pragma unroll
        for (int j = 0; j < 8; j++)
#pragma unroll
            for (int e = 0; e < 4; e++) sa[j][e] = 0.f;

#pragma unroll
        for (int k16 = 0; k16 < 8; k16++) {
            uint32_t kb[4][4];
#pragma unroll
            for (int nb = 0; nb < 4; nb++)
                ldsm_x4(kb[nb][0], kb[nb][1], kb[nb][2], kb[nb][3],
                        Ks + (nb*16 + lr16)*APITCH + k16*32 + lh16);
#pragma unroll
            for (int j = 0; j < 8; j++) {
                int nb = j >> 1, sub = j & 1;
                mma_f16(sa[j], qf[k16], kb[nb][sub], kb[nb][sub + 2]);
            }
        }

        if (jt == qb) {
#pragma unroll
            for (int j = 0; j < 8; j++) {
                int colb = j*8 + qd*2;
#pragma unroll
                for (int e = 0; e < 4; e++) {
                    int colg = colb + (e & 1);
                    int rowg = wq + g + (e >> 1) * 8;
                    if (colg > rowg) sa[j][e] = -INFINITY;
                }
            }
        }

        float mx_lo = -INFINITY, mx_hi = -INFINITY;
#pragma unroll
        for (int j = 0; j < 8; j++) {
            mx_lo = fmaxf(mx_lo, fmaxf(sa[j][0], sa[j][1]));
            mx_hi = fmaxf(mx_hi, fmaxf(sa[j][2], sa[j][3]));
        }
        mx_lo = fmaxf(mx_lo, __shfl_xor_sync(0xffffffffu, mx_lo, 1));
        mx_lo = fmaxf(mx_lo, __shfl_xor_sync(0xffffffffu, mx_lo, 2));
        mx_hi = fmaxf(mx_hi, __shfl_xor_sync(0xffffffffu, mx_hi, 1));
        mx_hi = fmaxf(mx_hi, __shfl_xor_sync(0xffffffffu, mx_hi, 2));
        float Mn_lo = fmaxf(M_lo, mx_lo * ACL);
        float Mn_hi = fmaxf(M_hi, mx_hi * ACL);
        float al_lo = ex2f(M_lo - Mn_lo);
        float al_hi = ex2f(M_hi - Mn_hi);
        M_lo = Mn_lo; M_hi = Mn_hi;

        uint32_t p16[8][2];
#pragma unroll
        for (int j = 0; j < 8; j++) {
            p16[j][0] = ex2_h2(fmaf(sa[j][0], ACL, -Mn_lo),
                               fmaf(sa[j][1], ACL, -Mn_lo));
            p16[j][1] = ex2_h2(fmaf(sa[j][2], ACL, -Mn_hi),
                               fmaf(sa[j][3], ACL, -Mn_hi));
        }

#pragma unroll
        for (int d = 0; d < 17; d++) {
            o[d][0] *= al_lo; o[d][1] *= al_lo;
            o[d][2] *= al_hi; o[d][3] *= al_hi;
        }

#pragma unroll
        for (int kk = 0; kk < 4; kk++) {
            uint32_t pa[4] = { p16[2*kk][0], p16[2*kk][1],
                               p16[2*kk+1][0], p16[2*kk+1][1] };
#pragma unroll
            for (int dp = 0; dp < 9; dp++) {
                uint32_t vb0, vb1, vb2, vb3;
                ldsm_x4t(vb0, vb1, vb2, vb3,
                         Vs + (kk*16 + lr16)*APITCH + dp*32 + lh16);
                mma_f16(o[2*dp], pa, vb0, vb1);
                if (dp < 8) mma_f16(o[2*dp + 1], pa, vb2, vb3);
            }
        }

        __syncthreads();
        if (jt + 2 < ntiles) load_kv(jt + 2, jt & 1);
        CP_COMMIT();
    }

    float l_lo = __shfl_sync(0xffffffffu, o[16][0], lid & ~3);
    float l_hi = __shfl_sync(0xffffffffu, o[16][2], lid & ~3);
    float r_lo = 1.f / l_lo;
    float r_hi = 1.f / l_hi;
    float* Y0 = Y + (((size_t)(b*32 + hs)) * SEQ + qb*64 + wq + g) * HDIM;
    float* Y1 = Y0 + 8 * HDIM;
#pragma unroll
    for (int dj = 0; dj < 16; dj++) {
        float2 v0 = make_float2(o[dj][0] * r_lo, o[dj][1] * r_lo);
        float2 v1 = make_float2(o[dj][2] * r_hi, o[dj][3] * r_hi);
        *(float2*)(Y0 + dj*8 + qd*2) = v0;
        *(float2*)(Y1 + dj*8 + qd*2) = v1;
    }
}

// ================ combine y1 - lam*y2, emits fp16 ============================
__global__ void __launch_bounds__(256)
combine_kernel(const float* __restrict__ Yin, const float* __restrict__ lam,
               __half* __restrict__ F)
{
    size_t slot = (size_t)blockIdx.x * blockDim.x + threadIdx.x;
    size_t e = slot * 4;
    const size_t total = (size_t)BATCH * SEQ * DMODEL;
    if (e >= total) return;
    int dd = (int)(e & 127);
    int h  = (int)((e >> 7) & 15);
    int t  = (int)((e >> 11) & (SEQ - 1));
    int b  = (int)(e >> 22);

    float4 y1 = *(const float4*)&Yin[(((size_t)(b*32 + h))      * SEQ + t) * HDIM + dd];
    float4 y2 = *(const float4*)&Yin[(((size_t)(b*32 + 16 + h)) * SEQ + t) * HDIM + dd];
    float l = lam[((size_t)b * 16 + h) * SEQ + t];
    __half2* Fp = (__half2*)(F + e);
    Fp[0] = __floats2half2_rn(y1.x - l * y2.x, y1.y - l * y2.y);
    Fp[1] = __floats2half2_rn(y1.z - l * y2.z, y1.w - l * y2.w);
}

// ================================= launch ====================================
extern "C" void kernel_launch(void* const* d_in, const int* in_sizes, int n_in,
                              void* d_out, int out_size)
{
    const float* x    = (const float*)d_in[0];
    const float* Wq1  = (const float*)d_in[1];
    const float* Wq2  = (const float*)d_in[2];
    const float* Wk   = (const float*)d_in[3];
    const float* Wv   = (const float*)d_in[4];
    const float* Wlam = (const float*)d_in[5];
    const float* Wo   = (const float*)d_in[6];
    float* out = (float*)d_out;

    __half *q, *k, *v, *xf, *wh, *wl;
    float *y, *lam;
    cudaGetSymbolAddress((void**)&q,   g_q);
    cudaGetSymbolAddress((void**)&k,   g_k);
    cudaGetSymbolAddress((void**)&v,   g_v);
    cudaGetSymbolAddress((void**)&y,   g_y);
    cudaGetSymbolAddress((void**)&lam, g_lam);
    cudaGetSymbolAddress((void**)&xf,  g_xf);
    cudaGetSymbolAddress((void**)&wh,  g_wh);
    cudaGetSymbolAddress((void**)&wl,  g_wl);

    cudaFuncSetAttribute(attn_kernel,
                         cudaFuncAttributeMaxDynamicSharedMemorySize, ATT_SMEM);
    cudaFuncSetAttribute((tc_gemm<0,2>),
                         cudaFuncAttributeMaxDynamicSharedMemorySize, GEMM_SMEM_MAX);
    cudaFuncSetAttribute((tc_gemm<1,1>),
                         cudaFuncAttributeMaxDynamicSharedMemorySize, GEMM_SMEM_MAX);

    const size_t WSZ = (size_t)DMODEL * DMODEL;
    const int n4x = MTOT * DMODEL / 4;
    dim3 tgrid(64, 64), tblk(32, 8);
    dim3 ggrid(DMODEL / 128, MTOT / 128);   // (16, 32)

    // conversions / splits (lo part only for Wo)
    convert_x_kernel<<<(n4x + 255) / 256, 256>>>(x, xf, n4x);
    splitT_kernel<<<tgrid, tblk>>>(Wq1, wh + 0*WSZ, (__half*)0);
    splitT_kernel<<<tgrid, tblk>>>(Wq2, wh + 1*WSZ, (__half*)0);
    splitT_kernel<<<tgrid, tblk>>>(Wk,  wh + 2*WSZ, (__half*)0);
    splitT_kernel<<<tgrid, tblk>>>(Wv,  wh + 3*WSZ, (__half*)0);
    splitT_kernel<<<tgrid, tblk>>>(Wo,  wh + 4*WSZ, wl);

    // projections -> fp16 head-scattered q/k/v (single product)
    tc_gemm<1,1><<<ggrid, 256, 2*2*BUF_B>>>(xf, wh + 0*WSZ, (__half*)0, q, 32, 0);
    tc_gemm<1,1><<<ggrid, 256, 2*2*BUF_B>>>(xf, wh + 1*WSZ, (__half*)0, q, 32, 16);
    tc_gemm<1,1><<<ggrid, 256, 2*2*BUF_B>>>(xf, wh + 2*WSZ, (__half*)0, k, 16, 0);
    tc_gemm<1,1><<<ggrid, 256, 2*2*BUF_B>>>(xf, wh + 3*WSZ, (__half*)0, v, 16, 0);

    lam_kernel<<<MTOT, 128>>>(x, Wlam, lam);

    attn_kernel<<<dim3(SEQ / 64, 32, BATCH), 128, ATT_SMEM>>>(q, k, v, y);

    // combine -> fp16 activations for the output GEMM
    const size_t total = (size_t)BATCH * SEQ * DMODEL;
    combine_kernel<<<(unsigned)((total / 4 + 255) / 256), 256>>>(y, lam, xf);

    // output GEMM (2-product: error lands directly on out)
    tc_gemm<0,2><<<ggrid, 256, 2*3*BUF_B>>>(xf, wh + 4*WSZ, wl, out, 0, 0);
}

// round 8
// speedup vs baseline: 6.6264x; 1.0792x over previous
#include <cuda_runtime.h>
#include <cuda_bf16.h>
#include <cuda_fp16.h>
#include <math.h>
#include <stdint.h>

// Problem constants
#define BATCH 2
#define SEQ   2048
#define DMODEL 2048
#define NHEAD 16
#define HDIM  128
#define MTOT  (BATCH*SEQ)          // 4096

// ======================= PTX helpers (portable, sm_80+) =====================
__device__ __forceinline__ uint32_t smem_to_u32(const void* p) {
    uint32_t addr;
    asm("{ .reg .u64 tmp; cvta.to.shared.u64 tmp, %1; cvt.u32.u64 %0, tmp; }"
        : "=r"(addr) : "l"(p));
    return addr;
}
__device__ __forceinline__ void cp_async16(uint32_t smem, const void* gmem) {
    asm volatile("cp.async.cg.shared.global [%0], [%1], 16;"
                 :: "r"(smem), "l"(gmem) : "memory");
}
#define CP_COMMIT() asm volatile("cp.async.commit_group;" ::: "memory")
#define CP_WAIT1()  asm volatile("cp.async.wait_group 1;" ::: "memory")
#define CP_WAIT0()  asm volatile("cp.async.wait_group 0;" ::: "memory")

__device__ __forceinline__ void ldsm_x4(uint32_t& r0, uint32_t& r1,
                                        uint32_t& r2, uint32_t& r3, uint32_t a) {
    asm volatile("ldmatrix.sync.aligned.m8n8.x4.shared.b16 {%0,%1,%2,%3}, [%4];"
                 : "=r"(r0), "=r"(r1), "=r"(r2), "=r"(r3) : "r"(a));
}
__device__ __forceinline__ void ldsm_x4t(uint32_t& r0, uint32_t& r1,
                                         uint32_t& r2, uint32_t& r3, uint32_t a) {
    asm volatile("ldmatrix.sync.aligned.m8n8.x4.trans.shared.b16 {%0,%1,%2,%3}, [%4];"
                 : "=r"(r0), "=r"(r1), "=r"(r2), "=r"(r3) : "r"(a));
}
__device__ __forceinline__ void mma_f16(float* c, const uint32_t* a,
                                        uint32_t b0, uint32_t b1) {
    asm volatile(
        "mma.sync.aligned.m16n8k16.row.col.f32.f16.f16.f32 "
        "{%0,%1,%2,%3}, {%4,%5,%6,%7}, {%8,%9}, {%0,%1,%2,%3};"
        : "+f"(c[0]), "+f"(c[1]), "+f"(c[2]), "+f"(c[3])
        : "r"(a[0]), "r"(a[1]), "r"(a[2]), "r"(a[3]), "r"(b0), "r"(b1));
}
__device__ __forceinline__ float ex2f(float x) {
    float r;
    asm("ex2.approx.f32 %0, %1;" : "=f"(r) : "f"(x));
    return r;
}
__device__ __forceinline__ uint32_t ex2_h2(float lo, float hi) {
    uint32_t packed, res;
    asm("cvt.rn.f16x2.f32 %0, %1, %2;" : "=r"(packed) : "f"(hi), "f"(lo));
    asm("ex2.approx.f16x2 %0, %1;" : "=r"(res) : "r"(packed));
    return res;
}

// ---------------- scratch (device globals; no allocations allowed) ----------
__device__ __half g_q [(size_t)BATCH*32*SEQ*HDIM];
__device__ __half g_k [(size_t)BATCH*16*SEQ*HDIM];
__device__ __half g_v [(size_t)BATCH*16*SEQ*HDIM];
__device__ float g_y  [(size_t)BATCH*32*SEQ*HDIM];
__device__ float g_lam[(size_t)BATCH*16*SEQ];
// fp16 GEMM operands
__device__ __half g_xf[(size_t)MTOT*DMODEL];               // activations fp16
__device__ __half g_wh[5][(size_t)DMODEL*DMODEL];          // W^T, [N][K]

// ============================ conversion kernels =============================
__global__ void __launch_bounds__(256)
convert_x_kernel(const float* __restrict__ X, __half* __restrict__ F, int n4)
{
    int i = blockIdx.x * blockDim.x + threadIdx.x;
    if (i >= n4) return;
    float4 v = ((const float4*)X)[i];
    __half2* Fp = (__half2*)F;
    Fp[2*i]   = __floats2half2_rn(v.x, v.y);
    Fp[2*i+1] = __floats2half2_rn(v.z, v.w);
}

// W [K][N] fp32 -> OH [N][K] fp16 (transpose + round)
__global__ void __launch_bounds__(256)
splitT_kernel(const float* __restrict__ W, __half* __restrict__ OH)
{
    __shared__ float t[32][33];
    int nx = blockIdx.x * 32, ky = blockIdx.y * 32;
    int tx = threadIdx.x, ty = threadIdx.y;   // 32 x 8
#pragma unroll
    for (int i = 0; i < 4; i++)
        t[ty + 8*i][tx] = W[(size_t)(ky + ty + 8*i) * DMODEL + nx + tx];
    __syncthreads();
#pragma unroll
    for (int i = 0; i < 4; i++) {
        float v = t[tx][ty + 8*i];
        size_t o = (size_t)(nx + ty + 8*i) * DMODEL + ky + tx;
        OH[o] = __float2half_rn(v);
    }
}

// ===================== mma.sync fp16 GEMM (single product) ==================
// C[4096,2048] = A[M,K] @ B^T.  A fp16 [M][K]; B fp16 [N][K].
// MODE 0: row-major fp32 store. MODE 1: head-scatter fp16 store.
#define GK     2048
#define NKCH   64            // K chunks of 32
#define PITCH  40            // fp16 elems per smem row (80B)
#define BUF_B  (128*PITCH*2)
#define GEMM_SMEM (2*2*BUF_B)

template <int MODE>
__global__ void __launch_bounds__(256, 1)
tc_gemm(const __half* __restrict__ Af, const __half* __restrict__ Bh,
        void* __restrict__ Cout, int headsTotal, int headOffset)
{
    constexpr int STAGE = 2 * BUF_B;
    extern __shared__ char dsm[];
    const uint32_t smbase = smem_to_u32(dsm);

    const int tid = threadIdx.x;
    const int wid = tid >> 5;
    const int lid = tid & 31;
    const int wm = wid >> 2;
    const int wn = wid & 3;

    const char* Asrc   = (const char*)(Af + (size_t)blockIdx.y * 128 * GK);
    const char* Bsrc_h = (const char*)(Bh + (size_t)blockIdx.x * 128 * GK);

    const int lrow0 = tid >> 2;
    const int lc16  = tid & 3;

    auto load_chunk = [&](int kt, int st) {
        uint32_t sb = smbase + st * STAGE;
        size_t go = (size_t)kt * 64 + lc16 * 16;
        const char* src[2] = { Asrc, Bsrc_h };
#pragma unroll
        for (int bi = 0; bi < 2; bi++) {
            uint32_t bo = sb + bi * BUF_B;
#pragma unroll
            for (int i = 0; i < 2; i++) {
                int row = lrow0 + i * 64;
                cp_async16(bo + row * (PITCH*2) + lc16 * 16,
                           src[bi] + (size_t)row * (GK*2) + go);
            }
        }
    };

    float acc[4][4][4];
#pragma unroll
    for (int mi = 0; mi < 4; mi++)
#pragma unroll
        for (int nj = 0; nj < 4; nj++)
#pragma unroll
            for (int e = 0; e < 4; e++) acc[mi][nj][e] = 0.f;

    load_chunk(0, 0); CP_COMMIT();
    load_chunk(1, 1); CP_COMMIT();

    const int lrow = lid & 15;
    const int lhalf = (lid >> 4) * 16;

    for (int kt = 0; kt < NKCH; kt++) {
        if (kt + 1 < NKCH) { CP_WAIT1(); } else { CP_WAIT0(); }
        __syncthreads();

        uint32_t sb = smbase + (kt & 1) * STAGE;
        uint32_t a_f = sb;
        uint32_t b_h = sb + BUF_B;

#pragma unroll
        for (int k16 = 0; k16 < 2; k16++) {
            const int kb = k16 * 32 + lhalf;
            uint32_t af[4][4], bh[2][4];
#pragma unroll
            for (int mi = 0; mi < 4; mi++) {
                int r = wm * 64 + mi * 16 + lrow;
                ldsm_x4(af[mi][0], af[mi][1], af[mi][2], af[mi][3],
                        a_f + r * (PITCH*2) + kb);
            }
#pragma unroll
            for (int ni = 0; ni < 2; ni++) {
                int r = wn * 32 + ni * 16 + lrow;
                ldsm_x4(bh[ni][0], bh[ni][1], bh[ni][2], bh[ni][3],
                        b_h + r * (PITCH*2) + kb);
            }
#pragma unroll
            for (int mi = 0; mi < 4; mi++)
#pragma unroll
                for (int nj = 0; nj < 4; nj++) {
                    int ni = nj >> 1, sub = nj & 1;
                    mma_f16(acc[mi][nj], af[mi], bh[ni][sub], bh[ni][sub + 2]);
                }
        }
        __syncthreads();
        if (kt + 2 < NKCH) { load_chunk(kt + 2, kt & 1); CP_COMMIT(); }
    }

    const int lg = lid >> 2;
    const int lc = (lid & 3) * 2;
#pragma unroll
    for (int mi = 0; mi < 4; mi++) {
        int row0 = blockIdx.y * 128 + wm * 64 + mi * 16 + lg;
#pragma unroll
        for (int half = 0; half < 2; half++) {
            int row = row0 + half * 8;
            if (MODE == 0) {
                float* dst = (float*)Cout + (size_t)row * DMODEL + blockIdx.x * 128;
#pragma unroll
                for (int nj = 0; nj < 4; nj++) {
                    int n = wn * 32 + nj * 8 + lc;
                    float2 v;
                    v.x = acc[mi][nj][half * 2 + 0];
                    v.y = acc[mi][nj][half * 2 + 1];
                    *(float2*)(dst + n) = v;
                }
            } else {
                int b = row >> 11;
                int t = row & (SEQ - 1);
                int h = headOffset + blockIdx.x;
                __half* dst = (__half*)Cout +
                    (((size_t)(b * headsTotal + h)) * SEQ + t) * HDIM;
#pragma unroll
                for (int nj = 0; nj < 4; nj++) {
                    int n = wn * 32 + nj * 8 + lc;
                    __half2 v = __floats2half2_rn(acc[mi][nj][half*2],
                                                  acc[mi][nj][half*2+1]);
                    *(__half2*)(dst + n) = v;
                }
            }
        }
    }
}

// ============================ lambda gate ====================================
__global__ void __launch_bounds__(128)
lam_kernel(const float* __restrict__ x, const float* __restrict__ Wl,
           float* __restrict__ lam)
{
    int btok = blockIdx.x;
    int b = btok >> 11, t = btok & (SEQ - 1);
    const float* xr = x + (size_t)btok * DMODEL;

    float acc[16];
#pragma unroll
    for (int h = 0; h < 16; h++) acc[h] = 0.f;

    for (int k = threadIdx.x; k < DMODEL; k += 128) {
        float xv = xr[k];
        const float4* w = (const float4*)(Wl + (size_t)k * 16);
        float4 w0 = w[0], w1 = w[1], w2 = w[2], w3 = w[3];
        acc[0]  = fmaf(xv, w0.x, acc[0]);  acc[1]  = fmaf(xv, w0.y, acc[1]);
        acc[2]  = fmaf(xv, w0.z, acc[2]);  acc[3]  = fmaf(xv, w0.w, acc[3]);
        acc[4]  = fmaf(xv, w1.x, acc[4]);  acc[5]  = fmaf(xv, w1.y, acc[5]);
        acc[6]  = fmaf(xv, w1.z, acc[6]);  acc[7]  = fmaf(xv, w1.w, acc[7]);
        acc[8]  = fmaf(xv, w2.x, acc[8]);  acc[9]  = fmaf(xv, w2.y, acc[9]);
        acc[10] = fmaf(xv, w2.z, acc[10]); acc[11] = fmaf(xv, w2.w, acc[11]);
        acc[12] = fmaf(xv, w3.x, acc[12]); acc[13] = fmaf(xv, w3.y, acc[13]);
        acc[14] = fmaf(xv, w3.z, acc[14]); acc[15] = fmaf(xv, w3.w, acc[15]);
    }

    __shared__ float red[128][16];
#pragma unroll
    for (int h = 0; h < 16; h++) red[threadIdx.x][h] = acc[h];
    __syncthreads();
    for (int s = 64; s > 0; s >>= 1) {
        if (threadIdx.x < s)
#pragma unroll
            for (int h = 0; h < 16; h++)
                red[threadIdx.x][h] += red[threadIdx.x + s][h];
        __syncthreads();
    }
    if (threadIdx.x < 16) {
        float vv = red[0][threadIdx.x];
        lam[((size_t)b * 16 + threadIdx.x) * SEQ + t] = 1.f / (1.f + __expf(-vv));
    }
}

// ================= flash attention (mma.sync fp16, 128-row CTA) ==============
// Q: [B,32,T,128] fp16; K,V: [B,16,T,128] fp16; Y: [B,32,T,128] fp32.
// 8 warps/CTA, 128 q-rows per CTA, 64-key tiles, ones-column row-sum trick.
#define APITCH 272            // bytes per smem row (136 halves)
#define QBYTES (128*APITCH)   // 34816
#define KSTAGE 17408          // 64*272
#define VSTAGE 17680          // 65*272 (pad row for trans ldsm overread)
#define ATT_SMEM (QBYTES + 2*KSTAGE + 2*VSTAGE)   // 104992
#define ACL 0.12751744f       // (1/sqrt(128)) * log2(e)

__global__ void __launch_bounds__(256)
attn_kernel(const __half* __restrict__ Q, const __half* __restrict__ Kg,
            const __half* __restrict__ Vg, float* __restrict__ Y)
{
    extern __shared__ char asmem[];
    const uint32_t sb  = smem_to_u32(asmem);
    const uint32_t Qs  = sb;
    const uint32_t Ks0 = sb + QBYTES;
    const uint32_t Vs0 = Ks0 + 2*KSTAGE;

    const int qb = gridDim.x - 1 - blockIdx.x;   // heavy CTAs first
    const int hs = blockIdx.y, b = blockIdx.z;
    const int kvh = hs >> 1;
    const int tid = threadIdx.x;
    const int wid = tid >> 5, lid = tid & 31;
    const int wq = wid * 16;                     // row offset within 128-tile
    const int g = lid >> 2, qd = lid & 3;

    const __half* Qb = Q  + (((size_t)(b*32 + hs))  * SEQ + qb * 128) * HDIM;
    const __half* Kb = Kg + ((size_t)(b*16 + kvh)) * SEQ * HDIM;
    const __half* Vb = Vg + ((size_t)(b*16 + kvh)) * SEQ * HDIM;

    // ones/zeros columns 128..135 of V smem (both stages, incl pad row)
    for (int idx = tid; idx < 130; idx += 256) {
        int st = idx / 65, r = idx % 65;
        *(uint4*)(asmem + (Vs0 - sb) + st*VSTAGE + r*APITCH + 256) =
            make_uint4(0x00003C00u, 0u, 0u, 0u);
    }

    auto load_q = [&]() {
#pragma unroll
        for (int i = 0; i < 8; i++) {
            int id = i*256 + tid, r = id >> 4, c = id & 15;
            cp_async16(Qs + r*APITCH + c*16, (const char*)Qb + r*256 + c*16);
        }
    };
    auto load_kv = [&](int jt, int st) {
        const char* kp = (const char*)(Kb + (size_t)jt * 64 * HDIM);
        const char* vp = (const char*)(Vb + (size_t)jt * 64 * HDIM);
#pragma unroll
        for (int i = 0; i < 4; i++) {
            int id = i*256 + tid, r = id >> 4, c = id & 15;
            cp_async16(Ks0 + st*KSTAGE + r*APITCH + c*16, kp + r*256 + c*16);
            cp_async16(Vs0 + st*VSTAGE + r*APITCH + c*16, vp + r*256 + c*16);
        }
    };

    const int ntiles = 2 * (qb + 1);
    const int nt_w   = 2*qb + 1 + (wid >> 2);    // warp's last active tile + 1
    const int rowb   = qb * 128 + wq;            // warp's global row base

    load_q(); load_kv(0, 0); CP_COMMIT();
    load_kv(1, 1); CP_COMMIT();

    float o[17][4];
#pragma unroll
    for (int d = 0; d < 17; d++)
#pragma unroll
        for (int e = 0; e < 4; e++) o[d][e] = 0.f;
    float M_lo = -INFINITY, M_hi = -INFINITY;
    uint32_t qf[8][4];

    const int lr16 = lid & 15;
    const int lh16 = (lid >> 4) * 16;

    for (int jt = 0; jt < ntiles; jt++) {
        if (jt + 1 < ntiles) { CP_WAIT1(); } else { CP_WAIT0(); }
        __syncthreads();
        if (jt == 0) {
#pragma unroll
            for (int k16 = 0; k16 < 8; k16++)
                ldsm_x4(qf[k16][0], qf[k16][1], qf[k16][2], qf[k16][3],
                        Qs + (wq + lr16)*APITCH + k16*32 + lh16);
        }
        const uint32_t Ks = Ks0 + (jt & 1) * KSTAGE;
        const uint32_t Vs = Vs0 + (jt & 1) * VSTAGE;

        if (jt < nt_w) {
            // ---- S = Q K^T
            float sa[8][4];
#pragma unroll
            for (int j = 0; j < 8; j++)
#pragma unroll
                for (int e = 0; e < 4; e++) sa[j][e] = 0.f;

#pragma unroll
            for (int k16 = 0; k16 < 8; k16++) {
                uint32_t kb[4][4];
#pragma unroll
                for (int nb = 0; nb < 4; nb++)
                    ldsm_x4(kb[nb][0], kb[nb][1], kb[nb][2], kb[nb][3],
                            Ks + (nb*16 + lr16)*APITCH + k16*32 + lh16);
#pragma unroll
                for (int j = 0; j < 8; j++) {
                    int nb = j >> 1, sub = j & 1;
                    mma_f16(sa[j], qf[k16], kb[nb][sub], kb[nb][sub + 2]);
                }
            }

            // ---- causal mask on warp's diagonal tile
            if (jt == nt_w - 1) {
#pragma unroll
                for (int j = 0; j < 8; j++) {
                    int colb = jt*64 + j*8 + qd*2;
#pragma unroll
                    for (int e = 0; e < 4; e++) {
                        int colg = colb + (e & 1);
                        int rowg = rowb + g + (e >> 1) * 8;
                        if (colg > rowg) sa[j][e] = -INFINITY;
                    }
                }
            }

            // ---- online softmax (registers + quad shuffles)
            float mx_lo = -INFINITY, mx_hi = -INFINITY;
#pragma unroll
            for (int j = 0; j < 8; j++) {
                mx_lo = fmaxf(mx_lo, fmaxf(sa[j][0], sa[j][1]));
                mx_hi = fmaxf(mx_hi, fmaxf(sa[j][2], sa[j][3]));
            }
            mx_lo = fmaxf(mx_lo, __shfl_xor_sync(0xffffffffu, mx_lo, 1));
            mx_lo = fmaxf(mx_lo, __shfl_xor_sync(0xffffffffu, mx_lo, 2));
            mx_hi = fmaxf(mx_hi, __shfl_xor_sync(0xffffffffu, mx_hi, 1));
            mx_hi = fmaxf(mx_hi, __shfl_xor_sync(0xffffffffu, mx_hi, 2));
            float Mn_lo = fmaxf(M_lo, mx_lo * ACL);
            float Mn_hi = fmaxf(M_hi, mx_hi * ACL);
            float al_lo = ex2f(M_lo - Mn_lo);
            float al_hi = ex2f(M_hi - Mn_hi);
            M_lo = Mn_lo; M_hi = Mn_hi;

            uint32_t p16[8][2];
#pragma unroll
            for (int j = 0; j < 8; j++) {
                p16[j][0] = ex2_h2(fmaf(sa[j][0], ACL, -Mn_lo),
                                   fmaf(sa[j][1], ACL, -Mn_lo));
                p16[j][1] = ex2_h2(fmaf(sa[j][2], ACL, -Mn_hi),
                                   fmaf(sa[j][3], ACL, -Mn_hi));
            }

#pragma unroll
            for (int d = 0; d < 17; d++) {
                o[d][0] *= al_lo; o[d][1] *= al_lo;
                o[d][2] *= al_hi; o[d][3] *= al_hi;
            }

            // ---- O += P V  (ones column at d-tile 16 accumulates l)
#pragma unroll
            for (int kk = 0; kk < 4; kk++) {
                uint32_t pa[4] = { p16[2*kk][0], p16[2*kk][1],
                                   p16[2*kk+1][0], p16[2*kk+1][1] };
#pragma unroll
                for (int dp = 0; dp < 9; dp++) {
                    uint32_t vb0, vb1, vb2, vb3;
                    ldsm_x4t(vb0, vb1, vb2, vb3,
                             Vs + (kk*16 + lr16)*APITCH + dp*32 + lh16);
                    mma_f16(o[2*dp], pa, vb0, vb1);
                    if (dp < 8) mma_f16(o[2*dp + 1], pa, vb2, vb3);
                }
            }
        }

        __syncthreads();
        if (jt + 2 < ntiles) { load_kv(jt + 2, jt & 1); }
        CP_COMMIT();
    }

    // ---- epilogue
    float l_lo = __shfl_sync(0xffffffffu, o[16][0], lid & ~3);
    float l_hi = __shfl_sync(0xffffffffu, o[16][2], lid & ~3);
    float r_lo = 1.f / l_lo;
    float r_hi = 1.f / l_hi;
    float* Y0 = Y + (((size_t)(b*32 + hs)) * SEQ + rowb + g) * HDIM;
    float* Y1 = Y0 + 8 * HDIM;
#pragma unroll
    for (int dj = 0; dj < 16; dj++) {
        float2 v0 = make_float2(o[dj][0] * r_lo, o[dj][1] * r_lo);
        float2 v1 = make_float2(o[dj][2] * r_hi, o[dj][3] * r_hi);
        *(float2*)(Y0 + dj*8 + qd*2) = v0;
        *(float2*)(Y1 + dj*8 + qd*2) = v1;
    }
}

// ================ combine y1 - lam*y2, emits fp16 ============================
__global__ void __launch_bounds__(256)
combine_kernel(const float* __restrict__ Yin, const float* __restrict__ lam,
               __half* __restrict__ F)
{
    size_t slot = (size_t)blockIdx.x * blockDim.x + threadIdx.x;
    size_t e = slot * 4;
    const size_t total = (size_t)BATCH * SEQ * DMODEL;
    if (e >= total) return;
    int dd = (int)(e & 127);
    int h  = (int)((e >> 7) & 15);
    int t  = (int)((e >> 11) & (SEQ - 1));
    int b  = (int)(e >> 22);

    float4 y1 = *(const float4*)&Yin[(((size_t)(b*32 + h))      * SEQ + t) * HDIM + dd];
    float4 y2 = *(const float4*)&Yin[(((size_t)(b*32 + 16 + h)) * SEQ + t) * HDIM + dd];
    float l = lam[((size_t)b * 16 + h) * SEQ + t];
    __half2* Fp = (__half2*)(F + e);
    Fp[0] = __floats2half2_rn(y1.x - l * y2.x, y1.y - l * y2.y);
    Fp[1] = __floats2half2_rn(y1.z - l * y2.z, y1.w - l * y2.w);
}

// ================================= launch ====================================
extern "C" void kernel_launch(void* const* d_in, const int* in_sizes, int n_in,
                              void* d_out, int out_size)
{
    const float* x    = (const float*)d_in[0];
    const float* Wq1  = (const float*)d_in[1];
    const float* Wq2  = (const float*)d_in[2];
    const float* Wk   = (const float*)d_in[3];
    const float* Wv   = (const float*)d_in[4];
    const float* Wlam = (const float*)d_in[5];
    const float* Wo   = (const float*)d_in[6];
    float* out = (float*)d_out;

    __half *q, *k, *v, *xf, *wh;
    float *y, *lam;
    cudaGetSymbolAddress((void**)&q,   g_q);
    cudaGetSymbolAddress((void**)&k,   g_k);
    cudaGetSymbolAddress((void**)&v,   g_v);
    cudaGetSymbolAddress((void**)&y,   g_y);
    cudaGetSymbolAddress((void**)&lam, g_lam);
    cudaGetSymbolAddress((void**)&xf,  g_xf);
    cudaGetSymbolAddress((void**)&wh,  g_wh);

    cudaFuncSetAttribute(attn_kernel,
                         cudaFuncAttributeMaxDynamicSharedMemorySize, ATT_SMEM);
    cudaFuncSetAttribute((tc_gemm<0>),
                         cudaFuncAttributeMaxDynamicSharedMemorySize, GEMM_SMEM);
    cudaFuncSetAttribute((tc_gemm<1>),
                         cudaFuncAttributeMaxDynamicSharedMemorySize, GEMM_SMEM);

    const size_t WSZ = (size_t)DMODEL * DMODEL;
    const int n4x = MTOT * DMODEL / 4;
    dim3 tgrid(64, 64), tblk(32, 8);
    dim3 ggrid(DMODEL / 128, MTOT / 128);   // (16, 32)

    // conversions
    convert_x_kernel<<<(n4x + 255) / 256, 256>>>(x, xf, n4x);
    splitT_kernel<<<tgrid, tblk>>>(Wq1, wh + 0*WSZ);
    splitT_kernel<<<tgrid, tblk>>>(Wq2, wh + 1*WSZ);
    splitT_kernel<<<tgrid, tblk>>>(Wk,  wh + 2*WSZ);
    splitT_kernel<<<tgrid, tblk>>>(Wv,  wh + 3*WSZ);
    splitT_kernel<<<tgrid, tblk>>>(Wo,  wh + 4*WSZ);

    // projections -> fp16 head-scattered q/k/v (single product)
    tc_gemm<1><<<ggrid, 256, GEMM_SMEM>>>(xf, wh + 0*WSZ, q, 32, 0);
    tc_gemm<1><<<ggrid, 256, GEMM_SMEM>>>(xf, wh + 1*WSZ, q, 32, 16);
    tc_gemm<1><<<ggrid, 256, GEMM_SMEM>>>(xf, wh + 2*WSZ, k, 16, 0);
    tc_gemm<1><<<ggrid, 256, GEMM_SMEM>>>(xf, wh + 3*WSZ, v, 16, 0);

    lam_kernel<<<MTOT, 128>>>(x, Wlam, lam);

    attn_kernel<<<dim3(SEQ / 128, 32, BATCH), 256, ATT_SMEM>>>(q, k, v, y);

    // combine -> fp16 activations for the output GEMM
    const size_t total = (size_t)BATCH * SEQ * DMODEL;
    combine_kernel<<<(unsigned)((total / 4 + 255) / 256), 256>>>(y, lam, xf);

    // output GEMM (single product)
    tc_gemm<0><<<ggrid, 256, GEMM_SMEM>>>(xf, wh + 4*WSZ, out, 0, 0);
}

// round 9
// speedup vs baseline: 7.1239x; 1.0751x over previous
#include <cuda_runtime.h>
#include <cuda_bf16.h>
#include <cuda_fp16.h>
#include <math.h>
#include <stdint.h>

// Problem constants
#define BATCH 2
#define SEQ   2048
#define DMODEL 2048
#define NHEAD 16
#define HDIM  128
#define MTOT  (BATCH*SEQ)          // 4096

// ======================= PTX helpers (portable, sm_80+) =====================
__device__ __forceinline__ uint32_t smem_to_u32(const void* p) {
    uint32_t addr;
    asm("{ .reg .u64 tmp; cvta.to.shared.u64 tmp, %1; cvt.u32.u64 %0, tmp; }"
        : "=r"(addr) : "l"(p));
    return addr;
}
__device__ __forceinline__ void cp_async16(uint32_t smem, const void* gmem) {
    asm volatile("cp.async.cg.shared.global [%0], [%1], 16;"
                 :: "r"(smem), "l"(gmem) : "memory");
}
#define CP_COMMIT() asm volatile("cp.async.commit_group;" ::: "memory")
#define CP_WAIT1()  asm volatile("cp.async.wait_group 1;" ::: "memory")
#define CP_WAIT0()  asm volatile("cp.async.wait_group 0;" ::: "memory")

__device__ __forceinline__ void ldsm_x4(uint32_t& r0, uint32_t& r1,
                                        uint32_t& r2, uint32_t& r3, uint32_t a) {
    asm volatile("ldmatrix.sync.aligned.m8n8.x4.shared.b16 {%0,%1,%2,%3}, [%4];"
                 : "=r"(r0), "=r"(r1), "=r"(r2), "=r"(r3) : "r"(a));
}
__device__ __forceinline__ void ldsm_x4t(uint32_t& r0, uint32_t& r1,
                                         uint32_t& r2, uint32_t& r3, uint32_t a) {
    asm volatile("ldmatrix.sync.aligned.m8n8.x4.trans.shared.b16 {%0,%1,%2,%3}, [%4];"
                 : "=r"(r0), "=r"(r1), "=r"(r2), "=r"(r3) : "r"(a));
}
__device__ __forceinline__ void mma_f16(float* c, const uint32_t* a,
                                        uint32_t b0, uint32_t b1) {
    asm volatile(
        "mma.sync.aligned.m16n8k16.row.col.f32.f16.f16.f32 "
        "{%0,%1,%2,%3}, {%4,%5,%6,%7}, {%8,%9}, {%0,%1,%2,%3};"
        : "+f"(c[0]), "+f"(c[1]), "+f"(c[2]), "+f"(c[3])
        : "r"(a[0]), "r"(a[1]), "r"(a[2]), "r"(a[3]), "r"(b0), "r"(b1));
}
__device__ __forceinline__ float ex2f(float x) {
    float r;
    asm("ex2.approx.f32 %0, %1;" : "=f"(r) : "f"(x));
    return r;
}
__device__ __forceinline__ uint32_t ex2_h2(float lo, float hi) {
    uint32_t packed, res;
    asm("cvt.rn.f16x2.f32 %0, %1, %2;" : "=r"(packed) : "f"(hi), "f"(lo));
    asm("ex2.approx.f16x2 %0, %1;" : "=r"(res) : "r"(packed));
    return res;
}

// ---------------- scratch (device globals; no allocations allowed) ----------
__device__ __half g_q [(size_t)BATCH*32*SEQ*HDIM];
__device__ __half g_k [(size_t)BATCH*16*SEQ*HDIM];
__device__ __half g_v [(size_t)BATCH*16*SEQ*HDIM];
__device__ float g_y  [(size_t)BATCH*32*SEQ*HDIM];
__device__ float g_lam[(size_t)BATCH*16*SEQ];
// fp16 GEMM operands
__device__ __half g_xf[(size_t)MTOT*DMODEL];               // activations fp16
__device__ __half g_wh[5][(size_t)DMODEL*DMODEL];          // W^T, [N][K]

#define WSZC ((size_t)DMODEL*DMODEL)

// ============================ conversion kernels =============================
__global__ void __launch_bounds__(256)
convert_x_kernel(const float* __restrict__ X, __half* __restrict__ F, int n4)
{
    int i = blockIdx.x * blockDim.x + threadIdx.x;
    if (i >= n4) return;
    float4 v = ((const float4*)X)[i];
    __half2* Fp = (__half2*)F;
    Fp[2*i]   = __floats2half2_rn(v.x, v.y);
    Fp[2*i+1] = __floats2half2_rn(v.z, v.w);
}

// 5 weights [K][N] fp32 -> [N][K] fp16 (transpose + round), one launch
__global__ void __launch_bounds__(256)
splitT5_kernel(const float* __restrict__ W0, const float* __restrict__ W1,
               const float* __restrict__ W2, const float* __restrict__ W3,
               const float* __restrict__ W4, __half* __restrict__ OHbase)
{
    const int z = blockIdx.z;
    const float* W = (z == 0) ? W0 : (z == 1) ? W1 : (z == 2) ? W2
                   : (z == 3) ? W3 : W4;
    __half* OH = OHbase + (size_t)z * WSZC;

    __shared__ float t[32][33];
    int nx = blockIdx.x * 32, ky = blockIdx.y * 32;
    int tx = threadIdx.x, ty = threadIdx.y;   // 32 x 8
#pragma unroll
    for (int i = 0; i < 4; i++)
        t[ty + 8*i][tx] = W[(size_t)(ky + ty + 8*i) * DMODEL + nx + tx];
    __syncthreads();
#pragma unroll
    for (int i = 0; i < 4; i++) {
        float v = t[tx][ty + 8*i];
        size_t o = (size_t)(nx + ty + 8*i) * DMODEL + ky + tx;
        OH[o] = __float2half_rn(v);
    }
}

// ===================== mma.sync fp16 GEMM core ===============================
#define GK     2048
#define NKCH   64            // K chunks of 32
#define PITCH  40            // fp16 elems per smem row (80B)
#define BUF_B  (128*PITCH*2)
#define STAGE_B (2*BUF_B)    // A + B per stage
#define GEMM_SMEM (3*STAGE_B)

// core mainloop: computes acc for one 128x128 tile (3-stage, 1 sync/kt)
__device__ __forceinline__ void gemm_core(
    const char* Asrc, const char* Bsrc, uint32_t smbase,
    int tid, int wm, int wn, int lid, float acc[4][4][4])
{
    const int lrow0 = tid >> 2;
    const int lc16  = tid & 3;

    auto load_chunk = [&](int kt, int st) {
        uint32_t sb = smbase + st * STAGE_B;
        size_t go = (size_t)kt * 64 + lc16 * 16;
        const char* src[2] = { Asrc, Bsrc };
#pragma unroll
        for (int bi = 0; bi < 2; bi++) {
            uint32_t bo = sb + bi * BUF_B;
#pragma unroll
            for (int i = 0; i < 2; i++) {
                int row = lrow0 + i * 64;
                cp_async16(bo + row * (PITCH*2) + lc16 * 16,
                           src[bi] + (size_t)row * (GK*2) + go);
            }
        }
    };

    load_chunk(0, 0); CP_COMMIT();
    load_chunk(1, 1); CP_COMMIT();

    const int lrow = lid & 15;
    const int lhalf = (lid >> 4) * 16;

    for (int kt = 0; kt < NKCH; kt++) {
        CP_WAIT1();
        __syncthreads();
        if (kt + 2 < NKCH) load_chunk(kt + 2, (kt + 2) % 3);
        CP_COMMIT();

        uint32_t sb = smbase + (kt % 3) * STAGE_B;
        uint32_t a_f = sb;
        uint32_t b_h = sb + BUF_B;

#pragma unroll
        for (int k16 = 0; k16 < 2; k16++) {
            const int kb = k16 * 32 + lhalf;
            uint32_t af[4][4], bh[2][4];
#pragma unroll
            for (int mi = 0; mi < 4; mi++) {
                int r = wm * 64 + mi * 16 + lrow;
                ldsm_x4(af[mi][0], af[mi][1], af[mi][2], af[mi][3],
                        a_f + r * (PITCH*2) + kb);
            }
#pragma unroll
            for (int ni = 0; ni < 2; ni++) {
                int r = wn * 32 + ni * 16 + lrow;
                ldsm_x4(bh[ni][0], bh[ni][1], bh[ni][2], bh[ni][3],
                        b_h + r * (PITCH*2) + kb);
            }
#pragma unroll
            for (int mi = 0; mi < 4; mi++)
#pragma unroll
                for (int nj = 0; nj < 4; nj++) {
                    int ni = nj >> 1, sub = nj & 1;
                    mma_f16(acc[mi][nj], af[mi], bh[ni][sub], bh[ni][sub + 2]);
                }
        }
    }
}

// fused projection GEMM: blockIdx.x = widx*16 + bn; widx selects W + dest
__global__ void __launch_bounds__(256, 1)
tc_proj(const __half* __restrict__ Af, const __half* __restrict__ Wbase,
        __half* __restrict__ q, __half* __restrict__ k, __half* __restrict__ v)
{
    extern __shared__ char dsm[];
    const uint32_t smbase = smem_to_u32(dsm);
    const int tid = threadIdx.x;
    const int wid = tid >> 5, lid = tid & 31;
    const int wm = wid >> 2, wn = wid & 3;

    const int widx = blockIdx.x >> 4;
    const int bn   = blockIdx.x & 15;

    const char* Asrc = (const char*)(Af + (size_t)blockIdx.y * 128 * GK);
    const char* Bsrc = (const char*)(Wbase + (size_t)widx * WSZC
                                     + (size_t)bn * 128 * GK);

    float acc[4][4][4];
#pragma unroll
    for (int mi = 0; mi < 4; mi++)
#pragma unroll
        for (int nj = 0; nj < 4; nj++)
#pragma unroll
            for (int e = 0; e < 4; e++) acc[mi][nj][e] = 0.f;

    gemm_core(Asrc, Bsrc, smbase, tid, wm, wn, lid, acc);

    // dest select
    __half* base = (widx < 2) ? q : (widx == 2) ? k : v;
    const int headsTotal = (widx < 2) ? 32 : 16;
    const int h = ((widx == 1) ? 16 : 0) + bn;

    const int lg = lid >> 2;
    const int lc = (lid & 3) * 2;
#pragma unroll
    for (int mi = 0; mi < 4; mi++) {
        int row0 = blockIdx.y * 128 + wm * 64 + mi * 16 + lg;
#pragma unroll
        for (int half = 0; half < 2; half++) {
            int row = row0 + half * 8;
            int b = row >> 11;
            int t = row & (SEQ - 1);
            __half* dst = base + (((size_t)(b * headsTotal + h)) * SEQ + t) * HDIM;
#pragma unroll
            for (int nj = 0; nj < 4; nj++) {
                int n = wn * 32 + nj * 8 + lc;
                __half2 vv = __floats2half2_rn(acc[mi][nj][half*2],
                                               acc[mi][nj][half*2+1]);
                *(__half2*)(dst + n) = vv;
            }
        }
    }
}

// output GEMM: row-major fp32 store
__global__ void __launch_bounds__(256, 1)
tc_out(const __half* __restrict__ Af, const __half* __restrict__ Bh,
       float* __restrict__ C)
{
    extern __shared__ char dsm[];
    const uint32_t smbase = smem_to_u32(dsm);
    const int tid = threadIdx.x;
    const int wid = tid >> 5, lid = tid & 31;
    const int wm = wid >> 2, wn = wid & 3;

    const char* Asrc = (const char*)(Af + (size_t)blockIdx.y * 128 * GK);
    const char* Bsrc = (const char*)(Bh + (size_t)blockIdx.x * 128 * GK);

    float acc[4][4][4];
#pragma unroll
    for (int mi = 0; mi < 4; mi++)
#pragma unroll
        for (int nj = 0; nj < 4; nj++)
#pragma unroll
            for (int e = 0; e < 4; e++) acc[mi][nj][e] = 0.f;

    gemm_core(Asrc, Bsrc, smbase, tid, wm, wn, lid, acc);

    const int lg = lid >> 2;
    const int lc = (lid & 3) * 2;
#pragma unroll
    for (int mi = 0; mi < 4; mi++) {
        int row0 = blockIdx.y * 128 + wm * 64 + mi * 16 + lg;
#pragma unroll
        for (int half = 0; half < 2; half++) {
            int row = row0 + half * 8;
            float* dst = C + (size_t)row * DMODEL + blockIdx.x * 128;
#pragma unroll
            for (int nj = 0; nj < 4; nj++) {
                int n = wn * 32 + nj * 8 + lc;
                float2 vv;
                vv.x = acc[mi][nj][half * 2 + 0];
                vv.y = acc[mi][nj][half * 2 + 1];
                *(float2*)(dst + n) = vv;
            }
        }
    }
}

// ============================ lambda gate ====================================
__global__ void __launch_bounds__(128)
lam_kernel(const float* __restrict__ x, const float* __restrict__ Wl,
           float* __restrict__ lam)
{
    int btok = blockIdx.x;
    int b = btok >> 11, t = btok & (SEQ - 1);
    const float* xr = x + (size_t)btok * DMODEL;

    float acc[16];
#pragma unroll
    for (int h = 0; h < 16; h++) acc[h] = 0.f;

    for (int k = threadIdx.x; k < DMODEL; k += 128) {
        float xv = xr[k];
        const float4* w = (const float4*)(Wl + (size_t)k * 16);
        float4 w0 = w[0], w1 = w[1], w2 = w[2], w3 = w[3];
        acc[0]  = fmaf(xv, w0.x, acc[0]);  acc[1]  = fmaf(xv, w0.y, acc[1]);
        acc[2]  = fmaf(xv, w0.z, acc[2]);  acc[3]  = fmaf(xv, w0.w, acc[3]);
        acc[4]  = fmaf(xv, w1.x, acc[4]);  acc[5]  = fmaf(xv, w1.y, acc[5]);
        acc[6]  = fmaf(xv, w1.z, acc[6]);  acc[7]  = fmaf(xv, w1.w, acc[7]);
        acc[8]  = fmaf(xv, w2.x, acc[8]);  acc[9]  = fmaf(xv, w2.y, acc[9]);
        acc[10] = fmaf(xv, w2.z, acc[10]); acc[11] = fmaf(xv, w2.w, acc[11]);
        acc[12] = fmaf(xv, w3.x, acc[12]); acc[13] = fmaf(xv, w3.y, acc[13]);
        acc[14] = fmaf(xv, w3.z, acc[14]); acc[15] = fmaf(xv, w3.w, acc[15]);
    }

    __shared__ float red[128][16];
#pragma unroll
    for (int h = 0; h < 16; h++) red[threadIdx.x][h] = acc[h];
    __syncthreads();
    for (int s = 64; s > 0; s >>= 1) {
        if (threadIdx.x < s)
#pragma unroll
            for (int h = 0; h < 16; h++)
                red[threadIdx.x][h] += red[threadIdx.x + s][h];
        __syncthreads();
    }
    if (threadIdx.x < 16) {
        float vv = red[0][threadIdx.x];
        lam[((size_t)b * 16 + threadIdx.x) * SEQ + t] = 1.f / (1.f + __expf(-vv));
    }
}

// ================= flash attention (mma.sync fp16, 128-row CTA) ==============
// 8 warps/CTA, 128 q-rows, 64-key tiles, 3-stage KV pipeline, 1 sync/tile.
#define APITCH 272            // bytes per smem row (136 halves)
#define QBYTES (128*APITCH)   // 34816
#define KSTAGE 17408          // 64*272
#define VSTAGE 17680          // 65*272 (pad row for trans ldsm overread)
#define ATT_SMEM (QBYTES + 3*KSTAGE + 3*VSTAGE)   // 140080
#define ACL 0.12751744f       // (1/sqrt(128)) * log2(e)

__global__ void __launch_bounds__(256)
attn_kernel(const __half* __restrict__ Q, const __half* __restrict__ Kg,
            const __half* __restrict__ Vg, float* __restrict__ Y)
{
    extern __shared__ char asmem[];
    const uint32_t sb  = smem_to_u32(asmem);
    const uint32_t Qs  = sb;
    const uint32_t Ks0 = sb + QBYTES;
    const uint32_t Vs0 = Ks0 + 3*KSTAGE;

    const int qb = gridDim.x - 1 - blockIdx.x;   // heavy CTAs first
    const int hs = blockIdx.y, b = blockIdx.z;
    const int kvh = hs >> 1;
    const int tid = threadIdx.x;
    const int wid = tid >> 5, lid = tid & 31;
    const int wq = wid * 16;
    const int g = lid >> 2, qd = lid & 3;

    const __half* Qb = Q  + (((size_t)(b*32 + hs))  * SEQ + qb * 128) * HDIM;
    const __half* Kb = Kg + ((size_t)(b*16 + kvh)) * SEQ * HDIM;
    const __half* Vb = Vg + ((size_t)(b*16 + kvh)) * SEQ * HDIM;

    // ones/zeros columns 128..135 of V smem (all 3 stages, incl pad row)
    for (int idx = tid; idx < 195; idx += 256) {
        int st = idx / 65, r = idx % 65;
        *(uint4*)(asmem + (Vs0 - sb) + st*VSTAGE + r*APITCH + 256) =
            make_uint4(0x00003C00u, 0u, 0u, 0u);
    }

    auto load_q = [&]() {
#pragma unroll
        for (int i = 0; i < 8; i++) {
            int id = i*256 + tid, r = id >> 4, c = id & 15;
            cp_async16(Qs + r*APITCH + c*16, (const char*)Qb + r*256 + c*16);
        }
    };
    auto load_kv = [&](int jt, int st) {
        const char* kp = (const char*)(Kb + (size_t)jt * 64 * HDIM);
        const char* vp = (const char*)(Vb + (size_t)jt * 64 * HDIM);
#pragma unroll
        for (int i = 0; i < 4; i++) {
            int id = i*256 + tid, r = id >> 4, c = id & 15;
            cp_async16(Ks0 + st*KSTAGE + r*APITCH + c*16, kp + r*256 + c*16);
            cp_async16(Vs0 + st*VSTAGE + r*APITCH + c*16, vp + r*256 + c*16);
        }
    };

    const int ntiles = 2 * (qb + 1);
    const int nt_w   = 2*qb + 1 + (wid >> 2);    // warp's last active tile + 1
    const int rowb   = qb * 128 + wq;

    load_q(); load_kv(0, 0); CP_COMMIT();
    load_kv(1, 1); CP_COMMIT();

    float o[17][4];
#pragma unroll
    for (int d = 0; d < 17; d++)
#pragma unroll
        for (int e = 0; e < 4; e++) o[d][e] = 0.f;
    float M_lo = -INFINITY, M_hi = -INFINITY;
    uint32_t qf[8][4];

    const int lr16 = lid & 15;
    const int lh16 = (lid >> 4) * 16;

    for (int jt = 0; jt < ntiles; jt++) {
        CP_WAIT1();
        __syncthreads();
        if (jt + 2 < ntiles) load_kv(jt + 2, (jt + 2) % 3);
        CP_COMMIT();

        if (jt == 0) {
#pragma unroll
            for (int k16 = 0; k16 < 8; k16++)
                ldsm_x4(qf[k16][0], qf[k16][1], qf[k16][2], qf[k16][3],
                        Qs + (wq + lr16)*APITCH + k16*32 + lh16);
        }
        const uint32_t Ks = Ks0 + (jt % 3) * KSTAGE;
        const uint32_t Vs = Vs0 + (jt % 3) * VSTAGE;

        if (jt < nt_w) {
            // ---- S = Q K^T
            float sa[8][4];
#pragma unroll
            for (int j = 0; j < 8; j++)
#pragma unroll
                for (int e = 0; e < 4; e++) sa[j][e] = 0.f;

#pragma unroll
            for (int k16 = 0; k16 < 8; k16++) {
                uint32_t kb[4][4];
#pragma unroll
                for (int nb = 0; nb < 4; nb++)
                    ldsm_x4(kb[nb][0], kb[nb][1], kb[nb][2], kb[nb][3],
                            Ks + (nb*16 + lr16)*APITCH + k16*32 + lh16);
#pragma unroll
                for (int j = 0; j < 8; j++) {
                    int nb = j >> 1, sub = j & 1;
                    mma_f16(sa[j], qf[k16], kb[nb][sub], kb[nb][sub + 2]);
                }
            }

            // ---- causal mask on warp's diagonal tile
            if (jt == nt_w - 1) {
#pragma unroll
                for (int j = 0; j < 8; j++) {
                    int colb = jt*64 + j*8 + qd*2;
#pragma unroll
                    for (int e = 0; e < 4; e++) {
                        int colg = colb + (e & 1);
                        int rowg = rowb + g + (e >> 1) * 8;
                        if (colg > rowg) sa[j][e] = -INFINITY;
                    }
                }
            }

            // ---- online softmax (registers + quad shuffles)
            float mx_lo = -INFINITY, mx_hi = -INFINITY;
#pragma unroll
            for (int j = 0; j < 8; j++) {
                mx_lo = fmaxf(mx_lo, fmaxf(sa[j][0], sa[j][1]));
                mx_hi = fmaxf(mx_hi, fmaxf(sa[j][2], sa[j][3]));
            }
            mx_lo = fmaxf(mx_lo, __shfl_xor_sync(0xffffffffu, mx_lo, 1));
            mx_lo = fmaxf(mx_lo, __shfl_xor_sync(0xffffffffu, mx_lo, 2));
            mx_hi = fmaxf(mx_hi, __shfl_xor_sync(0xffffffffu, mx_hi, 1));
            mx_hi = fmaxf(mx_hi, __shfl_xor_sync(0xffffffffu, mx_hi, 2));
            float Mn_lo = fmaxf(M_lo, mx_lo * ACL);
            float Mn_hi = fmaxf(M_hi, mx_hi * ACL);
            float al_lo = ex2f(M_lo - Mn_lo);
            float al_hi = ex2f(M_hi - Mn_hi);
            M_lo = Mn_lo; M_hi = Mn_hi;

            uint32_t p16[8][2];
#pragma unroll
            for (int j = 0; j < 8; j++) {
                p16[j][0] = ex2_h2(fmaf(sa[j][0], ACL, -Mn_lo),
                                   fmaf(sa[j][1], ACL, -Mn_lo));
                p16[j][1] = ex2_h2(fmaf(sa[j][2], ACL, -Mn_hi),
                                   fmaf(sa[j][3], ACL, -Mn_hi));
            }

#pragma unroll
            for (int d = 0; d < 17; d++) {
                o[d][0] *= al_lo; o[d][1] *= al_lo;
                o[d][2] *= al_hi; o[d][3] *= al_hi;
            }

            // ---- O += P V  (ones column at d-tile 16 accumulates l)
#pragma unroll
            for (int kk = 0; kk < 4; kk++) {
                uint32_t pa[4] = { p16[2*kk][0], p16[2*kk][1],
                                   p16[2*kk+1][0], p16[2*kk+1][1] };
#pragma unroll
                for (int dp = 0; dp < 9; dp++) {
                    uint32_t vb0, vb1, vb2, vb3;
                    ldsm_x4t(vb0, vb1, vb2, vb3,
                             Vs + (kk*16 + lr16)*APITCH + dp*32 + lh16);
                    mma_f16(o[2*dp], pa, vb0, vb1);
                    if (dp < 8) mma_f16(o[2*dp + 1], pa, vb2, vb3);
                }
            }
        }
    }

    // ---- epilogue
    float l_lo = __shfl_sync(0xffffffffu, o[16][0], lid & ~3);
    float l_hi = __shfl_sync(0xffffffffu, o[16][2], lid & ~3);
    float r_lo = 1.f / l_lo;
    float r_hi = 1.f / l_hi;
    float* Y0 = Y + (((size_t)(b*32 + hs)) * SEQ + rowb + g) * HDIM;
    float* Y1 = Y0 + 8 * HDIM;
#pragma unroll
    for (int dj = 0; dj < 16; dj++) {
        float2 v0 = make_float2(o[dj][0] * r_lo, o[dj][1] * r_lo);
        float2 v1 = make_float2(o[dj][2] * r_hi, o[dj][3] * r_hi);
        *(float2*)(Y0 + dj*8 + qd*2) = v0;
        *(float2*)(Y1 + dj*8 + qd*2) = v1;
    }
}

// ================ combine y1 - lam*y2, emits fp16 ============================
__global__ void __launch_bounds__(256)
combine_kernel(const float* __restrict__ Yin, const float* __restrict__ lam,
               __half* __restrict__ F)
{
    size_t slot = (size_t)blockIdx.x * blockDim.x + threadIdx.x;
    size_t e = slot * 4;
    const size_t total = (size_t)BATCH * SEQ * DMODEL;
    if (e >= total) return;
    int dd = (int)(e & 127);
    int h  = (int)((e >> 7) & 15);
    int t  = (int)((e >> 11) & (SEQ - 1));
    int b  = (int)(e >> 22);

    float4 y1 = *(const float4*)&Yin[(((size_t)(b*32 + h))      * SEQ + t) * HDIM + dd];
    float4 y2 = *(const float4*)&Yin[(((size_t)(b*32 + 16 + h)) * SEQ + t) * HDIM + dd];
    float l = lam[((size_t)b * 16 + h) * SEQ + t];
    __half2* Fp = (__half2*)(F + e);
    Fp[0] = __floats2half2_rn(y1.x - l * y2.x, y1.y - l * y2.y);
    Fp[1] = __floats2half2_rn(y1.z - l * y2.z, y1.w - l * y2.w);
}

// ================================= launch ====================================
extern "C" void kernel_launch(void* const* d_in, const int* in_sizes, int n_in,
                              void* d_out, int out_size)
{
    const float* x    = (const float*)d_in[0];
    const float* Wq1  = (const float*)d_in[1];
    const float* Wq2  = (const float*)d_in[2];
    const float* Wk   = (const float*)d_in[3];
    const float* Wv   = (const float*)d_in[4];
    const float* Wlam = (const float*)d_in[5];
    const float* Wo   = (const float*)d_in[6];
    float* out = (float*)d_out;

    __half *q, *k, *v, *xf, *wh;
    float *y, *lam;
    cudaGetSymbolAddress((void**)&q,   g_q);
    cudaGetSymbolAddress((void**)&k,   g_k);
    cudaGetSymbolAddress((void**)&v,   g_v);
    cudaGetSymbolAddress((void**)&y,   g_y);
    cudaGetSymbolAddress((void**)&lam, g_lam);
    cudaGetSymbolAddress((void**)&xf,  g_xf);
    cudaGetSymbolAddress((void**)&wh,  g_wh);

    cudaFuncSetAttribute(attn_kernel,
                         cudaFuncAttributeMaxDynamicSharedMemorySize, ATT_SMEM);
    cudaFuncSetAttribute(tc_proj,
                         cudaFuncAttributeMaxDynamicSharedMemorySize, GEMM_SMEM);
    cudaFuncSetAttribute(tc_out,
                         cudaFuncAttributeMaxDynamicSharedMemorySize, GEMM_SMEM);

    const int n4x = MTOT * DMODEL / 4;
    dim3 tgrid(64, 64, 5), tblk(32, 8);

    // conversions (batched)
    convert_x_kernel<<<(n4x + 255) / 256, 256>>>(x, xf, n4x);
    splitT5_kernel<<<tgrid, tblk>>>(Wq1, Wq2, Wk, Wv, Wo, wh);

    // fused projections: one launch, 2048 CTAs
    tc_proj<<<dim3(64, 32), 256, GEMM_SMEM>>>(xf, wh, q, k, v);

    lam_kernel<<<MTOT, 128>>>(x, Wlam, lam);

    attn_kernel<<<dim3(SEQ / 128, 32, BATCH), 256, ATT_SMEM>>>(q, k, v, y);

    // combine -> fp16 activations for the output GEMM
    const size_t total = (size_t)BATCH * SEQ * DMODEL;
    combine_kernel<<<(unsigned)((total / 4 + 255) / 256), 256>>>(y, lam, xf);

    // output GEMM
    tc_out<<<dim3(16, 32), 256, GEMM_SMEM>>>(xf, wh + 4*WSZC, out);
}